// round 9
// baseline (speedup 1.0000x reference)
#include <cuda_runtime.h>

#define NDEPTH 4
typedef unsigned long long u64;

__device__ __forceinline__ u64 ffma2(u64 a, u64 b, u64 c){
    u64 d; asm("fma.rn.f32x2 %0, %1, %2, %3;" : "=l"(d) : "l"(a), "l"(b), "l"(c)); return d;
}
__device__ __forceinline__ u64 fpack2(float x, float y){
    u64 d; asm("mov.b64 %0, {%1, %2};" : "=l"(d) : "f"(x), "f"(y)); return d;
}
__device__ __forceinline__ float2 funpack2(u64 a){
    float x, y; asm("mov.b64 {%0, %1}, %2;" : "=f"(x), "=f"(y) : "l"(a)); return make_float2(x, y);
}

// ---------------- scratch (device globals) ----------------
__device__ float  g_h0[8*64*65536];
__device__ float  g_h1[8*64*65536];
__device__ float2 g_f1[8*64*256*16];
__device__ float2 g_modes[8*64*256];
__device__ float2 g_mixed[8*64*256];               // mixedT [b][ky][kx][o]
__device__ u64    g_Gx[8*256*16*64];               // [b][y][ky][c] (gx,gx)
__device__ u64    g_Gy[8*256*16*64];               // (gy,gy)
__device__ float2 g_wt[NDEPTH*256*64*64];          // [d][m][i][o]
__device__ u64    g_wcd[NDEPTH*64*64];             // [d][i][o] (w,w)
__device__ u64    g_w1d[64*128];                   // [c][m]    (w,w)
__device__ float  g_ec[16*256], g_es[16*256];      // fwd: cos, -sin
__device__ float  g_ic[16*256], g_is[16*256];      // inv-W scaled tables

// ---------------- prep: tables + dup'd weights ----------------
__global__ void kprep(const float* __restrict__ ww, const float* __restrict__ w1){
    int idx = blockIdx.x * 256 + threadIdx.x;      // grid 64 -> 16384
    if (idx < 4096){
        int x = idx & 255, ky = idx >> 8;
        float ang = 6.283185307179586f * (float)((ky * x) & 255) / 256.f;
        float c = cosf(ang), s = sinf(ang);
        g_ec[idx] = c; g_es[idx] = -s;
        const float sc = 1.f / 65536.f;
        g_ic[idx] = (ky == 0) ? sc : 2.f * sc * c;
        g_is[idx] = (ky == 0) ? 0.f : -2.f * sc * s;
    }
    {   // g_wcd[(d*64+i)*64+o] = dup(ww[d][o][i])
        int i = idx & 63, o = (idx >> 6) & 63, d = idx >> 12;
        float w = ww[(d*64 + o)*64 + i];
        g_wcd[(d*64 + i)*64 + o] = fpack2(w, w);
    }
    if (idx < 8192){                               // g_w1d[c*128+m] = dup(w1[m][c])
        int c = idx >> 7, m = idx & 127;
        float w = w1[m*64 + c];
        g_w1d[c*128 + m] = fpack2(w, w);
    }
}

// ---------------- spectral weight transpose ----------------
__global__ void ktw(const float* __restrict__ wre, const float* __restrict__ wim){
    int idx = blockIdx.x * 256 + threadIdx.x;
    int ky = idx & 15, kx = (idx >> 4) & 15, o = (idx >> 8) & 63, i = (idx >> 14) & 63, d = idx >> 20;
    int m = kx * 16 + ky;
    g_wt[((d * 256 + m) * 64 + i) * 64 + o] = make_float2(wre[idx], wim[idx]);
}

// ---------------- fc0 ----------------
__global__ void kfc0(const float* __restrict__ x, const float* __restrict__ w,
                     const float* __restrict__ bv, float* __restrict__ out){
    int idx = blockIdx.x * 256 + threadIdx.x;
    int p4 = idx & 16383;
    int c  = (idx >> 14) & 63;
    int b  = idx >> 20;
    const float* xb = x + (size_t)b * 3 * 65536 + p4 * 4;
    float4 a0 = *(const float4*)&xb[0];
    float4 a1 = *(const float4*)&xb[65536];
    float4 a2 = *(const float4*)&xb[131072];
    float w0 = w[c*3], w1 = w[c*3+1], w2 = w[c*3+2], bb = bv[c];
    float4 r;
    r.x = bb + a0.x*w0 + a1.x*w1 + a2.x*w2;
    r.y = bb + a0.y*w0 + a1.y*w1 + a2.y*w2;
    r.z = bb + a0.z*w0 + a1.z*w1 + a2.z*w2;
    r.w = bb + a0.w*w0 + a1.w*w1 + a2.w*w2;
    *(float4*)&out[(size_t)idx * 4] = r;
}

// ---------------- fwd DFT along W: x-paired f32x2, zero in-loop MOVs ----------------
// 128 rows/block, 256 thr, thread = 4 rows x 2 ky. smem: tcp_c/tcp_s [8 kg][516] + sh [128][68]
__global__ __launch_bounds__(256) void kfwd1(const float* __restrict__ hin, float2* __restrict__ f1){
    extern __shared__ __align__(16) float dsm1[];
    float* tcp_c = dsm1;                           // 8*516
    float* tcp_s = dsm1 + 8*516;
    float* sh    = dsm1 + 16*516;                  // 128*68
    int tid = threadIdx.x;
    size_t rowbase = (size_t)blockIdx.x * 128;
    // fill kg-paired twiddle tables: [kg][xp][ky01][e]
    #pragma unroll
    for (int k = 0; k < 16; ++k){
        int idx = tid + k*256;                     // 4096 per table
        int e = idx & 1, ky = (idx >> 1) & 1, xp = (idx >> 2) & 127, kg = idx >> 9;
        int kyg = kg*2 + ky, x = xp*2 + e;
        int dst = kg*516 + xp*4 + ky*2 + e;
        tcp_c[dst] = g_ec[kyg*256 + x];
        tcp_s[dst] = g_es[kyg*256 + x];
    }
    int kg = tid & 7, rg = tid >> 3;
    int r0 = rg*4, ky0 = kg*2;
    const float* tc = &tcp_c[kg*516];
    const float* ts = &tcp_s[kg*516];
    u64 ar[4][2], ai[4][2];
    #pragma unroll
    for (int j = 0; j < 4; ++j){ ar[j][0]=ar[j][1]=ai[j][0]=ai[j][1]=0ull; }

    for (int ch = 0; ch < 4; ++ch){
        int xb = ch*64;
        __syncthreads();
        #pragma unroll
        for (int k = 0; k < 8; ++k){
            int idx = tid + k*256;                 // 2048 float4 = 128 rows x 16 blk
            int r = idx >> 4, blk = idx & 15;
            float4 v = *(const float4*)&hin[(rowbase + r)*256 + xb + blk*4];
            *(float4*)&sh[r*68 + ((blk ^ ((r>>1)&7))<<2)] = v;
        }
        __syncthreads();
        #pragma unroll 4
        for (int xl = 0; xl < 64; xl += 4){
            int xp4 = (xb + xl)*2;                 // (x/2)*4
            ulonglong2 A  = *(const ulonglong2*)&tc[xp4];
            ulonglong2 B  = *(const ulonglong2*)&tc[xp4 + 4];
            ulonglong2 Sa = *(const ulonglong2*)&ts[xp4];
            ulonglong2 Sb = *(const ulonglong2*)&ts[xp4 + 4];
            #pragma unroll
            for (int j = 0; j < 4; ++j){
                int r = r0 + j;
                ulonglong2 h = *(const ulonglong2*)&sh[r*68 + (((xl>>2) ^ ((r>>1)&7))<<2)];
                ar[j][0] = ffma2(h.x, A.x,  ar[j][0]);
                ar[j][0] = ffma2(h.y, B.x,  ar[j][0]);
                ai[j][0] = ffma2(h.x, Sa.x, ai[j][0]);
                ai[j][0] = ffma2(h.y, Sb.x, ai[j][0]);
                ar[j][1] = ffma2(h.x, A.y,  ar[j][1]);
                ar[j][1] = ffma2(h.y, B.y,  ar[j][1]);
                ai[j][1] = ffma2(h.x, Sa.y, ai[j][1]);
                ai[j][1] = ffma2(h.y, Sb.y, ai[j][1]);
            }
        }
    }
    #pragma unroll
    for (int j = 0; j < 4; ++j){
        float2 re0 = funpack2(ar[j][0]), im0 = funpack2(ai[j][0]);
        float2 re1 = funpack2(ar[j][1]), im1 = funpack2(ai[j][1]);
        float4 o = make_float4(re0.x+re0.y, im0.x+im0.y, re1.x+re1.y, im1.x+im1.y);
        *(float4*)&f1[(rowbase + r0 + j)*16 + ky0] = o;
    }
}

// ---------------- fwd DFT along H, split-K ----------------
__global__ void kfwd2(const float2* __restrict__ f1, float2* __restrict__ modes){
    __shared__ float2 sf[4096];
    __shared__ float ct[256], st[256];
    __shared__ float2 sred[256];
    int tid = threadIdx.x;                         // 512
    if (tid < 256){
        float ang = 6.283185307179586f * (float)tid / 256.f;
        ct[tid] = cosf(ang); st[tid] = sinf(ang);
    }
    int bc = blockIdx.x;
    const float2* src = f1 + (size_t)bc * 4096;
    for (int idx = tid; idx < 4096; idx += 512) sf[idx] = src[idx];
    __syncthreads();
    int outi = tid & 255;
    int kx = outi >> 4, ky = outi & 15;
    int yb = (tid >> 8) * 128;
    float re0=0.f, im0=0.f, re1=0.f, im1=0.f;
    #pragma unroll 4
    for (int yy = yb; yy < yb + 128; yy += 2){
        float2 v0 = sf[yy*16 + ky];
        int t0 = (kx * yy) & 255;
        float c0 = ct[t0], s0 = st[t0];
        re0 += v0.x*c0 + v0.y*s0;
        im0 += v0.y*c0 - v0.x*s0;
        float2 v1 = sf[(yy+1)*16 + ky];
        int t1 = (kx * (yy+1)) & 255;
        float c1 = ct[t1], s1 = st[t1];
        re1 += v1.x*c1 + v1.y*s1;
        im1 += v1.y*c1 - v1.x*s1;
    }
    float re = re0 + re1, im = im0 + im1;
    if (tid >= 256) sred[outi] = make_float2(re, im);
    __syncthreads();
    if (tid < 256){
        float2 o = sred[outi];
        modes[bc*256 + outi] = make_float2(re + o.x, im + o.y);
    }
}

// ---------------- mode mixing -> mixedT [b][ky][kx][o] ----------------
__global__ void kmix(const float2* __restrict__ modes, const float2* __restrict__ wt,
                     float2* __restrict__ mixedT){
    __shared__ float2 swt[4096];
    __shared__ float2 sin_[512];
    int tid = threadIdx.x, m = blockIdx.x;
    int ky = m & 15, kx = m >> 4;
    const float2* wsrc = wt + (size_t)m * 4096;
    for (int idx = tid; idx < 4096; idx += 256) swt[idx] = wsrc[idx];
    for (int idx = tid; idx < 512; idx += 256){
        int b = idx >> 6, i = idx & 63;
        sin_[idx] = modes[(b*64 + i)*256 + m];
    }
    __syncthreads();
    int o = tid & 63;
    for (int half = 0; half < 2; ++half){
        int b = (tid >> 6) + half * 4;
        float re = 0.f, im = 0.f;
        #pragma unroll 8
        for (int i = 0; i < 64; ++i){
            float2 a = sin_[b*64 + i];
            float2 wv = swt[i*64 + o];
            re += a.x*wv.x - a.y*wv.y;
            im += a.x*wv.y + a.y*wv.x;
        }
        mixedT[((b*16 + ky)*16 + kx)*64 + o] = make_float2(re, im);
    }
}

// ---------------- inv DFT along H -> dup'd Gx/Gy [b][y][ky][c] ----------------
__global__ void kinv1(const float2* __restrict__ mixedT, u64* __restrict__ Gx, u64* __restrict__ Gy){
    __shared__ float2 sm[1024];
    __shared__ float ct[256], st[256];
    int tid = threadIdx.x;                         // 256
    int ky = blockIdx.x & 15, yg = (blockIdx.x >> 4) & 15, b = blockIdx.x >> 8;
    {
        float ang = 6.283185307179586f * (float)tid / 256.f;
        ct[tid] = cosf(ang); st[tid] = sinf(ang);
    }
    const float2* src = mixedT + (size_t)(b*16 + ky) * 1024;
    for (int idx = tid; idx < 1024; idx += 256) sm[idx] = src[idx];
    __syncthreads();
    int c = tid & 63, yl = tid >> 6;
    #pragma unroll
    for (int yi = 0; yi < 4; ++yi){
        int yy = yg*16 + yl*4 + yi;
        float re = 0.f, im = 0.f;
        #pragma unroll
        for (int kx = 0; kx < 16; ++kx){
            float2 v = sm[kx*64 + c];
            int t = (kx * yy) & 255;
            float cc = ct[t], ss = st[t];
            re += v.x*cc - v.y*ss;
            im += v.x*ss + v.y*cc;
        }
        size_t oidx = ((size_t)(b*256 + yy)*16 + ky)*64 + c;
        Gx[oidx] = fpack2(re, re);
        Gy[oidx] = fpack2(im, im);
    }
}

// ---------------- fused: 1x1 conv + inv DFT along W + bias + relu ----------------
// smem 101632 B; thread 4o x 8x; zero in-loop MOVs
#define CMAD(oo, wd) \
    acc[oo][0]=ffma2(wd,h01.x,acc[oo][0]); acc[oo][1]=ffma2(wd,h01.y,acc[oo][1]); \
    acc[oo][2]=ffma2(wd,h23.x,acc[oo][2]); acc[oo][3]=ffma2(wd,h23.y,acc[oo][3]);
#define IMAD2(oo, gxd, gyd) \
    acc[oo][0]=ffma2(gxd,A01.x,acc[oo][0]); acc[oo][0]=ffma2(gyd,B01.x,acc[oo][0]); \
    acc[oo][1]=ffma2(gxd,A01.y,acc[oo][1]); acc[oo][1]=ffma2(gyd,B01.y,acc[oo][1]); \
    acc[oo][2]=ffma2(gxd,A23.x,acc[oo][2]); acc[oo][2]=ffma2(gyd,B23.x,acc[oo][2]); \
    acc[oo][3]=ffma2(gxd,A23.y,acc[oo][3]); acc[oo][3]=ffma2(gyd,B23.y,acc[oo][3]);

__global__ __launch_bounds__(256) void kfused(
        const float* __restrict__ hin, const u64* __restrict__ Gx, const u64* __restrict__ Gy,
        const u64* __restrict__ wcd, const float* __restrict__ wb,
        float* __restrict__ hout){
    extern __shared__ __align__(16) u64 dsm2[];
    u64*   swd = dsm2;                             // [64 i][66]  (w,w)
    u64*   sgx = swd + 64*66;                      // [16 ky][66] (gx,gx)
    u64*   sgy = sgx + 16*66;                      // [16 ky][66]
    float* sh  = (float*)(sgy + 16*66);            // [64 i][132]
    float* sA  = sh + 64*132;                      // [16 ky][132]
    float* sB  = sA + 16*132;                      // [16 ky][132]
    float* sb  = sB + 16*132;                      // [64]
    int tid = threadIdx.x;                         // 256
    int xh = blockIdx.x & 1;
    int y  = (blockIdx.x >> 1) & 255;
    int b  = blockIdx.x >> 9;
    int xg2 = xh * 128;

    const float* hb = hin + ((size_t)(b*64)*256 + y)*256 + xg2;
    #pragma unroll
    for (int k = 0; k < 8; ++k){
        int idx = tid + k*256;                     // 2048 float4
        int i = idx >> 5, xq = (idx & 31)*4;
        *(float4*)&sh[i*132 + xq] = *(const float4*)&hb[(size_t)i*65536 + xq];
    }
    #pragma unroll
    for (int k = 0; k < 16; ++k){
        int idx = tid + k*256;                     // 4096 u64
        int i = idx >> 6, o = idx & 63;
        swd[i*66 + o] = wcd[idx];
    }
    {
        const u64* Gxb = Gx + ((size_t)(b*256) + y) * 1024;
        const u64* Gyb = Gy + ((size_t)(b*256) + y) * 1024;
        #pragma unroll
        for (int k = 0; k < 4; ++k){
            int idx = tid + k*256;                 // 1024
            int ky = idx >> 6, o = idx & 63;
            sgx[ky*66 + o] = Gxb[idx];
            sgy[ky*66 + o] = Gyb[idx];
        }
    }
    #pragma unroll
    for (int k = 0; k < 2; ++k){
        int idx = tid + k*256;                     // 512 float4 (sA,sB)
        int ky = idx >> 5, xq = (idx & 31)*4;
        if (ky < 16){
            *(float4*)&sA[ky*132 + xq] = *(const float4*)&g_ic[ky*256 + xg2 + xq];
            *(float4*)&sB[ky*132 + xq] = *(const float4*)&g_is[ky*256 + xg2 + xq];
        }
    }
    if (tid < 64) sb[tid] = wb[tid];
    __syncthreads();

    int w = tid >> 5, l = tid & 31;
    int o0 = ((w & 1)*8 + (l >> 2)) * 4;
    int x0 = ((w >> 1)*4 + (l & 3)) * 8;
    u64 acc[4][4];
    {
        float4 bv = *(const float4*)&sb[o0];
        u64 b0 = fpack2(bv.x, bv.x), b1 = fpack2(bv.y, bv.y);
        u64 b2 = fpack2(bv.z, bv.z), b3 = fpack2(bv.w, bv.w);
        #pragma unroll
        for (int p = 0; p < 4; ++p){ acc[0][p]=b0; acc[1][p]=b1; acc[2][p]=b2; acc[3][p]=b3; }
    }
    #pragma unroll 4
    for (int i = 0; i < 64; ++i){
        ulonglong2 h01 = *(const ulonglong2*)&sh[i*132 + x0];
        ulonglong2 h23 = *(const ulonglong2*)&sh[i*132 + x0 + 4];
        ulonglong2 wA  = *(const ulonglong2*)&swd[i*66 + o0];
        ulonglong2 wB  = *(const ulonglong2*)&swd[i*66 + o0 + 2];
        CMAD(0, wA.x) CMAD(1, wA.y) CMAD(2, wB.x) CMAD(3, wB.y)
    }
    #pragma unroll 4
    for (int ky = 0; ky < 16; ++ky){
        ulonglong2 A01 = *(const ulonglong2*)&sA[ky*132 + x0];
        ulonglong2 A23 = *(const ulonglong2*)&sA[ky*132 + x0 + 4];
        ulonglong2 B01 = *(const ulonglong2*)&sB[ky*132 + x0];
        ulonglong2 B23 = *(const ulonglong2*)&sB[ky*132 + x0 + 4];
        ulonglong2 gxA = *(const ulonglong2*)&sgx[ky*66 + o0];
        ulonglong2 gxB = *(const ulonglong2*)&sgx[ky*66 + o0 + 2];
        ulonglong2 gyA = *(const ulonglong2*)&sgy[ky*66 + o0];
        ulonglong2 gyB = *(const ulonglong2*)&sgy[ky*66 + o0 + 2];
        IMAD2(0, gxA.x, gyA.x) IMAD2(1, gxA.y, gyA.y)
        IMAD2(2, gxB.x, gyB.x) IMAD2(3, gxB.y, gyB.y)
    }
    float* ob = hout + ((size_t)(b*64 + o0)*256 + y)*256 + xg2 + x0;
    #pragma unroll
    for (int oo = 0; oo < 4; ++oo){
        float2 p0 = funpack2(acc[oo][0]), p1 = funpack2(acc[oo][1]);
        float2 p2 = funpack2(acc[oo][2]), p3 = funpack2(acc[oo][3]);
        float4 v0 = make_float4(fmaxf(p0.x,0.f), fmaxf(p0.y,0.f), fmaxf(p1.x,0.f), fmaxf(p1.y,0.f));
        float4 v1 = make_float4(fmaxf(p2.x,0.f), fmaxf(p2.y,0.f), fmaxf(p3.x,0.f), fmaxf(p3.y,0.f));
        *(float4*)&ob[(size_t)oo*65536]     = v0;
        *(float4*)&ob[(size_t)oo*65536 + 4] = v1;
    }
}

// ---------------- fused MLP head (dup'd w1 from global) ----------------
// smem 120832 B
#define HMAD(mm, wd) \
    acc[mm][0]=ffma2(wd,h01.x,acc[mm][0]); acc[mm][1]=ffma2(wd,h01.y,acc[mm][1]); \
    acc[mm][2]=ffma2(wd,h23.x,acc[mm][2]); acc[mm][3]=ffma2(wd,h23.y,acc[mm][3]);

__global__ __launch_bounds__(256) void khead(
        const float* __restrict__ hin, const u64* __restrict__ w1d,
        const float* __restrict__ b1,
        const float* __restrict__ w2, const float* __restrict__ b2,
        float* __restrict__ out){
    extern __shared__ __align__(16) u64 dsm3[];
    u64*   sw1d = dsm3;                            // [64 c][130] (w,w)
    float* sh   = (float*)(sw1d + 64*130);         // [64 c][68]
    float* shid = sh + 64*68;                      // [128 m][68]
    float* sw2s = shid + 128*68;                   // [384]
    float* sb1s = sw2s + 384;                      // [128]
    int tid = threadIdx.x;                         // 256
    int xc = (blockIdx.x & 3) << 6;
    int y  = (blockIdx.x >> 2) & 255;
    int b  = blockIdx.x >> 10;

    const float* hb = hin + ((size_t)(b*64)*256 + y)*256 + xc;
    #pragma unroll
    for (int k = 0; k < 4; ++k){
        int idx = tid + k*256;
        int c = idx >> 4, xq = (idx & 15)*4;
        *(float4*)&sh[c*68 + xq] = *(const float4*)&hb[(size_t)c*65536 + xq];
    }
    #pragma unroll
    for (int k = 0; k < 32; ++k){
        int idx = tid + k*256;                     // 8192 u64
        int c = idx >> 7, m = idx & 127;
        sw1d[c*130 + m] = w1d[idx];
    }
    for (int idx = tid; idx < 384; idx += 256) sw2s[idx] = w2[idx];
    if (tid < 128) sb1s[tid] = b1[tid];
    __syncthreads();

    int w = tid >> 5, l = tid & 31;
    int m0 = ((w & 3)*8 + (l >> 2)) * 4;
    int x0 = ((w >> 2)*4 + (l & 3)) * 8;
    u64 acc[4][4];
    {
        float4 bv = *(const float4*)&sb1s[m0];
        u64 b0v = fpack2(bv.x,bv.x), b1v = fpack2(bv.y,bv.y);
        u64 b2v = fpack2(bv.z,bv.z), b3v = fpack2(bv.w,bv.w);
        #pragma unroll
        for (int p = 0; p < 4; ++p){ acc[0][p]=b0v; acc[1][p]=b1v; acc[2][p]=b2v; acc[3][p]=b3v; }
    }
    #pragma unroll 4
    for (int c = 0; c < 64; ++c){
        ulonglong2 h01 = *(const ulonglong2*)&sh[c*68 + x0];
        ulonglong2 h23 = *(const ulonglong2*)&sh[c*68 + x0 + 4];
        ulonglong2 wA  = *(const ulonglong2*)&sw1d[c*130 + m0];
        ulonglong2 wB  = *(const ulonglong2*)&sw1d[c*130 + m0 + 2];
        HMAD(0, wA.x) HMAD(1, wA.y) HMAD(2, wB.x) HMAD(3, wB.y)
    }
    #pragma unroll
    for (int mm = 0; mm < 4; ++mm){
        float2 p0 = funpack2(acc[mm][0]), p1 = funpack2(acc[mm][1]);
        float2 p2 = funpack2(acc[mm][2]), p3 = funpack2(acc[mm][3]);
        float4 v0 = make_float4(fmaxf(p0.x,0.f), fmaxf(p0.y,0.f), fmaxf(p1.x,0.f), fmaxf(p1.y,0.f));
        float4 v1 = make_float4(fmaxf(p2.x,0.f), fmaxf(p2.y,0.f), fmaxf(p3.x,0.f), fmaxf(p3.y,0.f));
        *(float4*)&shid[(m0+mm)*68 + x0]     = v0;
        *(float4*)&shid[(m0+mm)*68 + x0 + 4] = v1;
    }
    __syncthreads();
    if (tid < 192){
        int o = tid >> 6, xl = tid & 63;
        float a = b2[o];
        #pragma unroll 8
        for (int m = 0; m < 128; ++m)
            a = fmaf(shid[m*68 + xl], sw2s[o*128 + m], a);
        out[((size_t)(b*3 + o)*256 + y)*256 + xc + xl] = a;
    }
}

// ---------------- host ----------------
extern "C" void kernel_launch(void* const* d_in, const int* in_sizes, int n_in,
                              void* d_out, int out_size) {
    const float* x       = (const float*)d_in[0];
    const float* fc0_w   = (const float*)d_in[1];
    const float* fc0_b   = (const float*)d_in[2];
    const float* spec_re = (const float*)d_in[3];
    const float* spec_im = (const float*)d_in[4];
    const float* w_w     = (const float*)d_in[5];
    const float* w_b     = (const float*)d_in[6];
    const float* fc1_w   = (const float*)d_in[7];
    const float* fc1_b   = (const float*)d_in[8];
    const float* fc2_w   = (const float*)d_in[9];
    const float* fc2_b   = (const float*)d_in[10];

    float  *h0, *h1;
    float2 *f1, *mo, *mx, *wt;
    u64 *Gx, *Gy, *wcd, *w1d;
    cudaGetSymbolAddress((void**)&h0, g_h0);
    cudaGetSymbolAddress((void**)&h1, g_h1);
    cudaGetSymbolAddress((void**)&f1, g_f1);
    cudaGetSymbolAddress((void**)&mo, g_modes);
    cudaGetSymbolAddress((void**)&mx, g_mixed);
    cudaGetSymbolAddress((void**)&Gx, g_Gx);
    cudaGetSymbolAddress((void**)&Gy, g_Gy);
    cudaGetSymbolAddress((void**)&wt, g_wt);
    cudaGetSymbolAddress((void**)&wcd, g_wcd);
    cudaGetSymbolAddress((void**)&w1d, g_w1d);

    const int SM1 = (16*516 + 128*68) * 4;                          // 67840
    const int SM2 = (64*66 + 32*66)*8 + (64*132 + 32*132 + 64)*4;   // 101632
    const int SM3 = 64*130*8 + (64*68 + 128*68 + 384 + 128)*4;      // 120832
    cudaFuncSetAttribute(kfwd1,  cudaFuncAttributeMaxDynamicSharedMemorySize, SM1);
    cudaFuncSetAttribute(kfused, cudaFuncAttributeMaxDynamicSharedMemorySize, SM2);
    cudaFuncSetAttribute(khead,  cudaFuncAttributeMaxDynamicSharedMemorySize, SM3);

    kprep<<<64, 256>>>(w_w, fc1_w);
    ktw<<<16384, 256>>>(spec_re, spec_im);
    kfc0<<<32768, 256>>>(x, fc0_w, fc0_b, h0);

    float* hin = h0;
    float* hout = h1;
    for (int d = 0; d < NDEPTH; ++d) {
        kfwd1<<<1024, 256, SM1>>>(hin, f1);
        kfwd2<<<512, 512>>>(f1, mo);
        kmix<<<256, 256>>>(mo, wt + (size_t)d * 256 * 4096, mx);
        kinv1<<<2048, 256>>>(mx, Gx, Gy);
        kfused<<<4096, 256, SM2>>>(hin, Gx, Gy, wcd + (size_t)d * 4096, w_b + d * 64, hout);
        float* t = hin; hin = hout; hout = t;
    }
    khead<<<8192, 256, SM3>>>(hin, w1d, fc1_b, fc2_w, fc2_b, (float*)d_out);
}

// round 10
// speedup vs baseline: 1.0840x; 1.0840x over previous
#include <cuda_runtime.h>

#define NDEPTH 4
typedef unsigned long long u64;

__device__ __forceinline__ u64 ffma2(u64 a, u64 b, u64 c){
    u64 d; asm("fma.rn.f32x2 %0, %1, %2, %3;" : "=l"(d) : "l"(a), "l"(b), "l"(c)); return d;
}
__device__ __forceinline__ u64 fpack2(float x, float y){
    u64 d; asm("mov.b64 %0, {%1, %2};" : "=l"(d) : "f"(x), "f"(y)); return d;
}
__device__ __forceinline__ float2 funpack2(u64 a){
    float x, y; asm("mov.b64 {%0, %1}, %2;" : "=f"(x), "=f"(y) : "l"(a)); return make_float2(x, y);
}

// ---------------- scratch (device globals) ----------------
__device__ float  g_h0[8*64*65536];
__device__ float  g_h1[8*64*65536];
__device__ float2 g_f1[8*64*256*16];
__device__ float2 g_modes[8*64*256];
__device__ float2 g_mixed[8*64*256];               // mixedT [b][ky][kx][o]
__device__ float2 g_G[8*256*16*64];                // [b][y][ky][c]
__device__ float2 g_wt[NDEPTH*256*64*64];          // [d][m][i][o]
__device__ float  g_ec[16*256], g_es[16*256];      // fwd: cos, -sin
__device__ float  g_ic[16*256], g_is[16*256];      // inv-W scaled tables

// ---------------- prep: DFT tables ----------------
__global__ void kprep(){
    int idx = blockIdx.x * 256 + threadIdx.x;      // 4096 = [ky][x]
    int x = idx & 255, ky = idx >> 8;
    float ang = 6.283185307179586f * (float)((ky * x) & 255) / 256.f;
    float c = cosf(ang), s = sinf(ang);
    g_ec[idx] = c; g_es[idx] = -s;
    const float sc = 1.f / 65536.f;
    g_ic[idx] = (ky == 0) ? sc : 2.f * sc * c;
    g_is[idx] = (ky == 0) ? 0.f : -2.f * sc * s;
}

// ---------------- spectral weight transpose ----------------
__global__ void ktw(const float* __restrict__ wre, const float* __restrict__ wim){
    int idx = blockIdx.x * 256 + threadIdx.x;
    int ky = idx & 15, kx = (idx >> 4) & 15, o = (idx >> 8) & 63, i = (idx >> 14) & 63, d = idx >> 20;
    int m = kx * 16 + ky;
    g_wt[((d * 256 + m) * 64 + i) * 64 + o] = make_float2(wre[idx], wim[idx]);
}

// ---------------- fc0 ----------------
__global__ void kfc0(const float* __restrict__ x, const float* __restrict__ w,
                     const float* __restrict__ bv, float* __restrict__ out){
    int idx = blockIdx.x * 256 + threadIdx.x;
    int p4 = idx & 16383;
    int c  = (idx >> 14) & 63;
    int b  = idx >> 20;
    const float* xb = x + (size_t)b * 3 * 65536 + p4 * 4;
    float4 a0 = *(const float4*)&xb[0];
    float4 a1 = *(const float4*)&xb[65536];
    float4 a2 = *(const float4*)&xb[131072];
    float w0 = w[c*3], w1 = w[c*3+1], w2 = w[c*3+2], bb = bv[c];
    float4 r;
    r.x = bb + a0.x*w0 + a1.x*w1 + a2.x*w2;
    r.y = bb + a0.y*w0 + a1.y*w1 + a2.y*w2;
    r.z = bb + a0.z*w0 + a1.z*w1 + a2.z*w2;
    r.w = bb + a0.w*w0 + a1.w*w1 + a2.w*w2;
    *(float4*)&out[(size_t)idx * 4] = r;
}

// ---------------- fwd DFT along W: x-paired f32x2 (R9 version, measured 70.8us) ----------------
__global__ __launch_bounds__(256) void kfwd1(const float* __restrict__ hin, float2* __restrict__ f1){
    extern __shared__ __align__(16) float dsm1[];
    float* tcp_c = dsm1;                           // 8*516
    float* tcp_s = dsm1 + 8*516;
    float* sh    = dsm1 + 16*516;                  // 128*68
    int tid = threadIdx.x;
    size_t rowbase = (size_t)blockIdx.x * 128;
    #pragma unroll
    for (int k = 0; k < 16; ++k){
        int idx = tid + k*256;                     // 4096 per table
        int e = idx & 1, ky = (idx >> 1) & 1, xp = (idx >> 2) & 127, kg = idx >> 9;
        int kyg = kg*2 + ky, x = xp*2 + e;
        int dst = kg*516 + xp*4 + ky*2 + e;
        tcp_c[dst] = g_ec[kyg*256 + x];
        tcp_s[dst] = g_es[kyg*256 + x];
    }
    int kg = tid & 7, rg = tid >> 3;
    int r0 = rg*4, ky0 = kg*2;
    const float* tc = &tcp_c[kg*516];
    const float* ts = &tcp_s[kg*516];
    u64 ar[4][2], ai[4][2];
    #pragma unroll
    for (int j = 0; j < 4; ++j){ ar[j][0]=ar[j][1]=ai[j][0]=ai[j][1]=0ull; }

    for (int ch = 0; ch < 4; ++ch){
        int xb = ch*64;
        __syncthreads();
        #pragma unroll
        for (int k = 0; k < 8; ++k){
            int idx = tid + k*256;                 // 2048 float4
            int r = idx >> 4, blk = idx & 15;
            float4 v = *(const float4*)&hin[(rowbase + r)*256 + xb + blk*4];
            *(float4*)&sh[r*68 + ((blk ^ ((r>>1)&7))<<2)] = v;
        }
        __syncthreads();
        #pragma unroll 4
        for (int xl = 0; xl < 64; xl += 4){
            int xp4 = (xb + xl)*2;
            ulonglong2 A  = *(const ulonglong2*)&tc[xp4];
            ulonglong2 B  = *(const ulonglong2*)&tc[xp4 + 4];
            ulonglong2 Sa = *(const ulonglong2*)&ts[xp4];
            ulonglong2 Sb = *(const ulonglong2*)&ts[xp4 + 4];
            #pragma unroll
            for (int j = 0; j < 4; ++j){
                int r = r0 + j;
                ulonglong2 h = *(const ulonglong2*)&sh[r*68 + (((xl>>2) ^ ((r>>1)&7))<<2)];
                ar[j][0] = ffma2(h.x, A.x,  ar[j][0]);
                ar[j][0] = ffma2(h.y, B.x,  ar[j][0]);
                ai[j][0] = ffma2(h.x, Sa.x, ai[j][0]);
                ai[j][0] = ffma2(h.y, Sb.x, ai[j][0]);
                ar[j][1] = ffma2(h.x, A.y,  ar[j][1]);
                ar[j][1] = ffma2(h.y, B.y,  ar[j][1]);
                ai[j][1] = ffma2(h.x, Sa.y, ai[j][1]);
                ai[j][1] = ffma2(h.y, Sb.y, ai[j][1]);
            }
        }
    }
    #pragma unroll
    for (int j = 0; j < 4; ++j){
        float2 re0 = funpack2(ar[j][0]), im0 = funpack2(ai[j][0]);
        float2 re1 = funpack2(ar[j][1]), im1 = funpack2(ai[j][1]);
        float4 o = make_float4(re0.x+re0.y, im0.x+im0.y, re1.x+re1.y, im1.x+im1.y);
        *(float4*)&f1[(rowbase + r0 + j)*16 + ky0] = o;
    }
}

// ---------------- fwd DFT along H, split-K ----------------
__global__ void kfwd2(const float2* __restrict__ f1, float2* __restrict__ modes){
    __shared__ float2 sf[4096];
    __shared__ float ct[256], st[256];
    __shared__ float2 sred[256];
    int tid = threadIdx.x;                         // 512
    if (tid < 256){
        float ang = 6.283185307179586f * (float)tid / 256.f;
        ct[tid] = cosf(ang); st[tid] = sinf(ang);
    }
    int bc = blockIdx.x;
    const float2* src = f1 + (size_t)bc * 4096;
    for (int idx = tid; idx < 4096; idx += 512) sf[idx] = src[idx];
    __syncthreads();
    int outi = tid & 255;
    int kx = outi >> 4, ky = outi & 15;
    int yb = (tid >> 8) * 128;
    float re0=0.f, im0=0.f, re1=0.f, im1=0.f;
    #pragma unroll 4
    for (int yy = yb; yy < yb + 128; yy += 2){
        float2 v0 = sf[yy*16 + ky];
        int t0 = (kx * yy) & 255;
        float c0 = ct[t0], s0 = st[t0];
        re0 += v0.x*c0 + v0.y*s0;
        im0 += v0.y*c0 - v0.x*s0;
        float2 v1 = sf[(yy+1)*16 + ky];
        int t1 = (kx * (yy+1)) & 255;
        float c1 = ct[t1], s1 = st[t1];
        re1 += v1.x*c1 + v1.y*s1;
        im1 += v1.y*c1 - v1.x*s1;
    }
    float re = re0 + re1, im = im0 + im1;
    if (tid >= 256) sred[outi] = make_float2(re, im);
    __syncthreads();
    if (tid < 256){
        float2 o = sred[outi];
        modes[bc*256 + outi] = make_float2(re + o.x, im + o.y);
    }
}

// ---------------- mode mixing -> mixedT [b][ky][kx][o] ----------------
__global__ void kmix(const float2* __restrict__ modes, const float2* __restrict__ wt,
                     float2* __restrict__ mixedT){
    __shared__ float2 swt[4096];
    __shared__ float2 sin_[512];
    int tid = threadIdx.x, m = blockIdx.x;
    int ky = m & 15, kx = m >> 4;
    const float2* wsrc = wt + (size_t)m * 4096;
    for (int idx = tid; idx < 4096; idx += 256) swt[idx] = wsrc[idx];
    for (int idx = tid; idx < 512; idx += 256){
        int b = idx >> 6, i = idx & 63;
        sin_[idx] = modes[(b*64 + i)*256 + m];
    }
    __syncthreads();
    int o = tid & 63;
    for (int half = 0; half < 2; ++half){
        int b = (tid >> 6) + half * 4;
        float re = 0.f, im = 0.f;
        #pragma unroll 8
        for (int i = 0; i < 64; ++i){
            float2 a = sin_[b*64 + i];
            float2 wv = swt[i*64 + o];
            re += a.x*wv.x - a.y*wv.y;
            im += a.x*wv.y + a.y*wv.x;
        }
        mixedT[((b*16 + ky)*16 + kx)*64 + o] = make_float2(re, im);
    }
}

// ---------------- inv DFT along H: G [b][y][ky][c] (R8 version) ----------------
__global__ void kinv1(const float2* __restrict__ mixedT, float2* __restrict__ G){
    __shared__ float2 sm[1024];
    __shared__ float ct[256], st[256];
    int tid = threadIdx.x;                         // 256
    int ky = blockIdx.x & 15, yg = (blockIdx.x >> 4) & 15, b = blockIdx.x >> 8;
    {
        float ang = 6.283185307179586f * (float)tid / 256.f;
        ct[tid] = cosf(ang); st[tid] = sinf(ang);
    }
    const float2* src = mixedT + (size_t)(b*16 + ky) * 1024;
    for (int idx = tid; idx < 1024; idx += 256) sm[idx] = src[idx];
    __syncthreads();
    int c = tid & 63, yl = tid >> 6;
    #pragma unroll
    for (int yi = 0; yi < 4; ++yi){
        int yy = yg*16 + yl*4 + yi;
        float re = 0.f, im = 0.f;
        #pragma unroll
        for (int kx = 0; kx < 16; ++kx){
            float2 v = sm[kx*64 + c];
            int t = (kx * yy) & 255;
            float cc = ct[t], ss = st[t];
            re += v.x*cc - v.y*ss;
            im += v.x*ss + v.y*cc;
        }
        G[((size_t)(b*256 + yy)*16 + ky)*64 + c] = make_float2(re, im);
    }
}

// ---------------- fused: 1x1 conv + inv DFT along W + bias + relu ----------------
// R8 interfaces; dup-pack at smem-fill time; smem 101632 B (2 blocks/SM)
#define CMAD(oo, wd) \
    acc[oo][0]=ffma2(wd,h01.x,acc[oo][0]); acc[oo][1]=ffma2(wd,h01.y,acc[oo][1]); \
    acc[oo][2]=ffma2(wd,h23.x,acc[oo][2]); acc[oo][3]=ffma2(wd,h23.y,acc[oo][3]);
#define IMAD2(oo, gxd, gyd) \
    acc[oo][0]=ffma2(gxd,A01.x,acc[oo][0]); acc[oo][0]=ffma2(gyd,B01.x,acc[oo][0]); \
    acc[oo][1]=ffma2(gxd,A01.y,acc[oo][1]); acc[oo][1]=ffma2(gyd,B01.y,acc[oo][1]); \
    acc[oo][2]=ffma2(gxd,A23.x,acc[oo][2]); acc[oo][2]=ffma2(gyd,B23.x,acc[oo][2]); \
    acc[oo][3]=ffma2(gxd,A23.y,acc[oo][3]); acc[oo][3]=ffma2(gyd,B23.y,acc[oo][3]);

__global__ __launch_bounds__(256) void kfused(
        const float* __restrict__ hin, const float2* __restrict__ G,
        const float* __restrict__ ww, const float* __restrict__ wb,
        float* __restrict__ hout){
    extern __shared__ __align__(16) u64 dsm2[];
    u64*   swd = dsm2;                             // [64 i][66]  (w,w)
    u64*   sgx = swd + 64*66;                      // [16 ky][66] (gx,gx)
    u64*   sgy = sgx + 16*66;                      // [16 ky][66] (gy,gy)
    float* sh  = (float*)(sgy + 16*66);            // [64 i][132]
    float* sA  = sh + 64*132;                      // [16 ky][132]
    float* sB  = sA + 16*132;                      // [16 ky][132]
    float* sb  = sB + 16*132;                      // [64]
    int tid = threadIdx.x;                         // 256
    int xh = blockIdx.x & 1;
    int y  = (blockIdx.x >> 1) & 255;
    int b  = blockIdx.x >> 9;
    int xg2 = xh * 128;

    const float* hb = hin + ((size_t)(b*64)*256 + y)*256 + xg2;
    #pragma unroll
    for (int k = 0; k < 8; ++k){
        int idx = tid + k*256;                     // 2048 float4
        int i = idx >> 5, xq = (idx & 31)*4;
        *(float4*)&sh[i*132 + xq] = *(const float4*)&hb[(size_t)i*65536 + xq];
    }
    #pragma unroll
    for (int k = 0; k < 16; ++k){
        int idx = tid + k*256;                     // 4096: swd[i][o] = dup(ww[o][i])
        int i = idx & 63, o = idx >> 6;
        float w = ww[idx];
        swd[i*66 + o] = fpack2(w, w);
    }
    {
        const float2* Gb = G + ((size_t)(b*256) + y) * 1024;
        #pragma unroll
        for (int k = 0; k < 4; ++k){
            int idx = tid + k*256;                 // 1024
            int ky = idx >> 6, o = idx & 63;
            float2 g = Gb[idx];
            sgx[ky*66 + o] = fpack2(g.x, g.x);
            sgy[ky*66 + o] = fpack2(g.y, g.y);
        }
    }
    #pragma unroll
    for (int k = 0; k < 2; ++k){
        int idx = tid + k*256;                     // 512 float4 (sA,sB)
        int ky = idx >> 5, xq = (idx & 31)*4;
        if (ky < 16){
            *(float4*)&sA[ky*132 + xq] = *(const float4*)&g_ic[ky*256 + xg2 + xq];
            *(float4*)&sB[ky*132 + xq] = *(const float4*)&g_is[ky*256 + xg2 + xq];
        }
    }
    if (tid < 64) sb[tid] = wb[tid];
    __syncthreads();

    int w = tid >> 5, l = tid & 31;
    int o0 = ((w & 1)*8 + (l >> 2)) * 4;
    int x0 = ((w >> 1)*4 + (l & 3)) * 8;
    u64 acc[4][4];
    {
        float4 bv = *(const float4*)&sb[o0];
        u64 b0 = fpack2(bv.x, bv.x), b1 = fpack2(bv.y, bv.y);
        u64 b2 = fpack2(bv.z, bv.z), b3 = fpack2(bv.w, bv.w);
        #pragma unroll
        for (int p = 0; p < 4; ++p){ acc[0][p]=b0; acc[1][p]=b1; acc[2][p]=b2; acc[3][p]=b3; }
    }
    #pragma unroll 4
    for (int i = 0; i < 64; ++i){
        ulonglong2 h01 = *(const ulonglong2*)&sh[i*132 + x0];
        ulonglong2 h23 = *(const ulonglong2*)&sh[i*132 + x0 + 4];
        ulonglong2 wA  = *(const ulonglong2*)&swd[i*66 + o0];
        ulonglong2 wB  = *(const ulonglong2*)&swd[i*66 + o0 + 2];
        CMAD(0, wA.x) CMAD(1, wA.y) CMAD(2, wB.x) CMAD(3, wB.y)
    }
    #pragma unroll 4
    for (int ky = 0; ky < 16; ++ky){
        ulonglong2 A01 = *(const ulonglong2*)&sA[ky*132 + x0];
        ulonglong2 A23 = *(const ulonglong2*)&sA[ky*132 + x0 + 4];
        ulonglong2 B01 = *(const ulonglong2*)&sB[ky*132 + x0];
        ulonglong2 B23 = *(const ulonglong2*)&sB[ky*132 + x0 + 4];
        ulonglong2 gxA = *(const ulonglong2*)&sgx[ky*66 + o0];
        ulonglong2 gxB = *(const ulonglong2*)&sgx[ky*66 + o0 + 2];
        ulonglong2 gyA = *(const ulonglong2*)&sgy[ky*66 + o0];
        ulonglong2 gyB = *(const ulonglong2*)&sgy[ky*66 + o0 + 2];
        IMAD2(0, gxA.x, gyA.x) IMAD2(1, gxA.y, gyA.y)
        IMAD2(2, gxB.x, gyB.x) IMAD2(3, gxB.y, gyB.y)
    }
    float* ob = hout + ((size_t)(b*64 + o0)*256 + y)*256 + xg2 + x0;
    #pragma unroll
    for (int oo = 0; oo < 4; ++oo){
        float2 p0 = funpack2(acc[oo][0]), p1 = funpack2(acc[oo][1]);
        float2 p2 = funpack2(acc[oo][2]), p3 = funpack2(acc[oo][3]);
        float4 v0 = make_float4(fmaxf(p0.x,0.f), fmaxf(p0.y,0.f), fmaxf(p1.x,0.f), fmaxf(p1.y,0.f));
        float4 v1 = make_float4(fmaxf(p2.x,0.f), fmaxf(p2.y,0.f), fmaxf(p3.x,0.f), fmaxf(p3.y,0.f));
        *(float4*)&ob[(size_t)oo*65536]     = v0;
        *(float4*)&ob[(size_t)oo*65536 + 4] = v1;
    }
}

// ---------------- fused MLP head (R8 version, 87552 B -> 2 blocks/SM) ----------------
#define HMAD(mm, wd) \
    acc[mm][0]=ffma2(wd,h01.x,acc[mm][0]); acc[mm][1]=ffma2(wd,h01.y,acc[mm][1]); \
    acc[mm][2]=ffma2(wd,h23.x,acc[mm][2]); acc[mm][3]=ffma2(wd,h23.y,acc[mm][3]);

__global__ __launch_bounds__(256) void khead(
        const float* __restrict__ hin,
        const float* __restrict__ w1, const float* __restrict__ b1,
        const float* __restrict__ w2, const float* __restrict__ b2,
        float* __restrict__ out){
    extern __shared__ __align__(16) float dsm3[];
    float* sh   = dsm3;                            // [64 c][68]
    float* sw1t = sh + 64*68;                      // [64 c][130]  w1^T [c][m]
    float* shid = sw1t + 64*130;                   // [128 m][68]
    float* sw2s = shid + 128*68;                   // [384]
    float* sb1s = sw2s + 384;                      // [128]
    int tid = threadIdx.x;                         // 256
    int xc = (blockIdx.x & 3) << 6;
    int y  = (blockIdx.x >> 2) & 255;
    int b  = blockIdx.x >> 10;

    const float* hb = hin + ((size_t)(b*64)*256 + y)*256 + xc;
    #pragma unroll
    for (int k = 0; k < 4; ++k){
        int idx = tid + k*256;                     // 1024 float4
        int c = idx >> 4, xq = (idx & 15)*4;
        *(float4*)&sh[c*68 + xq] = *(const float4*)&hb[(size_t)c*65536 + xq];
    }
    #pragma unroll
    for (int k = 0; k < 32; ++k){
        int idx = tid + k*256;                     // 8192: sw1t[c][m] = w1[m][c]
        int c = idx & 63, m = idx >> 6;
        sw1t[c*130 + m] = w1[idx];
    }
    for (int idx = tid; idx < 384; idx += 256) sw2s[idx] = w2[idx];
    if (tid < 128) sb1s[tid] = b1[tid];
    __syncthreads();

    int w = tid >> 5, l = tid & 31;
    int m0 = ((w & 3)*8 + (l >> 2)) * 4;
    int x0 = ((w >> 2)*4 + (l & 3)) * 8;
    u64 acc[4][4];
    {
        float4 bv = *(const float4*)&sb1s[m0];
        u64 b0v = fpack2(bv.x,bv.x), b1v = fpack2(bv.y,bv.y);
        u64 b2v = fpack2(bv.z,bv.z), b3v = fpack2(bv.w,bv.w);
        #pragma unroll
        for (int p = 0; p < 4; ++p){ acc[0][p]=b0v; acc[1][p]=b1v; acc[2][p]=b2v; acc[3][p]=b3v; }
    }
    #pragma unroll 4
    for (int c = 0; c < 64; ++c){
        ulonglong2 h01 = *(const ulonglong2*)&sh[c*68 + x0];
        ulonglong2 h23 = *(const ulonglong2*)&sh[c*68 + x0 + 4];
        float2 wab = *(const float2*)&sw1t[c*130 + m0];
        float2 wcd = *(const float2*)&sw1t[c*130 + m0 + 2];
        u64 w0 = fpack2(wab.x,wab.x), w1d = fpack2(wab.y,wab.y);
        u64 w2d = fpack2(wcd.x,wcd.x), w3d = fpack2(wcd.y,wcd.y);
        HMAD(0, w0) HMAD(1, w1d) HMAD(2, w2d) HMAD(3, w3d)
    }
    #pragma unroll
    for (int mm = 0; mm < 4; ++mm){
        float2 p0 = funpack2(acc[mm][0]), p1 = funpack2(acc[mm][1]);
        float2 p2 = funpack2(acc[mm][2]), p3 = funpack2(acc[mm][3]);
        float4 v0 = make_float4(fmaxf(p0.x,0.f), fmaxf(p0.y,0.f), fmaxf(p1.x,0.f), fmaxf(p1.y,0.f));
        float4 v1 = make_float4(fmaxf(p2.x,0.f), fmaxf(p2.y,0.f), fmaxf(p3.x,0.f), fmaxf(p3.y,0.f));
        *(float4*)&shid[(m0+mm)*68 + x0]     = v0;
        *(float4*)&shid[(m0+mm)*68 + x0 + 4] = v1;
    }
    __syncthreads();
    if (tid < 192){
        int o = tid >> 6, xl = tid & 63;
        float a = b2[o];
        #pragma unroll 8
        for (int m = 0; m < 128; ++m)
            a = fmaf(shid[m*68 + xl], sw2s[o*128 + m], a);
        out[((size_t)(b*3 + o)*256 + y)*256 + xc + xl] = a;
    }
}

// ---------------- host ----------------
extern "C" void kernel_launch(void* const* d_in, const int* in_sizes, int n_in,
                              void* d_out, int out_size) {
    const float* x       = (const float*)d_in[0];
    const float* fc0_w   = (const float*)d_in[1];
    const float* fc0_b   = (const float*)d_in[2];
    const float* spec_re = (const float*)d_in[3];
    const float* spec_im = (const float*)d_in[4];
    const float* w_w     = (const float*)d_in[5];
    const float* w_b     = (const float*)d_in[6];
    const float* fc1_w   = (const float*)d_in[7];
    const float* fc1_b   = (const float*)d_in[8];
    const float* fc2_w   = (const float*)d_in[9];
    const float* fc2_b   = (const float*)d_in[10];

    float  *h0, *h1;
    float2 *f1, *mo, *mx, *G, *wt;
    cudaGetSymbolAddress((void**)&h0, g_h0);
    cudaGetSymbolAddress((void**)&h1, g_h1);
    cudaGetSymbolAddress((void**)&f1, g_f1);
    cudaGetSymbolAddress((void**)&mo, g_modes);
    cudaGetSymbolAddress((void**)&mx, g_mixed);
    cudaGetSymbolAddress((void**)&G,  g_G);
    cudaGetSymbolAddress((void**)&wt, g_wt);

    const int SM1 = (16*516 + 128*68) * 4;                          // 67840
    const int SM2 = (64*66 + 32*66)*8 + (64*132 + 32*132 + 64)*4;   // 101632
    const int SM3 = (64*68 + 64*130 + 128*68)*4 + 384*4 + 128*4;    // 87552
    cudaFuncSetAttribute(kfwd1,  cudaFuncAttributeMaxDynamicSharedMemorySize, SM1);
    cudaFuncSetAttribute(kfused, cudaFuncAttributeMaxDynamicSharedMemorySize, SM2);
    cudaFuncSetAttribute(khead,  cudaFuncAttributeMaxDynamicSharedMemorySize, SM3);

    kprep<<<16, 256>>>();
    ktw<<<16384, 256>>>(spec_re, spec_im);
    kfc0<<<32768, 256>>>(x, fc0_w, fc0_b, h0);

    float* hin = h0;
    float* hout = h1;
    for (int d = 0; d < NDEPTH; ++d) {
        kfwd1<<<1024, 256, SM1>>>(hin, f1);
        kfwd2<<<512, 512>>>(f1, mo);
        kmix<<<256, 256>>>(mo, wt + (size_t)d * 256 * 4096, mx);
        kinv1<<<2048, 256>>>(mx, G);
        kfused<<<4096, 256, SM2>>>(hin, G, w_w + d * 4096, w_b + d * 64, hout);
        float* t = hin; hin = hout; hout = t;
    }
    khead<<<8192, 256, SM3>>>(hin, fc1_w, fc1_b, fc2_w, fc2_b, (float*)d_out);
}

// round 11
// speedup vs baseline: 1.1917x; 1.0994x over previous
#include <cuda_runtime.h>

#define NDEPTH 4
typedef unsigned long long u64;

__device__ __forceinline__ u64 ffma2(u64 a, u64 b, u64 c){
    u64 d; asm("fma.rn.f32x2 %0, %1, %2, %3;" : "=l"(d) : "l"(a), "l"(b), "l"(c)); return d;
}
__device__ __forceinline__ u64 fpack2(float x, float y){
    u64 d; asm("mov.b64 %0, {%1, %2};" : "=l"(d) : "f"(x), "f"(y)); return d;
}
__device__ __forceinline__ float2 funpack2(u64 a){
    float x, y; asm("mov.b64 {%0, %1}, %2;" : "=f"(x), "=f"(y) : "l"(a)); return make_float2(x, y);
}

// ---------------- scratch (device globals) ----------------
__device__ float  g_h0[8*64*65536];
__device__ float  g_h1[8*64*65536];
__device__ float2 g_f1[8*64*256*16];
__device__ float2 g_modes[8*64*256];
__device__ float2 g_mixed[8*64*256];               // mixedT [b][ky][kx][o]
__device__ float2 g_G[8*256*16*64];                // [b][y][ky][c]
__device__ float2 g_wt[NDEPTH*256*64*64];          // [d][m][i][o]
__device__ float  g_ec[16*256], g_es[16*256];      // fwd: cos, -sin
__device__ float  g_ic[16*256], g_is[16*256];      // inv-W scaled tables

// ---------------- prep: DFT tables ----------------
__global__ void kprep(){
    int idx = blockIdx.x * 256 + threadIdx.x;      // 4096 = [ky][x]
    int x = idx & 255, ky = idx >> 8;
    float ang = 6.283185307179586f * (float)((ky * x) & 255) / 256.f;
    float c = cosf(ang), s = sinf(ang);
    g_ec[idx] = c; g_es[idx] = -s;
    const float sc = 1.f / 65536.f;
    g_ic[idx] = (ky == 0) ? sc : 2.f * sc * c;
    g_is[idx] = (ky == 0) ? 0.f : -2.f * sc * s;
}

// ---------------- spectral weight transpose ----------------
__global__ void ktw(const float* __restrict__ wre, const float* __restrict__ wim){
    int idx = blockIdx.x * 256 + threadIdx.x;
    int ky = idx & 15, kx = (idx >> 4) & 15, o = (idx >> 8) & 63, i = (idx >> 14) & 63, d = idx >> 20;
    int m = kx * 16 + ky;
    g_wt[((d * 256 + m) * 64 + i) * 64 + o] = make_float2(wre[idx], wim[idx]);
}

// ---------------- fc0 ----------------
__global__ void kfc0(const float* __restrict__ x, const float* __restrict__ w,
                     const float* __restrict__ bv, float* __restrict__ out){
    int idx = blockIdx.x * 256 + threadIdx.x;
    int p4 = idx & 16383;
    int c  = (idx >> 14) & 63;
    int b  = idx >> 20;
    const float* xb = x + (size_t)b * 3 * 65536 + p4 * 4;
    float4 a0 = *(const float4*)&xb[0];
    float4 a1 = *(const float4*)&xb[65536];
    float4 a2 = *(const float4*)&xb[131072];
    float w0 = w[c*3], w1 = w[c*3+1], w2 = w[c*3+2], bb = bv[c];
    float4 r;
    r.x = bb + a0.x*w0 + a1.x*w1 + a2.x*w2;
    r.y = bb + a0.y*w0 + a1.y*w1 + a2.y*w2;
    r.z = bb + a0.z*w0 + a1.z*w1 + a2.z*w2;
    r.w = bb + a0.w*w0 + a1.w*w1 + a2.w*w2;
    *(float4*)&out[(size_t)idx * 4] = r;
}

// ---------------- fwd DFT along W: x-paired f32x2 (R9 version, measured 71us) ----------------
__global__ __launch_bounds__(256) void kfwd1(const float* __restrict__ hin, float2* __restrict__ f1){
    extern __shared__ __align__(16) float dsm1[];
    float* tcp_c = dsm1;                           // 8*516
    float* tcp_s = dsm1 + 8*516;
    float* sh    = dsm1 + 16*516;                  // 128*68
    int tid = threadIdx.x;
    size_t rowbase = (size_t)blockIdx.x * 128;
    #pragma unroll
    for (int k = 0; k < 16; ++k){
        int idx = tid + k*256;                     // 4096 per table
        int e = idx & 1, ky = (idx >> 1) & 1, xp = (idx >> 2) & 127, kg = idx >> 9;
        int kyg = kg*2 + ky, x = xp*2 + e;
        int dst = kg*516 + xp*4 + ky*2 + e;
        tcp_c[dst] = g_ec[kyg*256 + x];
        tcp_s[dst] = g_es[kyg*256 + x];
    }
    int kg = tid & 7, rg = tid >> 3;
    int r0 = rg*4, ky0 = kg*2;
    const float* tc = &tcp_c[kg*516];
    const float* ts = &tcp_s[kg*516];
    u64 ar[4][2], ai[4][2];
    #pragma unroll
    for (int j = 0; j < 4; ++j){ ar[j][0]=ar[j][1]=ai[j][0]=ai[j][1]=0ull; }

    for (int ch = 0; ch < 4; ++ch){
        int xb = ch*64;
        __syncthreads();
        #pragma unroll
        for (int k = 0; k < 8; ++k){
            int idx = tid + k*256;                 // 2048 float4
            int r = idx >> 4, blk = idx & 15;
            float4 v = *(const float4*)&hin[(rowbase + r)*256 + xb + blk*4];
            *(float4*)&sh[r*68 + ((blk ^ ((r>>1)&7))<<2)] = v;
        }
        __syncthreads();
        #pragma unroll 4
        for (int xl = 0; xl < 64; xl += 4){
            int xp4 = (xb + xl)*2;
            ulonglong2 A  = *(const ulonglong2*)&tc[xp4];
            ulonglong2 B  = *(const ulonglong2*)&tc[xp4 + 4];
            ulonglong2 Sa = *(const ulonglong2*)&ts[xp4];
            ulonglong2 Sb = *(const ulonglong2*)&ts[xp4 + 4];
            #pragma unroll
            for (int j = 0; j < 4; ++j){
                int r = r0 + j;
                ulonglong2 h = *(const ulonglong2*)&sh[r*68 + (((xl>>2) ^ ((r>>1)&7))<<2)];
                ar[j][0] = ffma2(h.x, A.x,  ar[j][0]);
                ar[j][0] = ffma2(h.y, B.x,  ar[j][0]);
                ai[j][0] = ffma2(h.x, Sa.x, ai[j][0]);
                ai[j][0] = ffma2(h.y, Sb.x, ai[j][0]);
                ar[j][1] = ffma2(h.x, A.y,  ar[j][1]);
                ar[j][1] = ffma2(h.y, B.y,  ar[j][1]);
                ai[j][1] = ffma2(h.x, Sa.y, ai[j][1]);
                ai[j][1] = ffma2(h.y, Sb.y, ai[j][1]);
            }
        }
    }
    #pragma unroll
    for (int j = 0; j < 4; ++j){
        float2 re0 = funpack2(ar[j][0]), im0 = funpack2(ai[j][0]);
        float2 re1 = funpack2(ar[j][1]), im1 = funpack2(ai[j][1]);
        float4 o = make_float4(re0.x+re0.y, im0.x+im0.y, re1.x+re1.y, im1.x+im1.y);
        *(float4*)&f1[(rowbase + r0 + j)*16 + ky0] = o;
    }
}

// ---------------- fwd DFT along H, split-K (R8 version) ----------------
__global__ void kfwd2(const float2* __restrict__ f1, float2* __restrict__ modes){
    __shared__ float2 sf[4096];
    __shared__ float ct[256], st[256];
    __shared__ float2 sred[256];
    int tid = threadIdx.x;                         // 512
    if (tid < 256){
        float ang = 6.283185307179586f * (float)tid / 256.f;
        ct[tid] = cosf(ang); st[tid] = sinf(ang);
    }
    int bc = blockIdx.x;
    const float2* src = f1 + (size_t)bc * 4096;
    for (int idx = tid; idx < 4096; idx += 512) sf[idx] = src[idx];
    __syncthreads();
    int outi = tid & 255;
    int kx = outi >> 4, ky = outi & 15;
    int yb = (tid >> 8) * 128;
    float re0=0.f, im0=0.f, re1=0.f, im1=0.f;
    #pragma unroll 4
    for (int yy = yb; yy < yb + 128; yy += 2){
        float2 v0 = sf[yy*16 + ky];
        int t0 = (kx * yy) & 255;
        float c0 = ct[t0], s0 = st[t0];
        re0 += v0.x*c0 + v0.y*s0;
        im0 += v0.y*c0 - v0.x*s0;
        float2 v1 = sf[(yy+1)*16 + ky];
        int t1 = (kx * (yy+1)) & 255;
        float c1 = ct[t1], s1 = st[t1];
        re1 += v1.x*c1 + v1.y*s1;
        im1 += v1.y*c1 - v1.x*s1;
    }
    float re = re0 + re1, im = im0 + im1;
    if (tid >= 256) sred[outi] = make_float2(re, im);
    __syncthreads();
    if (tid < 256){
        float2 o = sred[outi];
        modes[bc*256 + outi] = make_float2(re + o.x, im + o.y);
    }
}

// ---------------- mode mixing -> mixedT [b][ky][kx][o] ----------------
__global__ void kmix(const float2* __restrict__ modes, const float2* __restrict__ wt,
                     float2* __restrict__ mixedT){
    __shared__ float2 swt[4096];
    __shared__ float2 sin_[512];
    int tid = threadIdx.x, m = blockIdx.x;
    int ky = m & 15, kx = m >> 4;
    const float2* wsrc = wt + (size_t)m * 4096;
    for (int idx = tid; idx < 4096; idx += 256) swt[idx] = wsrc[idx];
    for (int idx = tid; idx < 512; idx += 256){
        int b = idx >> 6, i = idx & 63;
        sin_[idx] = modes[(b*64 + i)*256 + m];
    }
    __syncthreads();
    int o = tid & 63;
    for (int half = 0; half < 2; ++half){
        int b = (tid >> 6) + half * 4;
        float re = 0.f, im = 0.f;
        #pragma unroll 8
        for (int i = 0; i < 64; ++i){
            float2 a = sin_[b*64 + i];
            float2 wv = swt[i*64 + o];
            re += a.x*wv.x - a.y*wv.y;
            im += a.x*wv.y + a.y*wv.x;
        }
        mixedT[((b*16 + ky)*16 + kx)*64 + o] = make_float2(re, im);
    }
}

// ---------------- inv DFT along H: G [b][y][ky][c] (R8 version) ----------------
__global__ void kinv1(const float2* __restrict__ mixedT, float2* __restrict__ G){
    __shared__ float2 sm[1024];
    __shared__ float ct[256], st[256];
    int tid = threadIdx.x;                         // 256
    int ky = blockIdx.x & 15, yg = (blockIdx.x >> 4) & 15, b = blockIdx.x >> 8;
    {
        float ang = 6.283185307179586f * (float)tid / 256.f;
        ct[tid] = cosf(ang); st[tid] = sinf(ang);
    }
    const float2* src = mixedT + (size_t)(b*16 + ky) * 1024;
    for (int idx = tid; idx < 1024; idx += 256) sm[idx] = src[idx];
    __syncthreads();
    int c = tid & 63, yl = tid >> 6;
    #pragma unroll
    for (int yi = 0; yi < 4; ++yi){
        int yy = yg*16 + yl*4 + yi;
        float re = 0.f, im = 0.f;
        #pragma unroll
        for (int kx = 0; kx < 16; ++kx){
            float2 v = sm[kx*64 + c];
            int t = (kx * yy) & 255;
            float cc = ct[t], ss = st[t];
            re += v.x*cc - v.y*ss;
            im += v.x*ss + v.y*cc;
        }
        G[((size_t)(b*256 + yy)*16 + ky)*64 + c] = make_float2(re, im);
    }
}

// ---------------- fused: 1x1 conv + inv DFT along W + bias + relu (R8 version) ----------------
#define CMAD(oo, wd) \
    acc[oo][0]=ffma2(wd,h01.x,acc[oo][0]); acc[oo][1]=ffma2(wd,h01.y,acc[oo][1]); \
    acc[oo][2]=ffma2(wd,h23.x,acc[oo][2]); acc[oo][3]=ffma2(wd,h23.y,acc[oo][3]);
#define IMAD2(oo, gxd, gyd) \
    acc[oo][0]=ffma2(gxd,A01.x,acc[oo][0]); acc[oo][0]=ffma2(gyd,B01.x,acc[oo][0]); \
    acc[oo][1]=ffma2(gxd,A01.y,acc[oo][1]); acc[oo][1]=ffma2(gyd,B01.y,acc[oo][1]); \
    acc[oo][2]=ffma2(gxd,A23.x,acc[oo][2]); acc[oo][2]=ffma2(gyd,B23.x,acc[oo][2]); \
    acc[oo][3]=ffma2(gxd,A23.y,acc[oo][3]); acc[oo][3]=ffma2(gyd,B23.y,acc[oo][3]);

__global__ __launch_bounds__(256) void kfused(
        const float* __restrict__ hin, const float2* __restrict__ G,
        const float* __restrict__ ww, const float* __restrict__ wb,
        float* __restrict__ hout){
    extern __shared__ __align__(16) float dsm2[];
    float*  sh = dsm2;                             // [64 i][132]
    float*  sA = sh + 64*132;                      // [16 ky][132]
    float*  sB = sA + 16*132;                      // [16 ky][132]
    float*  sw = sB + 16*132;                      // [64 i][66]  w[i][o]
    float2* sg = (float2*)(sw + 64*66);            // [16 ky][66] (gx,gy)
    float*  sb = (float*)(sg + 16*66);             // [64]
    int tid = threadIdx.x;                         // 256
    int xh = blockIdx.x & 1;
    int y  = (blockIdx.x >> 1) & 255;
    int b  = blockIdx.x >> 9;
    int xg2 = xh * 128;

    const float* hb = hin + ((size_t)(b*64)*256 + y)*256 + xg2;
    for (int k = 0; k < 8; ++k){
        int idx = tid + k*256;                     // 2048 float4
        int i = idx >> 5, xq = (idx & 31)*4;
        *(float4*)&sh[i*132 + xq] = *(const float4*)&hb[(size_t)i*65536 + xq];
    }
    for (int k = 0; k < 2; ++k){
        int idx = tid + k*256;                     // 512 float4 = sA,sB
        int ky = idx >> 5, xq = (idx & 31)*4;
        if (ky < 16){
            *(float4*)&sA[ky*132 + xq] = *(const float4*)&g_ic[ky*256 + xg2 + xq];
            *(float4*)&sB[ky*132 + xq] = *(const float4*)&g_is[ky*256 + xg2 + xq];
        }
    }
    for (int k = 0; k < 16; ++k){
        int idx = tid + k*256;                     // 4096: sw[i][o] = ww[o][i]
        int i = idx & 63, o = idx >> 6;
        sw[i*66 + o] = ww[idx];
    }
    {
        const float2* Gb = G + ((size_t)(b*256) + y) * 1024;
        for (int k = 0; k < 4; ++k){
            int idx = tid + k*256;                 // 1024
            int ky = idx >> 6, o = idx & 63;
            sg[ky*66 + o] = Gb[ky*64 + o];
        }
    }
    if (tid < 64) sb[tid] = wb[tid];
    __syncthreads();

    int w = tid >> 5, l = tid & 31;
    int o0 = ((w & 1)*8 + (l >> 2)) * 4;           // 16 o-groups
    int x0 = ((w >> 1)*4 + (l & 3)) * 8;           // 16 x-groups
    u64 acc[4][4];
    {
        float4 bv = *(const float4*)&sb[o0];
        u64 b0 = fpack2(bv.x, bv.x), b1 = fpack2(bv.y, bv.y);
        u64 b2 = fpack2(bv.z, bv.z), b3 = fpack2(bv.w, bv.w);
        #pragma unroll
        for (int p = 0; p < 4; ++p){ acc[0][p]=b0; acc[1][p]=b1; acc[2][p]=b2; acc[3][p]=b3; }
    }
    #pragma unroll 4
    for (int i = 0; i < 64; ++i){
        ulonglong2 h01 = *(const ulonglong2*)&sh[i*132 + x0];
        ulonglong2 h23 = *(const ulonglong2*)&sh[i*132 + x0 + 4];
        float2 wab = *(const float2*)&sw[i*66 + o0];
        float2 wcd = *(const float2*)&sw[i*66 + o0 + 2];
        u64 w0 = fpack2(wab.x, wab.x), w1 = fpack2(wab.y, wab.y);
        u64 w2 = fpack2(wcd.x, wcd.x), w3 = fpack2(wcd.y, wcd.y);
        CMAD(0, w0) CMAD(1, w1) CMAD(2, w2) CMAD(3, w3)
    }
    #pragma unroll 4
    for (int ky = 0; ky < 16; ++ky){
        ulonglong2 A01 = *(const ulonglong2*)&sA[ky*132 + x0];
        ulonglong2 A23 = *(const ulonglong2*)&sA[ky*132 + x0 + 4];
        ulonglong2 B01 = *(const ulonglong2*)&sB[ky*132 + x0];
        ulonglong2 B23 = *(const ulonglong2*)&sB[ky*132 + x0 + 4];
        float2 ga = sg[ky*66 + o0],     gb2 = sg[ky*66 + o0 + 1];
        float2 gc = sg[ky*66 + o0 + 2], gd  = sg[ky*66 + o0 + 3];
        u64 gx0 = fpack2(ga.x, ga.x),  gy0 = fpack2(ga.y, ga.y);
        u64 gx1 = fpack2(gb2.x, gb2.x), gy1 = fpack2(gb2.y, gb2.y);
        u64 gx2 = fpack2(gc.x, gc.x),  gy2 = fpack2(gc.y, gc.y);
        u64 gx3 = fpack2(gd.x, gd.x),  gy3 = fpack2(gd.y, gd.y);
        IMAD2(0, gx0, gy0) IMAD2(1, gx1, gy1) IMAD2(2, gx2, gy2) IMAD2(3, gx3, gy3)
    }
    float* ob = hout + ((size_t)(b*64 + o0)*256 + y)*256 + xg2 + x0;
    #pragma unroll
    for (int oo = 0; oo < 4; ++oo){
        float2 p0 = funpack2(acc[oo][0]), p1 = funpack2(acc[oo][1]);
        float2 p2 = funpack2(acc[oo][2]), p3 = funpack2(acc[oo][3]);
        float4 v0 = make_float4(fmaxf(p0.x,0.f), fmaxf(p0.y,0.f), fmaxf(p1.x,0.f), fmaxf(p1.y,0.f));
        float4 v1 = make_float4(fmaxf(p2.x,0.f), fmaxf(p2.y,0.f), fmaxf(p3.x,0.f), fmaxf(p3.y,0.f));
        *(float4*)&ob[(size_t)oo*65536]     = v0;
        *(float4*)&ob[(size_t)oo*65536 + 4] = v1;
    }
}

// ---------------- fused MLP head (R8 version) ----------------
#define HMAD(mm, wd) \
    acc[mm][0]=ffma2(wd,h01.x,acc[mm][0]); acc[mm][1]=ffma2(wd,h01.y,acc[mm][1]); \
    acc[mm][2]=ffma2(wd,h23.x,acc[mm][2]); acc[mm][3]=ffma2(wd,h23.y,acc[mm][3]);

__global__ __launch_bounds__(256) void khead(
        const float* __restrict__ hin,
        const float* __restrict__ w1, const float* __restrict__ b1,
        const float* __restrict__ w2, const float* __restrict__ b2,
        float* __restrict__ out){
    extern __shared__ __align__(16) float dsm3[];
    float* sh   = dsm3;                            // [64 c][68]
    float* sw1t = sh + 64*68;                      // [64 c][130]  w1^T [c][m]
    float* shid = sw1t + 64*130;                   // [128 m][68]
    float* sw2s = shid + 128*68;                   // [384]
    float* sb1s = sw2s + 384;                      // [128]
    int tid = threadIdx.x;                         // 256
    int xc = (blockIdx.x & 3) << 6;
    int y  = (blockIdx.x >> 2) & 255;
    int b  = blockIdx.x >> 10;

    const float* hb = hin + ((size_t)(b*64)*256 + y)*256 + xc;
    for (int k = 0; k < 4; ++k){
        int idx = tid + k*256;                     // 1024 float4
        int c = idx >> 4, xq = (idx & 15)*4;
        *(float4*)&sh[c*68 + xq] = *(const float4*)&hb[(size_t)c*65536 + xq];
    }
    for (int k = 0; k < 32; ++k){
        int idx = tid + k*256;                     // 8192: sw1t[c][m] = w1[m][c]
        int c = idx & 63, m = idx >> 6;
        sw1t[c*130 + m] = w1[idx];
    }
    for (int idx = tid; idx < 384; idx += 256) sw2s[idx] = w2[idx];
    if (tid < 128) sb1s[tid] = b1[tid];
    __syncthreads();

    int w = tid >> 5, l = tid & 31;
    int m0 = ((w & 3)*8 + (l >> 2)) * 4;           // 32 m-groups
    int x0 = ((w >> 2)*4 + (l & 3)) * 8;           // 8 x-groups
    u64 acc[4][4];
    {
        float4 bv = *(const float4*)&sb1s[m0];
        u64 b0v = fpack2(bv.x,bv.x), b1v = fpack2(bv.y,bv.y);
        u64 b2v = fpack2(bv.z,bv.z), b3v = fpack2(bv.w,bv.w);
        #pragma unroll
        for (int p = 0; p < 4; ++p){ acc[0][p]=b0v; acc[1][p]=b1v; acc[2][p]=b2v; acc[3][p]=b3v; }
    }
    #pragma unroll 4
    for (int c = 0; c < 64; ++c){
        ulonglong2 h01 = *(const ulonglong2*)&sh[c*68 + x0];
        ulonglong2 h23 = *(const ulonglong2*)&sh[c*68 + x0 + 4];
        float2 wab = *(const float2*)&sw1t[c*130 + m0];
        float2 wcd = *(const float2*)&sw1t[c*130 + m0 + 2];
        u64 w0 = fpack2(wab.x,wab.x), w1d = fpack2(wab.y,wab.y);
        u64 w2d = fpack2(wcd.x,wcd.x), w3d = fpack2(wcd.y,wcd.y);
        HMAD(0, w0) HMAD(1, w1d) HMAD(2, w2d) HMAD(3, w3d)
    }
    #pragma unroll
    for (int mm = 0; mm < 4; ++mm){
        float2 p0 = funpack2(acc[mm][0]), p1 = funpack2(acc[mm][1]);
        float2 p2 = funpack2(acc[mm][2]), p3 = funpack2(acc[mm][3]);
        float4 v0 = make_float4(fmaxf(p0.x,0.f), fmaxf(p0.y,0.f), fmaxf(p1.x,0.f), fmaxf(p1.y,0.f));
        float4 v1 = make_float4(fmaxf(p2.x,0.f), fmaxf(p2.y,0.f), fmaxf(p3.x,0.f), fmaxf(p3.y,0.f));
        *(float4*)&shid[(m0+mm)*68 + x0]     = v0;
        *(float4*)&shid[(m0+mm)*68 + x0 + 4] = v1;
    }
    __syncthreads();
    if (tid < 192){
        int o = tid >> 6, xl = tid & 63;
        float a = b2[o];
        #pragma unroll 8
        for (int m = 0; m < 128; ++m)
            a = fmaf(shid[m*68 + xl], sw2s[o*128 + m], a);
        out[((size_t)(b*3 + o)*256 + y)*256 + xc + xl] = a;
    }
}

// ---------------- host ----------------
extern "C" void kernel_launch(void* const* d_in, const int* in_sizes, int n_in,
                              void* d_out, int out_size) {
    const float* x       = (const float*)d_in[0];
    const float* fc0_w   = (const float*)d_in[1];
    const float* fc0_b   = (const float*)d_in[2];
    const float* spec_re = (const float*)d_in[3];
    const float* spec_im = (const float*)d_in[4];
    const float* w_w     = (const float*)d_in[5];
    const float* w_b     = (const float*)d_in[6];
    const float* fc1_w   = (const float*)d_in[7];
    const float* fc1_b   = (const float*)d_in[8];
    const float* fc2_w   = (const float*)d_in[9];
    const float* fc2_b   = (const float*)d_in[10];

    float  *h0, *h1;
    float2 *f1, *mo, *mx, *G, *wt;
    cudaGetSymbolAddress((void**)&h0, g_h0);
    cudaGetSymbolAddress((void**)&h1, g_h1);
    cudaGetSymbolAddress((void**)&f1, g_f1);
    cudaGetSymbolAddress((void**)&mo, g_modes);
    cudaGetSymbolAddress((void**)&mx, g_mixed);
    cudaGetSymbolAddress((void**)&G,  g_G);
    cudaGetSymbolAddress((void**)&wt, g_wt);

    const int SM1 = (16*516 + 128*68) * 4;                          // 67840
    const int SM2 = (64*132 + 32*132 + 64*66)*4 + 16*66*8 + 64*4;   // 76288
    const int SM3 = (64*68 + 64*130 + 128*68)*4 + 384*4 + 128*4;    // 87552
    cudaFuncSetAttribute(kfwd1,  cudaFuncAttributeMaxDynamicSharedMemorySize, SM1);
    cudaFuncSetAttribute(kfused, cudaFuncAttributeMaxDynamicSharedMemorySize, SM2);
    cudaFuncSetAttribute(khead,  cudaFuncAttributeMaxDynamicSharedMemorySize, SM3);

    kprep<<<16, 256>>>();
    ktw<<<16384, 256>>>(spec_re, spec_im);
    kfc0<<<32768, 256>>>(x, fc0_w, fc0_b, h0);

    float* hin = h0;
    float* hout = h1;
    for (int d = 0; d < NDEPTH; ++d) {
        kfwd1<<<1024, 256, SM1>>>(hin, f1);
        kfwd2<<<512, 512>>>(f1, mo);
        kmix<<<256, 256>>>(mo, wt + (size_t)d * 256 * 4096, mx);
        kinv1<<<2048, 256>>>(mx, G);
        kfused<<<4096, 256, SM2>>>(hin, G, w_w + d * 4096, w_b + d * 64, hout);
        float* t = hin; hin = hout; hout = t;
    }
    khead<<<8192, 256, SM3>>>(hin, fc1_w, fc1_b, fc2_w, fc2_b, (float*)d_out);
}

// round 12
// speedup vs baseline: 1.2521x; 1.0506x over previous
#include <cuda_runtime.h>

#define NDEPTH 4
typedef unsigned long long u64;

__device__ __forceinline__ u64 ffma2(u64 a, u64 b, u64 c){
    u64 d; asm("fma.rn.f32x2 %0, %1, %2, %3;" : "=l"(d) : "l"(a), "l"(b), "l"(c)); return d;
}
__device__ __forceinline__ u64 fpack2(float x, float y){
    u64 d; asm("mov.b64 %0, {%1, %2};" : "=l"(d) : "f"(x), "f"(y)); return d;
}
__device__ __forceinline__ float2 funpack2(u64 a){
    float x, y; asm("mov.b64 {%0, %1}, %2;" : "=f"(x), "=f"(y) : "l"(a)); return make_float2(x, y);
}
__device__ __forceinline__ void cpa16(void* dst_smem, const void* src){
    unsigned sa = (unsigned)__cvta_generic_to_shared(dst_smem);
    asm volatile("cp.async.cg.shared.global [%0], [%1], 16;" :: "r"(sa), "l"(src));
}
__device__ __forceinline__ void cpa8(void* dst_smem, const void* src){
    unsigned sa = (unsigned)__cvta_generic_to_shared(dst_smem);
    asm volatile("cp.async.ca.shared.global [%0], [%1], 8;" :: "r"(sa), "l"(src));
}
#define CP_COMMIT() asm volatile("cp.async.commit_group;")
template<int N> __device__ __forceinline__ void cp_wait(){
    asm volatile("cp.async.wait_group %0;" :: "n"(N));
}

// ---------------- scratch (device globals) ----------------
__device__ float  g_h0[8*64*65536];
__device__ float  g_h1[8*64*65536];
__device__ float2 g_f1[8*64*256*16];
__device__ float2 g_modes[8*64*256];
__device__ float2 g_mixed[8*64*256];               // mixedT [b][ky][kx][o]
__device__ float2 g_G[8*256*16*64];                // [b][y][ky][c]
__device__ float2 g_wt[NDEPTH*256*64*64];          // [d][m][i][o]
__device__ float  g_ec[16*256], g_es[16*256];      // fwd: cos, -sin
__device__ float  g_ic[16*256], g_is[16*256];      // inv-W scaled tables

// ---------------- prep: DFT tables ----------------
__global__ void kprep(){
    int idx = blockIdx.x * 256 + threadIdx.x;      // 4096 = [ky][x]
    int x = idx & 255, ky = idx >> 8;
    float ang = 6.283185307179586f * (float)((ky * x) & 255) / 256.f;
    float c = cosf(ang), s = sinf(ang);
    g_ec[idx] = c; g_es[idx] = -s;
    const float sc = 1.f / 65536.f;
    g_ic[idx] = (ky == 0) ? sc : 2.f * sc * c;
    g_is[idx] = (ky == 0) ? 0.f : -2.f * sc * s;
}

// ---------------- spectral weight transpose ----------------
__global__ void ktw(const float* __restrict__ wre, const float* __restrict__ wim){
    int idx = blockIdx.x * 256 + threadIdx.x;
    int ky = idx & 15, kx = (idx >> 4) & 15, o = (idx >> 8) & 63, i = (idx >> 14) & 63, d = idx >> 20;
    int m = kx * 16 + ky;
    g_wt[((d * 256 + m) * 64 + i) * 64 + o] = make_float2(wre[idx], wim[idx]);
}

// ---------------- fc0 ----------------
__global__ void kfc0(const float* __restrict__ x, const float* __restrict__ w,
                     const float* __restrict__ bv, float* __restrict__ out){
    int idx = blockIdx.x * 256 + threadIdx.x;
    int p4 = idx & 16383;
    int c  = (idx >> 14) & 63;
    int b  = idx >> 20;
    const float* xb = x + (size_t)b * 3 * 65536 + p4 * 4;
    float4 a0 = *(const float4*)&xb[0];
    float4 a1 = *(const float4*)&xb[65536];
    float4 a2 = *(const float4*)&xb[131072];
    float w0 = w[c*3], w1 = w[c*3+1], w2 = w[c*3+2], bb = bv[c];
    float4 r;
    r.x = bb + a0.x*w0 + a1.x*w1 + a2.x*w2;
    r.y = bb + a0.y*w0 + a1.y*w1 + a2.y*w2;
    r.z = bb + a0.z*w0 + a1.z*w1 + a2.z*w2;
    r.w = bb + a0.w*w0 + a1.w*w1 + a2.w*w2;
    *(float4*)&out[(size_t)idx * 4] = r;
}

// ---------------- fwd DFT along W: x-paired f32x2, cp.async double-buffered ----------------
// smem: tcp tables 16*516 + 2x sh[128*68] = 102656 B
__global__ __launch_bounds__(256) void kfwd1(const float* __restrict__ hin, float2* __restrict__ f1){
    extern __shared__ __align__(16) float dsm1[];
    float* tcp_c = dsm1;                           // 8*516
    float* tcp_s = dsm1 + 8*516;
    float* shb[2] = { dsm1 + 16*516, dsm1 + 16*516 + 128*68 };
    int tid = threadIdx.x;
    size_t rowbase = (size_t)blockIdx.x * 128;

    // issue chunks 0,1 via cp.async (overlap with twiddle fill)
    #pragma unroll
    for (int pc = 0; pc < 2; ++pc){
        int xb = pc*64;
        float* buf = shb[pc];
        #pragma unroll
        for (int k = 0; k < 8; ++k){
            int idx = tid + k*256;
            int r = idx >> 4, blk = idx & 15;
            cpa16(&buf[r*68 + ((blk ^ ((r>>1)&7))<<2)],
                  &hin[(rowbase + r)*256 + xb + blk*4]);
        }
        CP_COMMIT();
    }
    // twiddle tables (regular loads; overlap in-flight cp.async)
    #pragma unroll
    for (int k = 0; k < 16; ++k){
        int idx = tid + k*256;                     // 4096 per table
        int e = idx & 1, ky = (idx >> 1) & 1, xp = (idx >> 2) & 127, kg = idx >> 9;
        int kyg = kg*2 + ky, x = xp*2 + e;
        int dst = kg*516 + xp*4 + ky*2 + e;
        tcp_c[dst] = g_ec[kyg*256 + x];
        tcp_s[dst] = g_es[kyg*256 + x];
    }
    int kg = tid & 7, rg = tid >> 3;
    int r0 = rg*4, ky0 = kg*2;
    const float* tc = &tcp_c[kg*516];
    const float* ts = &tcp_s[kg*516];
    u64 ar[4][2], ai[4][2];
    #pragma unroll
    for (int j = 0; j < 4; ++j){ ar[j][0]=ar[j][1]=ai[j][0]=ai[j][1]=0ull; }

    #pragma unroll
    for (int ch = 0; ch < 4; ++ch){
        if (ch < 3) cp_wait<1>(); else cp_wait<0>();
        __syncthreads();
        const float* sh = shb[ch & 1];
        int xb = ch * 64;
        #pragma unroll 4
        for (int xl = 0; xl < 64; xl += 4){
            int xp4 = (xb + xl)*2;
            ulonglong2 A  = *(const ulonglong2*)&tc[xp4];
            ulonglong2 B  = *(const ulonglong2*)&tc[xp4 + 4];
            ulonglong2 Sa = *(const ulonglong2*)&ts[xp4];
            ulonglong2 Sb = *(const ulonglong2*)&ts[xp4 + 4];
            #pragma unroll
            for (int j = 0; j < 4; ++j){
                int r = r0 + j;
                ulonglong2 h = *(const ulonglong2*)&sh[r*68 + (((xl>>2) ^ ((r>>1)&7))<<2)];
                ar[j][0] = ffma2(h.x, A.x,  ar[j][0]);
                ar[j][0] = ffma2(h.y, B.x,  ar[j][0]);
                ai[j][0] = ffma2(h.x, Sa.x, ai[j][0]);
                ai[j][0] = ffma2(h.y, Sb.x, ai[j][0]);
                ar[j][1] = ffma2(h.x, A.y,  ar[j][1]);
                ar[j][1] = ffma2(h.y, B.y,  ar[j][1]);
                ai[j][1] = ffma2(h.x, Sa.y, ai[j][1]);
                ai[j][1] = ffma2(h.y, Sb.y, ai[j][1]);
            }
        }
        __syncthreads();
        if (ch + 2 < 4){                           // refill the buffer just consumed
            int xb2 = (ch + 2)*64;
            float* buf = shb[ch & 1];
            #pragma unroll
            for (int k = 0; k < 8; ++k){
                int idx = tid + k*256;
                int r = idx >> 4, blk = idx & 15;
                cpa16(&buf[r*68 + ((blk ^ ((r>>1)&7))<<2)],
                      &hin[(rowbase + r)*256 + xb2 + blk*4]);
            }
            CP_COMMIT();
        }
    }
    #pragma unroll
    for (int j = 0; j < 4; ++j){
        float2 re0 = funpack2(ar[j][0]), im0 = funpack2(ai[j][0]);
        float2 re1 = funpack2(ar[j][1]), im1 = funpack2(ai[j][1]);
        float4 o = make_float4(re0.x+re0.y, im0.x+im0.y, re1.x+re1.y, im1.x+im1.y);
        *(float4*)&f1[(rowbase + r0 + j)*16 + ky0] = o;
    }
}

// ---------------- fwd DFT along H, split-K ----------------
__global__ void kfwd2(const float2* __restrict__ f1, float2* __restrict__ modes){
    __shared__ float2 sf[4096];
    __shared__ float ct[256], st[256];
    __shared__ float2 sred[256];
    int tid = threadIdx.x;                         // 512
    if (tid < 256){
        float ang = 6.283185307179586f * (float)tid / 256.f;
        ct[tid] = cosf(ang); st[tid] = sinf(ang);
    }
    int bc = blockIdx.x;
    const float2* src = f1 + (size_t)bc * 4096;
    for (int idx = tid; idx < 4096; idx += 512) sf[idx] = src[idx];
    __syncthreads();
    int outi = tid & 255;
    int kx = outi >> 4, ky = outi & 15;
    int yb = (tid >> 8) * 128;
    float re0=0.f, im0=0.f, re1=0.f, im1=0.f;
    #pragma unroll 4
    for (int yy = yb; yy < yb + 128; yy += 2){
        float2 v0 = sf[yy*16 + ky];
        int t0 = (kx * yy) & 255;
        float c0 = ct[t0], s0 = st[t0];
        re0 += v0.x*c0 + v0.y*s0;
        im0 += v0.y*c0 - v0.x*s0;
        float2 v1 = sf[(yy+1)*16 + ky];
        int t1 = (kx * (yy+1)) & 255;
        float c1 = ct[t1], s1 = st[t1];
        re1 += v1.x*c1 + v1.y*s1;
        im1 += v1.y*c1 - v1.x*s1;
    }
    float re = re0 + re1, im = im0 + im1;
    if (tid >= 256) sred[outi] = make_float2(re, im);
    __syncthreads();
    if (tid < 256){
        float2 o = sred[outi];
        modes[bc*256 + outi] = make_float2(re + o.x, im + o.y);
    }
}

// ---------------- mode mixing -> mixedT [b][ky][kx][o] ----------------
__global__ void kmix(const float2* __restrict__ modes, const float2* __restrict__ wt,
                     float2* __restrict__ mixedT){
    __shared__ float2 swt[4096];
    __shared__ float2 sin_[512];
    int tid = threadIdx.x, m = blockIdx.x;
    int ky = m & 15, kx = m >> 4;
    const float2* wsrc = wt + (size_t)m * 4096;
    for (int idx = tid; idx < 4096; idx += 256) swt[idx] = wsrc[idx];
    for (int idx = tid; idx < 512; idx += 256){
        int b = idx >> 6, i = idx & 63;
        sin_[idx] = modes[(b*64 + i)*256 + m];
    }
    __syncthreads();
    int o = tid & 63;
    for (int half = 0; half < 2; ++half){
        int b = (tid >> 6) + half * 4;
        float re = 0.f, im = 0.f;
        #pragma unroll 8
        for (int i = 0; i < 64; ++i){
            float2 a = sin_[b*64 + i];
            float2 wv = swt[i*64 + o];
            re += a.x*wv.x - a.y*wv.y;
            im += a.x*wv.y + a.y*wv.x;
        }
        mixedT[((b*16 + ky)*16 + kx)*64 + o] = make_float2(re, im);
    }
}

// ---------------- inv DFT along H: G [b][y][ky][c] ----------------
__global__ void kinv1(const float2* __restrict__ mixedT, float2* __restrict__ G){
    __shared__ float2 sm[1024];
    __shared__ float ct[256], st[256];
    int tid = threadIdx.x;                         // 256
    int ky = blockIdx.x & 15, yg = (blockIdx.x >> 4) & 15, b = blockIdx.x >> 8;
    {
        float ang = 6.283185307179586f * (float)tid / 256.f;
        ct[tid] = cosf(ang); st[tid] = sinf(ang);
    }
    const float2* src = mixedT + (size_t)(b*16 + ky) * 1024;
    for (int idx = tid; idx < 1024; idx += 256) sm[idx] = src[idx];
    __syncthreads();
    int c = tid & 63, yl = tid >> 6;
    #pragma unroll
    for (int yi = 0; yi < 4; ++yi){
        int yy = yg*16 + yl*4 + yi;
        float re = 0.f, im = 0.f;
        #pragma unroll
        for (int kx = 0; kx < 16; ++kx){
            float2 v = sm[kx*64 + c];
            int t = (kx * yy) & 255;
            float cc = ct[t], ss = st[t];
            re += v.x*cc - v.y*ss;
            im += v.x*ss + v.y*cc;
        }
        G[((size_t)(b*256 + yy)*16 + ky)*64 + c] = make_float2(re, im);
    }
}

// ---------------- fused: 1x1 conv + inv DFT along W + bias + relu ----------------
// cp.async staged: group0 = sg/sA/sB, group1 = h; inv-DFT computed while h lands
#define CMAD(oo, wd) \
    acc[oo][0]=ffma2(wd,h01.x,acc[oo][0]); acc[oo][1]=ffma2(wd,h01.y,acc[oo][1]); \
    acc[oo][2]=ffma2(wd,h23.x,acc[oo][2]); acc[oo][3]=ffma2(wd,h23.y,acc[oo][3]);
#define IMAD2(oo, gxd, gyd) \
    acc[oo][0]=ffma2(gxd,A01.x,acc[oo][0]); acc[oo][0]=ffma2(gyd,B01.x,acc[oo][0]); \
    acc[oo][1]=ffma2(gxd,A01.y,acc[oo][1]); acc[oo][1]=ffma2(gyd,B01.y,acc[oo][1]); \
    acc[oo][2]=ffma2(gxd,A23.x,acc[oo][2]); acc[oo][2]=ffma2(gyd,B23.x,acc[oo][2]); \
    acc[oo][3]=ffma2(gxd,A23.y,acc[oo][3]); acc[oo][3]=ffma2(gyd,B23.y,acc[oo][3]);

__global__ __launch_bounds__(256) void kfused(
        const float* __restrict__ hin, const float2* __restrict__ G,
        const float* __restrict__ ww, const float* __restrict__ wb,
        float* __restrict__ hout){
    extern __shared__ __align__(16) float dsm2[];
    float*  sh = dsm2;                             // [64 i][132]
    float*  sA = sh + 64*132;                      // [16 ky][132]
    float*  sB = sA + 16*132;                      // [16 ky][132]
    float*  sw = sB + 16*132;                      // [64 i][66]  w[i][o]
    float2* sg = (float2*)(sw + 64*66);            // [16 ky][66] (gx,gy)
    float*  sb = (float*)(sg + 16*66);             // [64]
    int tid = threadIdx.x;                         // 256
    int xh = blockIdx.x & 1;
    int y  = (blockIdx.x >> 1) & 255;
    int b  = blockIdx.x >> 9;
    int xg2 = xh * 128;

    // group 0: sg + sA + sB (needed by inv-DFT)
    {
        const float2* Gb = G + ((size_t)(b*256) + y) * 1024;
        #pragma unroll
        for (int k = 0; k < 4; ++k){
            int idx = tid + k*256;                 // 1024
            int ky = idx >> 6, o = idx & 63;
            cpa8(&sg[ky*66 + o], &Gb[idx]);
        }
        #pragma unroll
        for (int k = 0; k < 2; ++k){
            int idx = tid + k*256;                 // 512 float4 (sA,sB)
            int ky = idx >> 5, xq = (idx & 31)*4;
            if (ky < 16){
                cpa16(&sA[ky*132 + xq], &g_ic[ky*256 + xg2 + xq]);
                cpa16(&sB[ky*132 + xq], &g_is[ky*256 + xg2 + xq]);
            }
        }
        CP_COMMIT();
    }
    // group 1: h tile (32 KB)
    {
        const float* hb = hin + ((size_t)(b*64)*256 + y)*256 + xg2;
        #pragma unroll
        for (int k = 0; k < 8; ++k){
            int idx = tid + k*256;                 // 2048 float4
            int i = idx >> 5, xq = (idx & 31)*4;
            cpa16(&sh[i*132 + xq], &hb[(size_t)i*65536 + xq]);
        }
        CP_COMMIT();
    }
    // synchronous fills (overlap the cp.asyncs): sw transpose + sb
    #pragma unroll
    for (int k = 0; k < 16; ++k){
        int idx = tid + k*256;                     // 4096: sw[i][o] = ww[o][i]
        int i = idx & 63, o = idx >> 6;
        sw[i*66 + o] = ww[idx];
    }
    if (tid < 64) sb[tid] = wb[tid];
    cp_wait<1>();                                  // group0 done
    __syncthreads();

    int w = tid >> 5, l = tid & 31;
    int o0 = ((w & 1)*8 + (l >> 2)) * 4;           // 16 o-groups
    int x0 = ((w >> 1)*4 + (l & 3)) * 8;           // 16 x-groups
    u64 acc[4][4];
    {
        float4 bv = *(const float4*)&sb[o0];
        u64 b0 = fpack2(bv.x, bv.x), b1 = fpack2(bv.y, bv.y);
        u64 b2 = fpack2(bv.z, bv.z), b3 = fpack2(bv.w, bv.w);
        #pragma unroll
        for (int p = 0; p < 4; ++p){ acc[0][p]=b0; acc[1][p]=b1; acc[2][p]=b2; acc[3][p]=b3; }
    }
    // inv-DFT first: overlaps the in-flight h cp.asyncs
    #pragma unroll 4
    for (int ky = 0; ky < 16; ++ky){
        ulonglong2 A01 = *(const ulonglong2*)&sA[ky*132 + x0];
        ulonglong2 A23 = *(const ulonglong2*)&sA[ky*132 + x0 + 4];
        ulonglong2 B01 = *(const ulonglong2*)&sB[ky*132 + x0];
        ulonglong2 B23 = *(const ulonglong2*)&sB[ky*132 + x0 + 4];
        float2 ga = sg[ky*66 + o0],     gb2 = sg[ky*66 + o0 + 1];
        float2 gc = sg[ky*66 + o0 + 2], gd  = sg[ky*66 + o0 + 3];
        u64 gx0 = fpack2(ga.x, ga.x),  gy0 = fpack2(ga.y, ga.y);
        u64 gx1 = fpack2(gb2.x, gb2.x), gy1 = fpack2(gb2.y, gb2.y);
        u64 gx2 = fpack2(gc.x, gc.x),  gy2 = fpack2(gc.y, gc.y);
        u64 gx3 = fpack2(gd.x, gd.x),  gy3 = fpack2(gd.y, gd.y);
        IMAD2(0, gx0, gy0) IMAD2(1, gx1, gy1) IMAD2(2, gx2, gy2) IMAD2(3, gx3, gy3)
    }
    cp_wait<0>();                                  // h tile done
    __syncthreads();
    #pragma unroll 4
    for (int i = 0; i < 64; ++i){
        ulonglong2 h01 = *(const ulonglong2*)&sh[i*132 + x0];
        ulonglong2 h23 = *(const ulonglong2*)&sh[i*132 + x0 + 4];
        float2 wab = *(const float2*)&sw[i*66 + o0];
        float2 wcd = *(const float2*)&sw[i*66 + o0 + 2];
        u64 w0 = fpack2(wab.x, wab.x), w1 = fpack2(wab.y, wab.y);
        u64 w2 = fpack2(wcd.x, wcd.x), w3 = fpack2(wcd.y, wcd.y);
        CMAD(0, w0) CMAD(1, w1) CMAD(2, w2) CMAD(3, w3)
    }
    float* ob = hout + ((size_t)(b*64 + o0)*256 + y)*256 + xg2 + x0;
    #pragma unroll
    for (int oo = 0; oo < 4; ++oo){
        float2 p0 = funpack2(acc[oo][0]), p1 = funpack2(acc[oo][1]);
        float2 p2 = funpack2(acc[oo][2]), p3 = funpack2(acc[oo][3]);
        float4 v0 = make_float4(fmaxf(p0.x,0.f), fmaxf(p0.y,0.f), fmaxf(p1.x,0.f), fmaxf(p1.y,0.f));
        float4 v1 = make_float4(fmaxf(p2.x,0.f), fmaxf(p2.y,0.f), fmaxf(p3.x,0.f), fmaxf(p3.y,0.f));
        *(float4*)&ob[(size_t)oo*65536]     = v0;
        *(float4*)&ob[(size_t)oo*65536 + 4] = v1;
    }
}

// ---------------- fused MLP head (h via cp.async, overlapped with w1 transpose) ----------------
#define HMAD(mm, wd) \
    acc[mm][0]=ffma2(wd,h01.x,acc[mm][0]); acc[mm][1]=ffma2(wd,h01.y,acc[mm][1]); \
    acc[mm][2]=ffma2(wd,h23.x,acc[mm][2]); acc[mm][3]=ffma2(wd,h23.y,acc[mm][3]);

__global__ __launch_bounds__(256) void khead(
        const float* __restrict__ hin,
        const float* __restrict__ w1, const float* __restrict__ b1,
        const float* __restrict__ w2, const float* __restrict__ b2,
        float* __restrict__ out){
    extern __shared__ __align__(16) float dsm3[];
    float* sh   = dsm3;                            // [64 c][68]
    float* sw1t = sh + 64*68;                      // [64 c][130]  w1^T [c][m]
    float* shid = sw1t + 64*130;                   // [128 m][68]
    float* sw2s = shid + 128*68;                   // [384]
    float* sb1s = sw2s + 384;                      // [128]
    int tid = threadIdx.x;                         // 256
    int xc = (blockIdx.x & 3) << 6;
    int y  = (blockIdx.x >> 2) & 255;
    int b  = blockIdx.x >> 10;

    {   // h via cp.async (group 0)
        const float* hb = hin + ((size_t)(b*64)*256 + y)*256 + xc;
        #pragma unroll
        for (int k = 0; k < 4; ++k){
            int idx = tid + k*256;                 // 1024 float4
            int c = idx >> 4, xq = (idx & 15)*4;
            cpa16(&sh[c*68 + xq], &hb[(size_t)c*65536 + xq]);
        }
        CP_COMMIT();
    }
    #pragma unroll
    for (int k = 0; k < 32; ++k){
        int idx = tid + k*256;                     // 8192: sw1t[c][m] = w1[m][c]
        int c = idx & 63, m = idx >> 6;
        sw1t[c*130 + m] = w1[idx];
    }
    for (int idx = tid; idx < 384; idx += 256) sw2s[idx] = w2[idx];
    if (tid < 128) sb1s[tid] = b1[tid];
    cp_wait<0>();
    __syncthreads();

    int w = tid >> 5, l = tid & 31;
    int m0 = ((w & 3)*8 + (l >> 2)) * 4;           // 32 m-groups
    int x0 = ((w >> 2)*4 + (l & 3)) * 8;           // 8 x-groups
    u64 acc[4][4];
    {
        float4 bv = *(const float4*)&sb1s[m0];
        u64 b0v = fpack2(bv.x,bv.x), b1v = fpack2(bv.y,bv.y);
        u64 b2v = fpack2(bv.z,bv.z), b3v = fpack2(bv.w,bv.w);
        #pragma unroll
        for (int p = 0; p < 4; ++p){ acc[0][p]=b0v; acc[1][p]=b1v; acc[2][p]=b2v; acc[3][p]=b3v; }
    }
    #pragma unroll 4
    for (int c = 0; c < 64; ++c){
        ulonglong2 h01 = *(const ulonglong2*)&sh[c*68 + x0];
        ulonglong2 h23 = *(const ulonglong2*)&sh[c*68 + x0 + 4];
        float2 wab = *(const float2*)&sw1t[c*130 + m0];
        float2 wcd = *(const float2*)&sw1t[c*130 + m0 + 2];
        u64 w0 = fpack2(wab.x,wab.x), w1d = fpack2(wab.y,wab.y);
        u64 w2d = fpack2(wcd.x,wcd.x), w3d = fpack2(wcd.y,wcd.y);
        HMAD(0, w0) HMAD(1, w1d) HMAD(2, w2d) HMAD(3, w3d)
    }
    #pragma unroll
    for (int mm = 0; mm < 4; ++mm){
        float2 p0 = funpack2(acc[mm][0]), p1 = funpack2(acc[mm][1]);
        float2 p2 = funpack2(acc[mm][2]), p3 = funpack2(acc[mm][3]);
        float4 v0 = make_float4(fmaxf(p0.x,0.f), fmaxf(p0.y,0.f), fmaxf(p1.x,0.f), fmaxf(p1.y,0.f));
        float4 v1 = make_float4(fmaxf(p2.x,0.f), fmaxf(p2.y,0.f), fmaxf(p3.x,0.f), fmaxf(p3.y,0.f));
        *(float4*)&shid[(m0+mm)*68 + x0]     = v0;
        *(float4*)&shid[(m0+mm)*68 + x0 + 4] = v1;
    }
    __syncthreads();
    if (tid < 192){
        int o = tid >> 6, xl = tid & 63;
        float a = b2[o];
        #pragma unroll 8
        for (int m = 0; m < 128; ++m)
            a = fmaf(shid[m*68 + xl], sw2s[o*128 + m], a);
        out[((size_t)(b*3 + o)*256 + y)*256 + xc + xl] = a;
    }
}

// ---------------- host ----------------
extern "C" void kernel_launch(void* const* d_in, const int* in_sizes, int n_in,
                              void* d_out, int out_size) {
    const float* x       = (const float*)d_in[0];
    const float* fc0_w   = (const float*)d_in[1];
    const float* fc0_b   = (const float*)d_in[2];
    const float* spec_re = (const float*)d_in[3];
    const float* spec_im = (const float*)d_in[4];
    const float* w_w     = (const float*)d_in[5];
    const float* w_b     = (const float*)d_in[6];
    const float* fc1_w   = (const float*)d_in[7];
    const float* fc1_b   = (const float*)d_in[8];
    const float* fc2_w   = (const float*)d_in[9];
    const float* fc2_b   = (const float*)d_in[10];

    float  *h0, *h1;
    float2 *f1, *mo, *mx, *G, *wt;
    cudaGetSymbolAddress((void**)&h0, g_h0);
    cudaGetSymbolAddress((void**)&h1, g_h1);
    cudaGetSymbolAddress((void**)&f1, g_f1);
    cudaGetSymbolAddress((void**)&mo, g_modes);
    cudaGetSymbolAddress((void**)&mx, g_mixed);
    cudaGetSymbolAddress((void**)&G,  g_G);
    cudaGetSymbolAddress((void**)&wt, g_wt);

    const int SM1 = (16*516 + 2*128*68) * 4;                        // 102656
    const int SM2 = (64*132 + 32*132 + 64*66)*4 + 16*66*8 + 64*4;   // 76288
    const int SM3 = (64*68 + 64*130 + 128*68)*4 + 384*4 + 128*4;    // 87552
    cudaFuncSetAttribute(kfwd1,  cudaFuncAttributeMaxDynamicSharedMemorySize, SM1);
    cudaFuncSetAttribute(kfused, cudaFuncAttributeMaxDynamicSharedMemorySize, SM2);
    cudaFuncSetAttribute(khead,  cudaFuncAttributeMaxDynamicSharedMemorySize, SM3);

    kprep<<<16, 256>>>();
    ktw<<<16384, 256>>>(spec_re, spec_im);
    kfc0<<<32768, 256>>>(x, fc0_w, fc0_b, h0);

    float* hin = h0;
    float* hout = h1;
    for (int d = 0; d < NDEPTH; ++d) {
        kfwd1<<<1024, 256, SM1>>>(hin, f1);
        kfwd2<<<512, 512>>>(f1, mo);
        kmix<<<256, 256>>>(mo, wt + (size_t)d * 256 * 4096, mx);
        kinv1<<<2048, 256>>>(mx, G);
        kfused<<<4096, 256, SM2>>>(hin, G, w_w + d * 4096, w_b + d * 64, hout);
        float* t = hin; hin = hout; hout = t;
    }
    khead<<<8192, 256, SM3>>>(hin, fc1_w, fc1_b, fc2_w, fc2_b, (float*)d_out);
}

// round 13
// speedup vs baseline: 1.3075x; 1.0443x over previous
#include <cuda_runtime.h>

#define NDEPTH 4
typedef unsigned long long u64;

__device__ __forceinline__ u64 ffma2(u64 a, u64 b, u64 c){
    u64 d; asm("fma.rn.f32x2 %0, %1, %2, %3;" : "=l"(d) : "l"(a), "l"(b), "l"(c)); return d;
}
__device__ __forceinline__ u64 fadd2(u64 a, u64 b){
    u64 d; asm("add.rn.f32x2 %0, %1, %2;" : "=l"(d) : "l"(a), "l"(b)); return d;
}
__device__ __forceinline__ u64 fpack2(float x, float y){
    u64 d; asm("mov.b64 %0, {%1, %2};" : "=l"(d) : "f"(x), "f"(y)); return d;
}
__device__ __forceinline__ float2 funpack2(u64 a){
    float x, y; asm("mov.b64 {%0, %1}, %2;" : "=f"(x), "=f"(y) : "l"(a)); return make_float2(x, y);
}
__device__ __forceinline__ void cpa16(void* dst_smem, const void* src){
    unsigned sa = (unsigned)__cvta_generic_to_shared(dst_smem);
    asm volatile("cp.async.cg.shared.global [%0], [%1], 16;" :: "r"(sa), "l"(src));
}
__device__ __forceinline__ void cpa8(void* dst_smem, const void* src){
    unsigned sa = (unsigned)__cvta_generic_to_shared(dst_smem);
    asm volatile("cp.async.ca.shared.global [%0], [%1], 8;" :: "r"(sa), "l"(src));
}
#define CP_COMMIT() asm volatile("cp.async.commit_group;")
template<int N> __device__ __forceinline__ void cp_wait(){
    asm volatile("cp.async.wait_group %0;" :: "n"(N));
}

// ---------------- scratch (device globals) ----------------
// +64 slack: kfwd1 mirror-chunk fill overreads up to 4 floats past row end at buffer tail
__device__ float  g_h0[8*64*65536 + 64];
__device__ float  g_h1[8*64*65536 + 64];
__device__ float2 g_f1[8*64*256*16];
__device__ float2 g_modes[8*64*256];
__device__ float2 g_mixed[8*64*256];               // mixedT [b][ky][kx][o]
__device__ float2 g_G[8*256*16*64];                // [b][y][ky][c]
__device__ float2 g_wt[NDEPTH*256*64*64];          // [d][m][i][o]
__device__ float  g_ec[16*256], g_es[16*256];      // fwd: cos, -sin
__device__ float  g_ic[16*256], g_is[16*256];      // inv-W scaled tables

// ---------------- prep: DFT tables ----------------
__global__ void kprep(){
    int idx = blockIdx.x * 256 + threadIdx.x;      // 4096 = [ky][x]
    int x = idx & 255, ky = idx >> 8;
    float ang = 6.283185307179586f * (float)((ky * x) & 255) / 256.f;
    float c = cosf(ang), s = sinf(ang);
    g_ec[idx] = c; g_es[idx] = -s;
    const float sc = 1.f / 65536.f;
    g_ic[idx] = (ky == 0) ? sc : 2.f * sc * c;
    g_is[idx] = (ky == 0) ? 0.f : -2.f * sc * s;
}

// ---------------- spectral weight transpose ----------------
__global__ void ktw(const float* __restrict__ wre, const float* __restrict__ wim){
    int idx = blockIdx.x * 256 + threadIdx.x;
    int ky = idx & 15, kx = (idx >> 4) & 15, o = (idx >> 8) & 63, i = (idx >> 14) & 63, d = idx >> 20;
    int m = kx * 16 + ky;
    g_wt[((d * 256 + m) * 64 + i) * 64 + o] = make_float2(wre[idx], wim[idx]);
}

// ---------------- fc0 ----------------
__global__ void kfc0(const float* __restrict__ x, const float* __restrict__ w,
                     const float* __restrict__ bv, float* __restrict__ out){
    int idx = blockIdx.x * 256 + threadIdx.x;
    int p4 = idx & 16383;
    int c  = (idx >> 14) & 63;
    int b  = idx >> 20;
    const float* xb = x + (size_t)b * 3 * 65536 + p4 * 4;
    float4 a0 = *(const float4*)&xb[0];
    float4 a1 = *(const float4*)&xb[65536];
    float4 a2 = *(const float4*)&xb[131072];
    float w0 = w[c*3], w1 = w[c*3+1], w2 = w[c*3+2], bb = bv[c];
    float4 r;
    r.x = bb + a0.x*w0 + a1.x*w1 + a2.x*w2;
    r.y = bb + a0.y*w0 + a1.y*w1 + a2.y*w2;
    r.z = bb + a0.z*w0 + a1.z*w1 + a2.z*w2;
    r.w = bb + a0.w*w0 + a1.w*w1 + a2.w*w2;
    *(float4*)&out[(size_t)idx * 4] = r;
}

// ---------------- fwd DFT along W: real-input symmetry (half FMAs) ----------------
// 128 rows/block, 4 x-stages of 32. re=sum s*cos (+/-v128), im=sum d*(-sin).
// smem: sv[128][36] su[128][40] ss[128][36] sd[128][36] twc/tws[8][260] = 92416 B
__global__ __launch_bounds__(256) void kfwd1(const float* __restrict__ hin, float2* __restrict__ f1){
    extern __shared__ __align__(16) float dsm1[];
    float* sv  = dsm1;                              // [128][36] fwd chunk
    float* su  = sv + 128*36;                       // [128][40] mirror chunk (36 data)
    float* ss  = su + 128*40;                       // [128][36] s
    float* sd  = ss + 128*36;                       // [128][36] d
    float* twc = sd + 128*36;                       // [8 kg][260] : [kg][e2*128 + x]
    float* tws = twc + 8*260;
    int tid = threadIdx.x;
    size_t rowbase = (size_t)blockIdx.x * 128;
    int rg = tid >> 3, kg = tid & 7;                // thread: rows rg+32j, ky = kg*2+{0,1}

    // ---- fill stage 0 ----
    {
        const int k = 0;
        #pragma unroll
        for (int t = 0; t < 4; ++t){                // v chunk: 1024 float4
            int idx = tid + t*256;
            int row = idx >> 3, q = idx & 7;
            cpa16(&sv[row*36 + q*4], &hin[(rowbase + row)*256 + k*32 + q*4]);
        }
        #pragma unroll
        for (int t = 0; t < 4; ++t){                // mirror main: 1024 float4
            int idx = tid + t*256;
            int row = idx >> 3, q = idx & 7;
            cpa16(&su[row*40 + q*4], &hin[(rowbase + row)*256 + 224 - k*32 + q*4]);
        }
        if (tid < 128)                              // mirror extra float4 (may overread slack)
            cpa16(&su[tid*40 + 32], &hin[(rowbase + tid)*256 + 256 - k*32]);
        CP_COMMIT();
    }
    // ---- twiddle tables (sync loads; overlap fill0) ----
    #pragma unroll
    for (int t = 0; t < 8; ++t){
        int idx = tid + t*256;                      // 2048 per table
        int x = idx & 127, e2 = (idx >> 7) & 1, g = idx >> 8;
        twc[g*260 + e2*128 + x] = g_ec[(g*2 + e2)*256 + x];
        tws[g*260 + e2*128 + x] = g_es[(g*2 + e2)*256 + x];
    }

    u64 ar[4][2], ai[4][2];
    #pragma unroll
    for (int j = 0; j < 4; ++j){ ar[j][0]=ar[j][1]=ai[j][0]=ai[j][1]=0ull; }
    const u64 NEG1 = fpack2(-1.f, -1.f);

    for (int k = 0; k < 4; ++k){
        cp_wait<0>();
        __syncthreads();
        // ---- prep: s,d for x in [32k, 32k+32) ----
        #pragma unroll
        for (int t = 0; t < 8; ++t){
            int idx = tid + t*256;                  // 2048 x-pairs
            int row = idx >> 4, xl = (idx & 15)*2;
            u64 vv = *(const u64*)&sv[row*36 + xl];
            float p0 = (k == 0 && xl == 0) ? 0.f : su[row*40 + 32 - xl];
            float p1 = su[row*40 + 31 - xl];
            u64 pp = fpack2(p0, p1);
            *(u64*)&ss[row*36 + xl] = fadd2(vv, pp);
            *(u64*)&sd[row*36 + xl] = ffma2(pp, NEG1, vv);
        }
        __syncthreads();
        // ---- issue next fill (overlaps compute) ----
        if (k < 3){
            int kn = k + 1;
            #pragma unroll
            for (int t = 0; t < 4; ++t){
                int idx = tid + t*256;
                int row = idx >> 3, q = idx & 7;
                cpa16(&sv[row*36 + q*4], &hin[(rowbase + row)*256 + kn*32 + q*4]);
            }
            #pragma unroll
            for (int t = 0; t < 4; ++t){
                int idx = tid + t*256;
                int row = idx >> 3, q = idx & 7;
                cpa16(&su[row*40 + q*4], &hin[(rowbase + row)*256 + 224 - kn*32 + q*4]);
            }
            if (tid < 128)
                cpa16(&su[tid*40 + 32], &hin[(rowbase + tid)*256 + 256 - kn*32]);
            CP_COMMIT();
        }
        // ---- compute: accumulate over this chunk ----
        #pragma unroll 4
        for (int j4 = 0; j4 < 32; j4 += 4){
            int xg = k*32 + j4;
            ulonglong2 c0 = *(const ulonglong2*)&twc[kg*260 + xg];
            ulonglong2 c1 = *(const ulonglong2*)&twc[kg*260 + 128 + xg];
            ulonglong2 s0 = *(const ulonglong2*)&tws[kg*260 + xg];
            ulonglong2 s1 = *(const ulonglong2*)&tws[kg*260 + 128 + xg];
            #pragma unroll
            for (int j = 0; j < 4; ++j){
                int r = rg + 32*j;
                ulonglong2 sp = *(const ulonglong2*)&ss[r*36 + j4];
                ulonglong2 dp = *(const ulonglong2*)&sd[r*36 + j4];
                ar[j][0] = ffma2(sp.x, c0.x, ar[j][0]);
                ar[j][0] = ffma2(sp.y, c0.y, ar[j][0]);
                ar[j][1] = ffma2(sp.x, c1.x, ar[j][1]);
                ar[j][1] = ffma2(sp.y, c1.y, ar[j][1]);
                ai[j][0] = ffma2(dp.x, s0.x, ai[j][0]);
                ai[j][0] = ffma2(dp.y, s0.y, ai[j][0]);
                ai[j][1] = ffma2(dp.x, s1.x, ai[j][1]);
                ai[j][1] = ffma2(dp.y, s1.y, ai[j][1]);
            }
        }
        __syncthreads();                            // protect ss/sd before next prep
    }
    // ---- epilogue: +/- v[128] (su stage-3 chunk holds up[0]=v[128]) ----
    #pragma unroll
    for (int j = 0; j < 4; ++j){
        int r = rg + 32*j;
        float u0 = su[r*40];
        float2 re0 = funpack2(ar[j][0]), im0 = funpack2(ai[j][0]);
        float2 re1 = funpack2(ar[j][1]), im1 = funpack2(ai[j][1]);
        float4 o = make_float4(re0.x + re0.y + u0, im0.x + im0.y,
                               re1.x + re1.y - u0, im1.x + im1.y);
        *(float4*)&f1[(rowbase + r)*16 + kg*2] = o;
    }
}

// ---------------- fwd DFT along H, split-K ----------------
__global__ void kfwd2(const float2* __restrict__ f1, float2* __restrict__ modes){
    __shared__ float2 sf[4096];
    __shared__ float ct[256], st[256];
    __shared__ float2 sred[256];
    int tid = threadIdx.x;                         // 512
    if (tid < 256){
        float ang = 6.283185307179586f * (float)tid / 256.f;
        ct[tid] = cosf(ang); st[tid] = sinf(ang);
    }
    int bc = blockIdx.x;
    const float2* src = f1 + (size_t)bc * 4096;
    for (int idx = tid; idx < 4096; idx += 512) sf[idx] = src[idx];
    __syncthreads();
    int outi = tid & 255;
    int kx = outi >> 4, ky = outi & 15;
    int yb = (tid >> 8) * 128;
    float re0=0.f, im0=0.f, re1=0.f, im1=0.f;
    #pragma unroll 4
    for (int yy = yb; yy < yb + 128; yy += 2){
        float2 v0 = sf[yy*16 + ky];
        int t0 = (kx * yy) & 255;
        float c0 = ct[t0], s0 = st[t0];
        re0 += v0.x*c0 + v0.y*s0;
        im0 += v0.y*c0 - v0.x*s0;
        float2 v1 = sf[(yy+1)*16 + ky];
        int t1 = (kx * (yy+1)) & 255;
        float c1 = ct[t1], s1 = st[t1];
        re1 += v1.x*c1 + v1.y*s1;
        im1 += v1.y*c1 - v1.x*s1;
    }
    float re = re0 + re1, im = im0 + im1;
    if (tid >= 256) sred[outi] = make_float2(re, im);
    __syncthreads();
    if (tid < 256){
        float2 o = sred[outi];
        modes[bc*256 + outi] = make_float2(re + o.x, im + o.y);
    }
}

// ---------------- mode mixing -> mixedT [b][ky][kx][o] ----------------
__global__ void kmix(const float2* __restrict__ modes, const float2* __restrict__ wt,
                     float2* __restrict__ mixedT){
    __shared__ float2 swt[4096];
    __shared__ float2 sin_[512];
    int tid = threadIdx.x, m = blockIdx.x;
    int ky = m & 15, kx = m >> 4;
    const float2* wsrc = wt + (size_t)m * 4096;
    for (int idx = tid; idx < 4096; idx += 256) swt[idx] = wsrc[idx];
    for (int idx = tid; idx < 512; idx += 256){
        int b = idx >> 6, i = idx & 63;
        sin_[idx] = modes[(b*64 + i)*256 + m];
    }
    __syncthreads();
    int o = tid & 63;
    for (int half = 0; half < 2; ++half){
        int b = (tid >> 6) + half * 4;
        float re = 0.f, im = 0.f;
        #pragma unroll 8
        for (int i = 0; i < 64; ++i){
            float2 a = sin_[b*64 + i];
            float2 wv = swt[i*64 + o];
            re += a.x*wv.x - a.y*wv.y;
            im += a.x*wv.y + a.y*wv.x;
        }
        mixedT[((b*16 + ky)*16 + kx)*64 + o] = make_float2(re, im);
    }
}

// ---------------- inv DFT along H: G [b][y][ky][c] ----------------
__global__ void kinv1(const float2* __restrict__ mixedT, float2* __restrict__ G){
    __shared__ float2 sm[1024];
    __shared__ float ct[256], st[256];
    int tid = threadIdx.x;                         // 256
    int ky = blockIdx.x & 15, yg = (blockIdx.x >> 4) & 15, b = blockIdx.x >> 8;
    {
        float ang = 6.283185307179586f * (float)tid / 256.f;
        ct[tid] = cosf(ang); st[tid] = sinf(ang);
    }
    const float2* src = mixedT + (size_t)(b*16 + ky) * 1024;
    for (int idx = tid; idx < 1024; idx += 256) sm[idx] = src[idx];
    __syncthreads();
    int c = tid & 63, yl = tid >> 6;
    #pragma unroll
    for (int yi = 0; yi < 4; ++yi){
        int yy = yg*16 + yl*4 + yi;
        float re = 0.f, im = 0.f;
        #pragma unroll
        for (int kx = 0; kx < 16; ++kx){
            float2 v = sm[kx*64 + c];
            int t = (kx * yy) & 255;
            float cc = ct[t], ss = st[t];
            re += v.x*cc - v.y*ss;
            im += v.x*ss + v.y*cc;
        }
        G[((size_t)(b*256 + yy)*16 + ky)*64 + c] = make_float2(re, im);
    }
}

// ---------------- fused: 1x1 conv + inv DFT along W + bias + relu (R12) ----------------
#define CMAD(oo, wd) \
    acc[oo][0]=ffma2(wd,h01.x,acc[oo][0]); acc[oo][1]=ffma2(wd,h01.y,acc[oo][1]); \
    acc[oo][2]=ffma2(wd,h23.x,acc[oo][2]); acc[oo][3]=ffma2(wd,h23.y,acc[oo][3]);
#define IMAD2(oo, gxd, gyd) \
    acc[oo][0]=ffma2(gxd,A01.x,acc[oo][0]); acc[oo][0]=ffma2(gyd,B01.x,acc[oo][0]); \
    acc[oo][1]=ffma2(gxd,A01.y,acc[oo][1]); acc[oo][1]=ffma2(gyd,B01.y,acc[oo][1]); \
    acc[oo][2]=ffma2(gxd,A23.x,acc[oo][2]); acc[oo][2]=ffma2(gyd,B23.x,acc[oo][2]); \
    acc[oo][3]=ffma2(gxd,A23.y,acc[oo][3]); acc[oo][3]=ffma2(gyd,B23.y,acc[oo][3]);

__global__ __launch_bounds__(256) void kfused(
        const float* __restrict__ hin, const float2* __restrict__ G,
        const float* __restrict__ ww, const float* __restrict__ wb,
        float* __restrict__ hout){
    extern __shared__ __align__(16) float dsm2[];
    float*  sh = dsm2;                             // [64 i][132]
    float*  sA = sh + 64*132;                      // [16 ky][132]
    float*  sB = sA + 16*132;                      // [16 ky][132]
    float*  sw = sB + 16*132;                      // [64 i][66]  w[i][o]
    float2* sg = (float2*)(sw + 64*66);            // [16 ky][66] (gx,gy)
    float*  sb = (float*)(sg + 16*66);             // [64]
    int tid = threadIdx.x;                         // 256
    int xh = blockIdx.x & 1;
    int y  = (blockIdx.x >> 1) & 255;
    int b  = blockIdx.x >> 9;
    int xg2 = xh * 128;

    {
        const float2* Gb = G + ((size_t)(b*256) + y) * 1024;
        #pragma unroll
        for (int k = 0; k < 4; ++k){
            int idx = tid + k*256;
            int ky = idx >> 6, o = idx & 63;
            cpa8(&sg[ky*66 + o], &Gb[idx]);
        }
        #pragma unroll
        for (int k = 0; k < 2; ++k){
            int idx = tid + k*256;
            int ky = idx >> 5, xq = (idx & 31)*4;
            if (ky < 16){
                cpa16(&sA[ky*132 + xq], &g_ic[ky*256 + xg2 + xq]);
                cpa16(&sB[ky*132 + xq], &g_is[ky*256 + xg2 + xq]);
            }
        }
        CP_COMMIT();
    }
    {
        const float* hb = hin + ((size_t)(b*64)*256 + y)*256 + xg2;
        #pragma unroll
        for (int k = 0; k < 8; ++k){
            int idx = tid + k*256;
            int i = idx >> 5, xq = (idx & 31)*4;
            cpa16(&sh[i*132 + xq], &hb[(size_t)i*65536 + xq]);
        }
        CP_COMMIT();
    }
    #pragma unroll
    for (int k = 0; k < 16; ++k){
        int idx = tid + k*256;
        int i = idx & 63, o = idx >> 6;
        sw[i*66 + o] = ww[idx];
    }
    if (tid < 64) sb[tid] = wb[tid];
    cp_wait<1>();
    __syncthreads();

    int w = tid >> 5, l = tid & 31;
    int o0 = ((w & 1)*8 + (l >> 2)) * 4;
    int x0 = ((w >> 1)*4 + (l & 3)) * 8;
    u64 acc[4][4];
    {
        float4 bv = *(const float4*)&sb[o0];
        u64 b0 = fpack2(bv.x, bv.x), b1 = fpack2(bv.y, bv.y);
        u64 b2 = fpack2(bv.z, bv.z), b3 = fpack2(bv.w, bv.w);
        #pragma unroll
        for (int p = 0; p < 4; ++p){ acc[0][p]=b0; acc[1][p]=b1; acc[2][p]=b2; acc[3][p]=b3; }
    }
    #pragma unroll 4
    for (int ky = 0; ky < 16; ++ky){
        ulonglong2 A01 = *(const ulonglong2*)&sA[ky*132 + x0];
        ulonglong2 A23 = *(const ulonglong2*)&sA[ky*132 + x0 + 4];
        ulonglong2 B01 = *(const ulonglong2*)&sB[ky*132 + x0];
        ulonglong2 B23 = *(const ulonglong2*)&sB[ky*132 + x0 + 4];
        float2 ga = sg[ky*66 + o0],     gb2 = sg[ky*66 + o0 + 1];
        float2 gc = sg[ky*66 + o0 + 2], gd  = sg[ky*66 + o0 + 3];
        u64 gx0 = fpack2(ga.x, ga.x),  gy0 = fpack2(ga.y, ga.y);
        u64 gx1 = fpack2(gb2.x, gb2.x), gy1 = fpack2(gb2.y, gb2.y);
        u64 gx2 = fpack2(gc.x, gc.x),  gy2 = fpack2(gc.y, gc.y);
        u64 gx3 = fpack2(gd.x, gd.x),  gy3 = fpack2(gd.y, gd.y);
        IMAD2(0, gx0, gy0) IMAD2(1, gx1, gy1) IMAD2(2, gx2, gy2) IMAD2(3, gx3, gy3)
    }
    cp_wait<0>();
    __syncthreads();
    #pragma unroll 4
    for (int i = 0; i < 64; ++i){
        ulonglong2 h01 = *(const ulonglong2*)&sh[i*132 + x0];
        ulonglong2 h23 = *(const ulonglong2*)&sh[i*132 + x0 + 4];
        float2 wab = *(const float2*)&sw[i*66 + o0];
        float2 wcd = *(const float2*)&sw[i*66 + o0 + 2];
        u64 w0 = fpack2(wab.x, wab.x), w1 = fpack2(wab.y, wab.y);
        u64 w2 = fpack2(wcd.x, wcd.x), w3 = fpack2(wcd.y, wcd.y);
        CMAD(0, w0) CMAD(1, w1) CMAD(2, w2) CMAD(3, w3)
    }
    float* ob = hout + ((size_t)(b*64 + o0)*256 + y)*256 + xg2 + x0;
    #pragma unroll
    for (int oo = 0; oo < 4; ++oo){
        float2 p0 = funpack2(acc[oo][0]), p1 = funpack2(acc[oo][1]);
        float2 p2 = funpack2(acc[oo][2]), p3 = funpack2(acc[oo][3]);
        float4 v0 = make_float4(fmaxf(p0.x,0.f), fmaxf(p0.y,0.f), fmaxf(p1.x,0.f), fmaxf(p1.y,0.f));
        float4 v1 = make_float4(fmaxf(p2.x,0.f), fmaxf(p2.y,0.f), fmaxf(p3.x,0.f), fmaxf(p3.y,0.f));
        *(float4*)&ob[(size_t)oo*65536]     = v0;
        *(float4*)&ob[(size_t)oo*65536 + 4] = v1;
    }
}

// ---------------- fused MLP head (R12) ----------------
#define HMAD(mm, wd) \
    acc[mm][0]=ffma2(wd,h01.x,acc[mm][0]); acc[mm][1]=ffma2(wd,h01.y,acc[mm][1]); \
    acc[mm][2]=ffma2(wd,h23.x,acc[mm][2]); acc[mm][3]=ffma2(wd,h23.y,acc[mm][3]);

__global__ __launch_bounds__(256) void khead(
        const float* __restrict__ hin,
        const float* __restrict__ w1, const float* __restrict__ b1,
        const float* __restrict__ w2, const float* __restrict__ b2,
        float* __restrict__ out){
    extern __shared__ __align__(16) float dsm3[];
    float* sh   = dsm3;                            // [64 c][68]
    float* sw1t = sh + 64*68;                      // [64 c][130]
    float* shid = sw1t + 64*130;                   // [128 m][68]
    float* sw2s = shid + 128*68;                   // [384]
    float* sb1s = sw2s + 384;                      // [128]
    int tid = threadIdx.x;                         // 256
    int xc = (blockIdx.x & 3) << 6;
    int y  = (blockIdx.x >> 2) & 255;
    int b  = blockIdx.x >> 10;

    {
        const float* hb = hin + ((size_t)(b*64)*256 + y)*256 + xc;
        #pragma unroll
        for (int k = 0; k < 4; ++k){
            int idx = tid + k*256;
            int c = idx >> 4, xq = (idx & 15)*4;
            cpa16(&sh[c*68 + xq], &hb[(size_t)c*65536 + xq]);
        }
        CP_COMMIT();
    }
    #pragma unroll
    for (int k = 0; k < 32; ++k){
        int idx = tid + k*256;
        int c = idx & 63, m = idx >> 6;
        sw1t[c*130 + m] = w1[idx];
    }
    for (int idx = tid; idx < 384; idx += 256) sw2s[idx] = w2[idx];
    if (tid < 128) sb1s[tid] = b1[tid];
    cp_wait<0>();
    __syncthreads();

    int w = tid >> 5, l = tid & 31;
    int m0 = ((w & 3)*8 + (l >> 2)) * 4;
    int x0 = ((w >> 2)*4 + (l & 3)) * 8;
    u64 acc[4][4];
    {
        float4 bv = *(const float4*)&sb1s[m0];
        u64 b0v = fpack2(bv.x,bv.x), b1v = fpack2(bv.y,bv.y);
        u64 b2v = fpack2(bv.z,bv.z), b3v = fpack2(bv.w,bv.w);
        #pragma unroll
        for (int p = 0; p < 4; ++p){ acc[0][p]=b0v; acc[1][p]=b1v; acc[2][p]=b2v; acc[3][p]=b3v; }
    }
    #pragma unroll 4
    for (int c = 0; c < 64; ++c){
        ulonglong2 h01 = *(const ulonglong2*)&sh[c*68 + x0];
        ulonglong2 h23 = *(const ulonglong2*)&sh[c*68 + x0 + 4];
        float2 wab = *(const float2*)&sw1t[c*130 + m0];
        float2 wcd = *(const float2*)&sw1t[c*130 + m0 + 2];
        u64 w0 = fpack2(wab.x,wab.x), w1d = fpack2(wab.y,wab.y);
        u64 w2d = fpack2(wcd.x,wcd.x), w3d = fpack2(wcd.y,wcd.y);
        HMAD(0, w0) HMAD(1, w1d) HMAD(2, w2d) HMAD(3, w3d)
    }
    #pragma unroll
    for (int mm = 0; mm < 4; ++mm){
        float2 p0 = funpack2(acc[mm][0]), p1 = funpack2(acc[mm][1]);
        float2 p2 = funpack2(acc[mm][2]), p3 = funpack2(acc[mm][3]);
        float4 v0 = make_float4(fmaxf(p0.x,0.f), fmaxf(p0.y,0.f), fmaxf(p1.x,0.f), fmaxf(p1.y,0.f));
        float4 v1 = make_float4(fmaxf(p2.x,0.f), fmaxf(p2.y,0.f), fmaxf(p3.x,0.f), fmaxf(p3.y,0.f));
        *(float4*)&shid[(m0+mm)*68 + x0]     = v0;
        *(float4*)&shid[(m0+mm)*68 + x0 + 4] = v1;
    }
    __syncthreads();
    if (tid < 192){
        int o = tid >> 6, xl = tid & 63;
        float a = b2[o];
        #pragma unroll 8
        for (int m = 0; m < 128; ++m)
            a = fmaf(shid[m*68 + xl], sw2s[o*128 + m], a);
        out[((size_t)(b*3 + o)*256 + y)*256 + xc + xl] = a;
    }
}

// ---------------- host ----------------
extern "C" void kernel_launch(void* const* d_in, const int* in_sizes, int n_in,
                              void* d_out, int out_size) {
    const float* x       = (const float*)d_in[0];
    const float* fc0_w   = (const float*)d_in[1];
    const float* fc0_b   = (const float*)d_in[2];
    const float* spec_re = (const float*)d_in[3];
    const float* spec_im = (const float*)d_in[4];
    const float* w_w     = (const float*)d_in[5];
    const float* w_b     = (const float*)d_in[6];
    const float* fc1_w   = (const float*)d_in[7];
    const float* fc1_b   = (const float*)d_in[8];
    const float* fc2_w   = (const float*)d_in[9];
    const float* fc2_b   = (const float*)d_in[10];

    float  *h0, *h1;
    float2 *f1, *mo, *mx, *G, *wt;
    cudaGetSymbolAddress((void**)&h0, g_h0);
    cudaGetSymbolAddress((void**)&h1, g_h1);
    cudaGetSymbolAddress((void**)&f1, g_f1);
    cudaGetSymbolAddress((void**)&mo, g_modes);
    cudaGetSymbolAddress((void**)&mx, g_mixed);
    cudaGetSymbolAddress((void**)&G,  g_G);
    cudaGetSymbolAddress((void**)&wt, g_wt);

    const int SM1 = (4*128*36 + 128*40 + 2*8*260 - 128*36 + 128*36) * 4;        // see layout
    const int SM1b = (128*36 + 128*40 + 128*36 + 128*36 + 2*8*260) * 4;         // 92416
    const int SM2 = (64*132 + 32*132 + 64*66)*4 + 16*66*8 + 64*4;               // 76288
    const int SM3 = (64*68 + 64*130 + 128*68)*4 + 384*4 + 128*4;                // 87552
    (void)SM1;
    cudaFuncSetAttribute(kfwd1,  cudaFuncAttributeMaxDynamicSharedMemorySize, SM1b);
    cudaFuncSetAttribute(kfused, cudaFuncAttributeMaxDynamicSharedMemorySize, SM2);
    cudaFuncSetAttribute(khead,  cudaFuncAttributeMaxDynamicSharedMemorySize, SM3);

    kprep<<<16, 256>>>();
    ktw<<<16384, 256>>>(spec_re, spec_im);
    kfc0<<<32768, 256>>>(x, fc0_w, fc0_b, h0);

    float* hin = h0;
    float* hout = h1;
    for (int d = 0; d < NDEPTH; ++d) {
        kfwd1<<<1024, 256, SM1b>>>(hin, f1);
        kfwd2<<<512, 512>>>(f1, mo);
        kmix<<<256, 256>>>(mo, wt + (size_t)d * 256 * 4096, mx);
        kinv1<<<2048, 256>>>(mx, G);
        kfused<<<4096, 256, SM2>>>(hin, G, w_w + d * 4096, w_b + d * 64, hout);
        float* t = hin; hin = hout; hout = t;
    }
    khead<<<8192, 256, SM3>>>(hin, fc1_w, fc1_b, fc2_w, fc2_b, (float*)d_out);
}

// round 15
// speedup vs baseline: 1.3243x; 1.0128x over previous
#include <cuda_runtime.h>

#define NDEPTH 4
typedef unsigned long long u64;

__device__ __forceinline__ u64 ffma2(u64 a, u64 b, u64 c){
    u64 d; asm("fma.rn.f32x2 %0, %1, %2, %3;" : "=l"(d) : "l"(a), "l"(b), "l"(c)); return d;
}
__device__ __forceinline__ u64 fadd2(u64 a, u64 b){
    u64 d; asm("add.rn.f32x2 %0, %1, %2;" : "=l"(d) : "l"(a), "l"(b)); return d;
}
__device__ __forceinline__ u64 fpack2(float x, float y){
    u64 d; asm("mov.b64 %0, {%1, %2};" : "=l"(d) : "f"(x), "f"(y)); return d;
}
__device__ __forceinline__ float2 funpack2(u64 a){
    float x, y; asm("mov.b64 {%0, %1}, %2;" : "=f"(x), "=f"(y) : "l"(a)); return make_float2(x, y);
}
__device__ __forceinline__ void cpa16(void* dst_smem, const void* src){
    unsigned sa = (unsigned)__cvta_generic_to_shared(dst_smem);
    asm volatile("cp.async.cg.shared.global [%0], [%1], 16;" :: "r"(sa), "l"(src));
}
__device__ __forceinline__ void cpa8(void* dst_smem, const void* src){
    unsigned sa = (unsigned)__cvta_generic_to_shared(dst_smem);
    asm volatile("cp.async.ca.shared.global [%0], [%1], 8;" :: "r"(sa), "l"(src));
}
#define CP_COMMIT() asm volatile("cp.async.commit_group;")
template<int N> __device__ __forceinline__ void cp_wait(){
    asm volatile("cp.async.wait_group %0;" :: "n"(N));
}

// ---------------- scratch (device globals) ----------------
__device__ float  g_h0[8*64*65536 + 64];
__device__ float  g_h1[8*64*65536 + 64];
__device__ float2 g_f1[8*64*256*16];
__device__ float2 g_modes[8*64*256];
__device__ float2 g_mixed[8*64*256];               // mixedT [b][ky][kx][o]
__device__ float2 g_G[8*256*16*64];                // [b][y][ky][c]
__device__ float2 g_wt[NDEPTH*256*64*64];          // [d][m][i][o]
__device__ float  g_ec[16*256], g_es[16*256];      // fwd: cos, -sin
__device__ float  g_ic[16*256], g_is[16*256];      // inv-W scaled tables
__device__ u64    g_e2c[16*128], g_e2s[16*128];    // fwd-H y-paired (cos,cos)/(sin,sin)

// ---------------- prep: DFT tables ----------------
__global__ void kprep(){
    int idx = blockIdx.x * 256 + threadIdx.x;      // 4096
    int x = idx & 255, ky = idx >> 8;
    float ang = 6.283185307179586f * (float)((ky * x) & 255) / 256.f;
    float c = cosf(ang), s = sinf(ang);
    g_ec[idx] = c; g_es[idx] = -s;
    const float sc = 1.f / 65536.f;
    g_ic[idx] = (ky == 0) ? sc : 2.f * sc * c;
    g_is[idx] = (ky == 0) ? 0.f : -2.f * sc * s;
    if (idx < 2048){                               // y-paired fwd-H tables
        int kx = idx >> 7, yp = idx & 127;
        float a0 = 6.283185307179586f * (float)((kx * (2*yp))     & 255) / 256.f;
        float a1 = 6.283185307179586f * (float)((kx * (2*yp + 1)) & 255) / 256.f;
        g_e2c[idx] = fpack2(cosf(a0), cosf(a1));
        g_e2s[idx] = fpack2(sinf(a0), sinf(a1));
    }
}

// ---------------- spectral weight transpose ----------------
__global__ void ktw(const float* __restrict__ wre, const float* __restrict__ wim){
    int idx = blockIdx.x * 256 + threadIdx.x;
    int ky = idx & 15, kx = (idx >> 4) & 15, o = (idx >> 8) & 63, i = (idx >> 14) & 63, d = idx >> 20;
    int m = kx * 16 + ky;
    g_wt[((d * 256 + m) * 64 + i) * 64 + o] = make_float2(wre[idx], wim[idx]);
}

// ---------------- fc0 ----------------
__global__ void kfc0(const float* __restrict__ x, const float* __restrict__ w,
                     const float* __restrict__ bv, float* __restrict__ out){
    int idx = blockIdx.x * 256 + threadIdx.x;
    int p4 = idx & 16383;
    int c  = (idx >> 14) & 63;
    int b  = idx >> 20;
    const float* xb = x + (size_t)b * 3 * 65536 + p4 * 4;
    float4 a0 = *(const float4*)&xb[0];
    float4 a1 = *(const float4*)&xb[65536];
    float4 a2 = *(const float4*)&xb[131072];
    float w0 = w[c*3], w1 = w[c*3+1], w2 = w[c*3+2], bb = bv[c];
    float4 r;
    r.x = bb + a0.x*w0 + a1.x*w1 + a2.x*w2;
    r.y = bb + a0.y*w0 + a1.y*w1 + a2.y*w2;
    r.z = bb + a0.z*w0 + a1.z*w1 + a2.z*w2;
    r.w = bb + a0.w*w0 + a1.w*w1 + a2.w*w2;
    *(float4*)&out[(size_t)idx * 4] = r;
}

// ---------------- fwd DFT along W: real-input symmetry (R13, measured 53.5us) ----------------
__global__ __launch_bounds__(256) void kfwd1(const float* __restrict__ hin, float2* __restrict__ f1){
    extern __shared__ __align__(16) float dsm1[];
    float* sv  = dsm1;                              // [128][36]
    float* su  = sv + 128*36;                       // [128][40]
    float* ss  = su + 128*40;                       // [128][36]
    float* sd  = ss + 128*36;                       // [128][36]
    float* twc = sd + 128*36;                       // [8][260]
    float* tws = twc + 8*260;
    int tid = threadIdx.x;
    size_t rowbase = (size_t)blockIdx.x * 128;
    int rg = tid >> 3, kg = tid & 7;

    {
        const int k = 0;
        #pragma unroll
        for (int t = 0; t < 4; ++t){
            int idx = tid + t*256;
            int row = idx >> 3, q = idx & 7;
            cpa16(&sv[row*36 + q*4], &hin[(rowbase + row)*256 + k*32 + q*4]);
        }
        #pragma unroll
        for (int t = 0; t < 4; ++t){
            int idx = tid + t*256;
            int row = idx >> 3, q = idx & 7;
            cpa16(&su[row*40 + q*4], &hin[(rowbase + row)*256 + 224 - k*32 + q*4]);
        }
        if (tid < 128)
            cpa16(&su[tid*40 + 32], &hin[(rowbase + tid)*256 + 256 - k*32]);
        CP_COMMIT();
    }
    #pragma unroll
    for (int t = 0; t < 8; ++t){
        int idx = tid + t*256;
        int x = idx & 127, e2 = (idx >> 7) & 1, g = idx >> 8;
        twc[g*260 + e2*128 + x] = g_ec[(g*2 + e2)*256 + x];
        tws[g*260 + e2*128 + x] = g_es[(g*2 + e2)*256 + x];
    }

    u64 ar[4][2], ai[4][2];
    #pragma unroll
    for (int j = 0; j < 4; ++j){ ar[j][0]=ar[j][1]=ai[j][0]=ai[j][1]=0ull; }
    const u64 NEG1 = fpack2(-1.f, -1.f);

    for (int k = 0; k < 4; ++k){
        cp_wait<0>();
        __syncthreads();
        #pragma unroll
        for (int t = 0; t < 8; ++t){
            int idx = tid + t*256;
            int row = idx >> 4, xl = (idx & 15)*2;
            u64 vv = *(const u64*)&sv[row*36 + xl];
            float p0 = (k == 0 && xl == 0) ? 0.f : su[row*40 + 32 - xl];
            float p1 = su[row*40 + 31 - xl];
            u64 pp = fpack2(p0, p1);
            *(u64*)&ss[row*36 + xl] = fadd2(vv, pp);
            *(u64*)&sd[row*36 + xl] = ffma2(pp, NEG1, vv);
        }
        __syncthreads();
        if (k < 3){
            int kn = k + 1;
            #pragma unroll
            for (int t = 0; t < 4; ++t){
                int idx = tid + t*256;
                int row = idx >> 3, q = idx & 7;
                cpa16(&sv[row*36 + q*4], &hin[(rowbase + row)*256 + kn*32 + q*4]);
            }
            #pragma unroll
            for (int t = 0; t < 4; ++t){
                int idx = tid + t*256;
                int row = idx >> 3, q = idx & 7;
                cpa16(&su[row*40 + q*4], &hin[(rowbase + row)*256 + 224 - kn*32 + q*4]);
            }
            if (tid < 128)
                cpa16(&su[tid*40 + 32], &hin[(rowbase + tid)*256 + 256 - kn*32]);
            CP_COMMIT();
        }
        #pragma unroll 4
        for (int j4 = 0; j4 < 32; j4 += 4){
            int xg = k*32 + j4;
            ulonglong2 c0 = *(const ulonglong2*)&twc[kg*260 + xg];
            ulonglong2 c1 = *(const ulonglong2*)&twc[kg*260 + 128 + xg];
            ulonglong2 s0 = *(const ulonglong2*)&tws[kg*260 + xg];
            ulonglong2 s1 = *(const ulonglong2*)&tws[kg*260 + 128 + xg];
            #pragma unroll
            for (int j = 0; j < 4; ++j){
                int r = rg + 32*j;
                ulonglong2 sp = *(const ulonglong2*)&ss[r*36 + j4];
                ulonglong2 dp = *(const ulonglong2*)&sd[r*36 + j4];
                ar[j][0] = ffma2(sp.x, c0.x, ar[j][0]);
                ar[j][0] = ffma2(sp.y, c0.y, ar[j][0]);
                ar[j][1] = ffma2(sp.x, c1.x, ar[j][1]);
                ar[j][1] = ffma2(sp.y, c1.y, ar[j][1]);
                ai[j][0] = ffma2(dp.x, s0.x, ai[j][0]);
                ai[j][0] = ffma2(dp.y, s0.y, ai[j][0]);
                ai[j][1] = ffma2(dp.x, s1.x, ai[j][1]);
                ai[j][1] = ffma2(dp.y, s1.y, ai[j][1]);
            }
        }
        __syncthreads();
    }
    #pragma unroll
    for (int j = 0; j < 4; ++j){
        int r = rg + 32*j;
        float u0 = su[r*40];
        float2 re0 = funpack2(ar[j][0]), im0 = funpack2(ai[j][0]);
        float2 re1 = funpack2(ar[j][1]), im1 = funpack2(ai[j][1]);
        float4 o = make_float4(re0.x + re0.y + u0, im0.x + im0.y,
                               re1.x + re1.y - u0, im1.x + im1.y);
        *(float4*)&f1[(rowbase + r)*16 + kg*2] = o;
    }
}

// ---------------- fwd DFT along H: f32x2 register-tiled (u64 loads, 8B-aligned) ----------------
// smem: sfx/sfy [16 ky][266] + tw2c/tw2s [16 kx][132] u64 = 67840 B
__global__ __launch_bounds__(256) void kfwd2(const float2* __restrict__ f1, float2* __restrict__ modes){
    extern __shared__ __align__(16) float dsmf[];
    float* sfx  = dsmf;                            // [16][266]
    float* sfy  = sfx + 16*266;                    // [16][266]
    u64*   tw2c = (u64*)(sfy + 16*266);            // [16][132]
    u64*   tw2s = tw2c + 16*132;
    int tid = threadIdx.x;                         // 256
    int bc = blockIdx.x;

    // twiddle tables via cp.async
    #pragma unroll
    for (int t = 0; t < 4; ++t){
        int idx = tid + t*256;                     // 1024 x 16B
        int kx = idx >> 6, yq = (idx & 63)*2;
        cpa16(&tw2c[kx*132 + yq], &g_e2c[kx*128 + yq]);
        cpa16(&tw2s[kx*132 + yq], &g_e2s[kx*128 + yq]);
    }
    CP_COMMIT();
    // f1 tile: transpose + split re/im (conflict-free scatter, stride 266)
    {
        const float4* src = (const float4*)(f1 + (size_t)bc * 4096);
        #pragma unroll
        for (int t = 0; t < 8; ++t){
            int idx = tid + t*256;                 // 2048 float4
            int y = idx >> 3, kyq = idx & 7;
            float4 v = src[idx];
            sfx[(2*kyq)*266 + y]     = v.x;
            sfy[(2*kyq)*266 + y]     = v.y;
            sfx[(2*kyq + 1)*266 + y] = v.z;
            sfy[(2*kyq + 1)*266 + y] = v.w;
        }
    }
    cp_wait<0>();
    __syncthreads();

    int kx = tid >> 4, ky = tid & 15;
    u64 A = 0ull, B = 0ull, C = 0ull, D = 0ull;
    const float* fx = &sfx[ky*266];                // 8B-aligned (266*4 % 8 == 0)
    const float* fy = &sfy[ky*266];
    const u64* tc = &tw2c[kx*132];                 // 16B-aligned
    const u64* ts = &tw2s[kx*132];
    #pragma unroll 8
    for (int i = 0; i < 64; ++i){
        u64 vx0 = *(const u64*)&fx[4*i];
        u64 vx1 = *(const u64*)&fx[4*i + 2];
        u64 vy0 = *(const u64*)&fy[4*i];
        u64 vy1 = *(const u64*)&fy[4*i + 2];
        ulonglong2 c2 = *(const ulonglong2*)&tc[2*i];
        ulonglong2 s2 = *(const ulonglong2*)&ts[2*i];
        A = ffma2(vx0, c2.x, A); A = ffma2(vx1, c2.y, A);
        B = ffma2(vy0, s2.x, B); B = ffma2(vy1, s2.y, B);
        C = ffma2(vy0, c2.x, C); C = ffma2(vy1, c2.y, C);
        D = ffma2(vx0, s2.x, D); D = ffma2(vx1, s2.y, D);
    }
    float2 a = funpack2(A), b2 = funpack2(B), c = funpack2(C), d = funpack2(D);
    modes[bc*256 + tid] = make_float2(a.x + a.y + b2.x + b2.y,
                                      c.x + c.y - d.x - d.y);
}

// ---------------- mode mixing -> mixedT [b][ky][kx][o] ----------------
__global__ void kmix(const float2* __restrict__ modes, const float2* __restrict__ wt,
                     float2* __restrict__ mixedT){
    __shared__ float2 swt[4096];
    __shared__ float2 sin_[512];
    int tid = threadIdx.x, m = blockIdx.x;
    int ky = m & 15, kx = m >> 4;
    const float2* wsrc = wt + (size_t)m * 4096;
    for (int idx = tid; idx < 4096; idx += 256) swt[idx] = wsrc[idx];
    for (int idx = tid; idx < 512; idx += 256){
        int b = idx >> 6, i = idx & 63;
        sin_[idx] = modes[(b*64 + i)*256 + m];
    }
    __syncthreads();
    int o = tid & 63;
    for (int half = 0; half < 2; ++half){
        int b = (tid >> 6) + half * 4;
        float re = 0.f, im = 0.f;
        #pragma unroll 8
        for (int i = 0; i < 64; ++i){
            float2 a = sin_[b*64 + i];
            float2 wv = swt[i*64 + o];
            re += a.x*wv.x - a.y*wv.y;
            im += a.x*wv.y + a.y*wv.x;
        }
        mixedT[((b*16 + ky)*16 + kx)*64 + o] = make_float2(re, im);
    }
}

// ---------------- inv DFT along H: G [b][y][ky][c] ----------------
__global__ void kinv1(const float2* __restrict__ mixedT, float2* __restrict__ G){
    __shared__ float2 sm[1024];
    __shared__ float ct[256], st[256];
    int tid = threadIdx.x;                         // 256
    int ky = blockIdx.x & 15, yg = (blockIdx.x >> 4) & 15, b = blockIdx.x >> 8;
    {
        float ang = 6.283185307179586f * (float)tid / 256.f;
        ct[tid] = cosf(ang); st[tid] = sinf(ang);
    }
    const float2* src = mixedT + (size_t)(b*16 + ky) * 1024;
    for (int idx = tid; idx < 1024; idx += 256) sm[idx] = src[idx];
    __syncthreads();
    int c = tid & 63, yl = tid >> 6;
    #pragma unroll
    for (int yi = 0; yi < 4; ++yi){
        int yy = yg*16 + yl*4 + yi;
        float re = 0.f, im = 0.f;
        #pragma unroll
        for (int kx = 0; kx < 16; ++kx){
            float2 v = sm[kx*64 + c];
            int t = (kx * yy) & 255;
            float cc = ct[t], ss = st[t];
            re += v.x*cc - v.y*ss;
            im += v.x*ss + v.y*cc;
        }
        G[((size_t)(b*256 + yy)*16 + ky)*64 + c] = make_float2(re, im);
    }
}

// ---------------- fused: 1x1 conv + inv DFT along W + bias + relu (R12/R13) ----------------
#define CMAD(oo, wd) \
    acc[oo][0]=ffma2(wd,h01.x,acc[oo][0]); acc[oo][1]=ffma2(wd,h01.y,acc[oo][1]); \
    acc[oo][2]=ffma2(wd,h23.x,acc[oo][2]); acc[oo][3]=ffma2(wd,h23.y,acc[oo][3]);
#define IMAD2(oo, gxd, gyd) \
    acc[oo][0]=ffma2(gxd,A01.x,acc[oo][0]); acc[oo][0]=ffma2(gyd,B01.x,acc[oo][0]); \
    acc[oo][1]=ffma2(gxd,A01.y,acc[oo][1]); acc[oo][1]=ffma2(gyd,B01.y,acc[oo][1]); \
    acc[oo][2]=ffma2(gxd,A23.x,acc[oo][2]); acc[oo][2]=ffma2(gyd,B23.x,acc[oo][2]); \
    acc[oo][3]=ffma2(gxd,A23.y,acc[oo][3]); acc[oo][3]=ffma2(gyd,B23.y,acc[oo][3]);

__global__ __launch_bounds__(256) void kfused(
        const float* __restrict__ hin, const float2* __restrict__ G,
        const float* __restrict__ ww, const float* __restrict__ wb,
        float* __restrict__ hout){
    extern __shared__ __align__(16) float dsm2[];
    float*  sh = dsm2;                             // [64 i][132]
    float*  sA = sh + 64*132;                      // [16 ky][132]
    float*  sB = sA + 16*132;                      // [16 ky][132]
    float*  sw = sB + 16*132;                      // [64 i][66]
    float2* sg = (float2*)(sw + 64*66);            // [16 ky][66]
    float*  sb = (float*)(sg + 16*66);             // [64]
    int tid = threadIdx.x;                         // 256
    int xh = blockIdx.x & 1;
    int y  = (blockIdx.x >> 1) & 255;
    int b  = blockIdx.x >> 9;
    int xg2 = xh * 128;

    {
        const float2* Gb = G + ((size_t)(b*256) + y) * 1024;
        #pragma unroll
        for (int k = 0; k < 4; ++k){
            int idx = tid + k*256;
            int ky = idx >> 6, o = idx & 63;
            cpa8(&sg[ky*66 + o], &Gb[idx]);
        }
        #pragma unroll
        for (int k = 0; k < 2; ++k){
            int idx = tid + k*256;
            int ky = idx >> 5, xq = (idx & 31)*4;
            if (ky < 16){
                cpa16(&sA[ky*132 + xq], &g_ic[ky*256 + xg2 + xq]);
                cpa16(&sB[ky*132 + xq], &g_is[ky*256 + xg2 + xq]);
            }
        }
        CP_COMMIT();
    }
    {
        const float* hb = hin + ((size_t)(b*64)*256 + y)*256 + xg2;
        #pragma unroll
        for (int k = 0; k < 8; ++k){
            int idx = tid + k*256;
            int i = idx >> 5, xq = (idx & 31)*4;
            cpa16(&sh[i*132 + xq], &hb[(size_t)i*65536 + xq]);
        }
        CP_COMMIT();
    }
    #pragma unroll
    for (int k = 0; k < 16; ++k){
        int idx = tid + k*256;
        int i = idx & 63, o = idx >> 6;
        sw[i*66 + o] = ww[idx];
    }
    if (tid < 64) sb[tid] = wb[tid];
    cp_wait<1>();
    __syncthreads();

    int w = tid >> 5, l = tid & 31;
    int o0 = ((w & 1)*8 + (l >> 2)) * 4;
    int x0 = ((w >> 1)*4 + (l & 3)) * 8;
    u64 acc[4][4];
    {
        float4 bv = *(const float4*)&sb[o0];
        u64 b0 = fpack2(bv.x, bv.x), b1 = fpack2(bv.y, bv.y);
        u64 b2 = fpack2(bv.z, bv.z), b3 = fpack2(bv.w, bv.w);
        #pragma unroll
        for (int p = 0; p < 4; ++p){ acc[0][p]=b0; acc[1][p]=b1; acc[2][p]=b2; acc[3][p]=b3; }
    }
    #pragma unroll 4
    for (int ky = 0; ky < 16; ++ky){
        ulonglong2 A01 = *(const ulonglong2*)&sA[ky*132 + x0];
        ulonglong2 A23 = *(const ulonglong2*)&sA[ky*132 + x0 + 4];
        ulonglong2 B01 = *(const ulonglong2*)&sB[ky*132 + x0];
        ulonglong2 B23 = *(const ulonglong2*)&sB[ky*132 + x0 + 4];
        float2 ga = sg[ky*66 + o0],     gb2 = sg[ky*66 + o0 + 1];
        float2 gc = sg[ky*66 + o0 + 2], gd  = sg[ky*66 + o0 + 3];
        u64 gx0 = fpack2(ga.x, ga.x),  gy0 = fpack2(ga.y, ga.y);
        u64 gx1 = fpack2(gb2.x, gb2.x), gy1 = fpack2(gb2.y, gb2.y);
        u64 gx2 = fpack2(gc.x, gc.x),  gy2 = fpack2(gc.y, gc.y);
        u64 gx3 = fpack2(gd.x, gd.x),  gy3 = fpack2(gd.y, gd.y);
        IMAD2(0, gx0, gy0) IMAD2(1, gx1, gy1) IMAD2(2, gx2, gy2) IMAD2(3, gx3, gy3)
    }
    cp_wait<0>();
    __syncthreads();
    #pragma unroll 4
    for (int i = 0; i < 64; ++i){
        ulonglong2 h01 = *(const ulonglong2*)&sh[i*132 + x0];
        ulonglong2 h23 = *(const ulonglong2*)&sh[i*132 + x0 + 4];
        float2 wab = *(const float2*)&sw[i*66 + o0];
        float2 wcd = *(const float2*)&sw[i*66 + o0 + 2];
        u64 w0 = fpack2(wab.x, wab.x), w1 = fpack2(wab.y, wab.y);
        u64 w2 = fpack2(wcd.x, wcd.x), w3 = fpack2(wcd.y, wcd.y);
        CMAD(0, w0) CMAD(1, w1) CMAD(2, w2) CMAD(3, w3)
    }
    float* ob = hout + ((size_t)(b*64 + o0)*256 + y)*256 + xg2 + x0;
    #pragma unroll
    for (int oo = 0; oo < 4; ++oo){
        float2 p0 = funpack2(acc[oo][0]), p1 = funpack2(acc[oo][1]);
        float2 p2 = funpack2(acc[oo][2]), p3 = funpack2(acc[oo][3]);
        float4 v0 = make_float4(fmaxf(p0.x,0.f), fmaxf(p0.y,0.f), fmaxf(p1.x,0.f), fmaxf(p1.y,0.f));
        float4 v1 = make_float4(fmaxf(p2.x,0.f), fmaxf(p2.y,0.f), fmaxf(p3.x,0.f), fmaxf(p3.y,0.f));
        *(float4*)&ob[(size_t)oo*65536]     = v0;
        *(float4*)&ob[(size_t)oo*65536 + 4] = v1;
    }
}

// ---------------- fused MLP head ----------------
#define HMAD(mm, wd) \
    acc[mm][0]=ffma2(wd,h01.x,acc[mm][0]); acc[mm][1]=ffma2(wd,h01.y,acc[mm][1]); \
    acc[mm][2]=ffma2(wd,h23.x,acc[mm][2]); acc[mm][3]=ffma2(wd,h23.y,acc[mm][3]);

__global__ __launch_bounds__(256) void khead(
        const float* __restrict__ hin,
        const float* __restrict__ w1, const float* __restrict__ b1,
        const float* __restrict__ w2, const float* __restrict__ b2,
        float* __restrict__ out){
    extern __shared__ __align__(16) float dsm3[];
    float* sh   = dsm3;                            // [64 c][68]
    float* sw1t = sh + 64*68;                      // [64 c][130]
    float* shid = sw1t + 64*130;                   // [128 m][68]
    float* sw2s = shid + 128*68;                   // [384]
    float* sb1s = sw2s + 384;                      // [128]
    int tid = threadIdx.x;                         // 256
    int xc = (blockIdx.x & 3) << 6;
    int y  = (blockIdx.x >> 2) & 255;
    int b  = blockIdx.x >> 10;

    {
        const float* hb = hin + ((size_t)(b*64)*256 + y)*256 + xc;
        #pragma unroll
        for (int k = 0; k < 4; ++k){
            int idx = tid + k*256;
            int c = idx >> 4, xq = (idx & 15)*4;
            cpa16(&sh[c*68 + xq], &hb[(size_t)c*65536 + xq]);
        }
        CP_COMMIT();
    }
    #pragma unroll
    for (int k = 0; k < 32; ++k){
        int idx = tid + k*256;
        int c = idx & 63, m = idx >> 6;
        sw1t[c*130 + m] = w1[idx];
    }
    for (int idx = tid; idx < 384; idx += 256) sw2s[idx] = w2[idx];
    if (tid < 128) sb1s[tid] = b1[tid];
    cp_wait<0>();
    __syncthreads();

    int w = tid >> 5, l = tid & 31;
    int m0 = ((w & 3)*8 + (l >> 2)) * 4;
    int x0 = ((w >> 2)*4 + (l & 3)) * 8;
    u64 acc[4][4];
    {
        float4 bv = *(const float4*)&sb1s[m0];
        u64 b0v = fpack2(bv.x,bv.x), b1v = fpack2(bv.y,bv.y);
        u64 b2v = fpack2(bv.z,bv.z), b3v = fpack2(bv.w,bv.w);
        #pragma unroll
        for (int p = 0; p < 4; ++p){ acc[0][p]=b0v; acc[1][p]=b1v; acc[2][p]=b2v; acc[3][p]=b3v; }
    }
    #pragma unroll 4
    for (int c = 0; c < 64; ++c){
        ulonglong2 h01 = *(const ulonglong2*)&sh[c*68 + x0];
        ulonglong2 h23 = *(const ulonglong2*)&sh[c*68 + x0 + 4];
        float2 wab = *(const float2*)&sw1t[c*130 + m0];
        float2 wcd = *(const float2*)&sw1t[c*130 + m0 + 2];
        u64 w0 = fpack2(wab.x,wab.x), w1d = fpack2(wab.y,wab.y);
        u64 w2d = fpack2(wcd.x,wcd.x), w3d = fpack2(wcd.y,wcd.y);
        HMAD(0, w0) HMAD(1, w1d) HMAD(2, w2d) HMAD(3, w3d)
    }
    #pragma unroll
    for (int mm = 0; mm < 4; ++mm){
        float2 p0 = funpack2(acc[mm][0]), p1 = funpack2(acc[mm][1]);
        float2 p2 = funpack2(acc[mm][2]), p3 = funpack2(acc[mm][3]);
        float4 v0 = make_float4(fmaxf(p0.x,0.f), fmaxf(p0.y,0.f), fmaxf(p1.x,0.f), fmaxf(p1.y,0.f));
        float4 v1 = make_float4(fmaxf(p2.x,0.f), fmaxf(p2.y,0.f), fmaxf(p3.x,0.f), fmaxf(p3.y,0.f));
        *(float4*)&shid[(m0+mm)*68 + x0]     = v0;
        *(float4*)&shid[(m0+mm)*68 + x0 + 4] = v1;
    }
    __syncthreads();
    if (tid < 192){
        int o = tid >> 6, xl = tid & 63;
        float a0 = b2[o], a1 = 0.f;                 // split dependency chain
        #pragma unroll 8
        for (int m = 0; m < 64; ++m){
            a0 = fmaf(shid[m*68 + xl],        sw2s[o*128 + m],      a0);
            a1 = fmaf(shid[(m + 64)*68 + xl], sw2s[o*128 + m + 64], a1);
        }
        out[((size_t)(b*3 + o)*256 + y)*256 + xc + xl] = a0 + a1;
    }
}

// ---------------- host ----------------
extern "C" void kernel_launch(void* const* d_in, const int* in_sizes, int n_in,
                              void* d_out, int out_size) {
    const float* x       = (const float*)d_in[0];
    const float* fc0_w   = (const float*)d_in[1];
    const float* fc0_b   = (const float*)d_in[2];
    const float* spec_re = (const float*)d_in[3];
    const float* spec_im = (const float*)d_in[4];
    const float* w_w     = (const float*)d_in[5];
    const float* w_b     = (const float*)d_in[6];
    const float* fc1_w   = (const float*)d_in[7];
    const float* fc1_b   = (const float*)d_in[8];
    const float* fc2_w   = (const float*)d_in[9];
    const float* fc2_b   = (const float*)d_in[10];

    float  *h0, *h1;
    float2 *f1, *mo, *mx, *G, *wt;
    cudaGetSymbolAddress((void**)&h0, g_h0);
    cudaGetSymbolAddress((void**)&h1, g_h1);
    cudaGetSymbolAddress((void**)&f1, g_f1);
    cudaGetSymbolAddress((void**)&mo, g_modes);
    cudaGetSymbolAddress((void**)&mx, g_mixed);
    cudaGetSymbolAddress((void**)&G,  g_G);
    cudaGetSymbolAddress((void**)&wt, g_wt);

    const int SM1 = (128*36 + 128*40 + 128*36 + 128*36 + 2*8*260) * 4;          // 92416
    const int SMF = (2*16*266)*4 + (2*16*132)*8;                                // 67840
    const int SM2 = (64*132 + 32*132 + 64*66)*4 + 16*66*8 + 64*4;               // 76288
    const int SM3 = (64*68 + 64*130 + 128*68)*4 + 384*4 + 128*4;                // 87552
    cudaFuncSetAttribute(kfwd1,  cudaFuncAttributeMaxDynamicSharedMemorySize, SM1);
    cudaFuncSetAttribute(kfwd2,  cudaFuncAttributeMaxDynamicSharedMemorySize, SMF);
    cudaFuncSetAttribute(kfused, cudaFuncAttributeMaxDynamicSharedMemorySize, SM2);
    cudaFuncSetAttribute(khead,  cudaFuncAttributeMaxDynamicSharedMemorySize, SM3);

    kprep<<<16, 256>>>();
    ktw<<<16384, 256>>>(spec_re, spec_im);
    kfc0<<<32768, 256>>>(x, fc0_w, fc0_b, h0);

    float* hin = h0;
    float* hout = h1;
    for (int d = 0; d < NDEPTH; ++d) {
        kfwd1<<<1024, 256, SM1>>>(hin, f1);
        kfwd2<<<512, 256, SMF>>>(f1, mo);
        kmix<<<256, 256>>>(mo, wt + (size_t)d * 256 * 4096, mx);
        kinv1<<<2048, 256>>>(mx, G);
        kfused<<<4096, 256, SM2>>>(hin, G, w_w + d * 4096, w_b + d * 64, hout);
        float* t = hin; hin = hout; hout = t;
    }
    khead<<<8192, 256, SM3>>>(hin, fc1_w, fc1_b, fc2_w, fc2_b, (float*)d_out);
}

// round 16
// speedup vs baseline: 1.3487x; 1.0184x over previous
#include <cuda_runtime.h>

#define NDEPTH 4
typedef unsigned long long u64;

__device__ __forceinline__ u64 ffma2(u64 a, u64 b, u64 c){
    u64 d; asm("fma.rn.f32x2 %0, %1, %2, %3;" : "=l"(d) : "l"(a), "l"(b), "l"(c)); return d;
}
__device__ __forceinline__ u64 fadd2(u64 a, u64 b){
    u64 d; asm("add.rn.f32x2 %0, %1, %2;" : "=l"(d) : "l"(a), "l"(b)); return d;
}
__device__ __forceinline__ u64 fpack2(float x, float y){
    u64 d; asm("mov.b64 %0, {%1, %2};" : "=l"(d) : "f"(x), "f"(y)); return d;
}
__device__ __forceinline__ float2 funpack2(u64 a){
    float x, y; asm("mov.b64 {%0, %1}, %2;" : "=f"(x), "=f"(y) : "l"(a)); return make_float2(x, y);
}
__device__ __forceinline__ void cpa16(void* dst_smem, const void* src){
    unsigned sa = (unsigned)__cvta_generic_to_shared(dst_smem);
    asm volatile("cp.async.cg.shared.global [%0], [%1], 16;" :: "r"(sa), "l"(src));
}
__device__ __forceinline__ void cpa8(void* dst_smem, const void* src){
    unsigned sa = (unsigned)__cvta_generic_to_shared(dst_smem);
    asm volatile("cp.async.ca.shared.global [%0], [%1], 8;" :: "r"(sa), "l"(src));
}
#define CP_COMMIT() asm volatile("cp.async.commit_group;")
template<int N> __device__ __forceinline__ void cp_wait(){
    asm volatile("cp.async.wait_group %0;" :: "n"(N));
}

// ---------------- scratch (device globals) ----------------
__device__ float  g_h0[8*64*65536 + 64];
__device__ float  g_h1[8*64*65536 + 64];
__device__ float2 g_f1[8*64*256*16];
__device__ float2 g_modes[8*64*256];
__device__ float2 g_mixed[8*64*256];               // mixedT [b][ky][kx][o]
__device__ float2 g_G[8*256*16*64];                // [b][y][ky][c]
__device__ float2 g_wt[NDEPTH*256*64*64];          // [d][m][i][o]
__device__ float  g_ec[16*256], g_es[16*256];      // fwd: cos, -sin
__device__ float  g_ic[16*256], g_is[16*256];      // inv-W scaled tables
__device__ u64    g_e2c[16*128], g_e2s[16*128];    // y-paired (cos,cos)/(sin,sin)

// ---------------- prep: DFT tables ----------------
__global__ void kprep(){
    int idx = blockIdx.x * 256 + threadIdx.x;      // 4096
    int x = idx & 255, ky = idx >> 8;
    float ang = 6.283185307179586f * (float)((ky * x) & 255) / 256.f;
    float c = cosf(ang), s = sinf(ang);
    g_ec[idx] = c; g_es[idx] = -s;
    const float sc = 1.f / 65536.f;
    g_ic[idx] = (ky == 0) ? sc : 2.f * sc * c;
    g_is[idx] = (ky == 0) ? 0.f : -2.f * sc * s;
    if (idx < 2048){                               // y-paired tables
        int kx = idx >> 7, yp = idx & 127;
        float a0 = 6.283185307179586f * (float)((kx * (2*yp))     & 255) / 256.f;
        float a1 = 6.283185307179586f * (float)((kx * (2*yp + 1)) & 255) / 256.f;
        g_e2c[idx] = fpack2(cosf(a0), cosf(a1));
        g_e2s[idx] = fpack2(sinf(a0), sinf(a1));
    }
}

// ---------------- spectral weight transpose ----------------
__global__ void ktw(const float* __restrict__ wre, const float* __restrict__ wim){
    int idx = blockIdx.x * 256 + threadIdx.x;
    int ky = idx & 15, kx = (idx >> 4) & 15, o = (idx >> 8) & 63, i = (idx >> 14) & 63, d = idx >> 20;
    int m = kx * 16 + ky;
    g_wt[((d * 256 + m) * 64 + i) * 64 + o] = make_float2(wre[idx], wim[idx]);
}

// ---------------- fc0 ----------------
__global__ void kfc0(const float* __restrict__ x, const float* __restrict__ w,
                     const float* __restrict__ bv, float* __restrict__ out){
    int idx = blockIdx.x * 256 + threadIdx.x;
    int p4 = idx & 16383;
    int c  = (idx >> 14) & 63;
    int b  = idx >> 20;
    const float* xb = x + (size_t)b * 3 * 65536 + p4 * 4;
    float4 a0 = *(const float4*)&xb[0];
    float4 a1 = *(const float4*)&xb[65536];
    float4 a2 = *(const float4*)&xb[131072];
    float w0 = w[c*3], w1 = w[c*3+1], w2 = w[c*3+2], bb = bv[c];
    float4 r;
    r.x = bb + a0.x*w0 + a1.x*w1 + a2.x*w2;
    r.y = bb + a0.y*w0 + a1.y*w1 + a2.y*w2;
    r.z = bb + a0.z*w0 + a1.z*w1 + a2.z*w2;
    r.w = bb + a0.w*w0 + a1.w*w1 + a2.w*w2;
    *(float4*)&out[(size_t)idx * 4] = r;
}

// ---------------- fwd DFT along W: real-input symmetry (R13/R15) ----------------
__global__ __launch_bounds__(256) void kfwd1(const float* __restrict__ hin, float2* __restrict__ f1){
    extern __shared__ __align__(16) float dsm1[];
    float* sv  = dsm1;                              // [128][36]
    float* su  = sv + 128*36;                       // [128][40]
    float* ss  = su + 128*40;                       // [128][36]
    float* sd  = ss + 128*36;                       // [128][36]
    float* twc = sd + 128*36;                       // [8][260]
    float* tws = twc + 8*260;
    int tid = threadIdx.x;
    size_t rowbase = (size_t)blockIdx.x * 128;
    int rg = tid >> 3, kg = tid & 7;

    {
        const int k = 0;
        #pragma unroll
        for (int t = 0; t < 4; ++t){
            int idx = tid + t*256;
            int row = idx >> 3, q = idx & 7;
            cpa16(&sv[row*36 + q*4], &hin[(rowbase + row)*256 + k*32 + q*4]);
        }
        #pragma unroll
        for (int t = 0; t < 4; ++t){
            int idx = tid + t*256;
            int row = idx >> 3, q = idx & 7;
            cpa16(&su[row*40 + q*4], &hin[(rowbase + row)*256 + 224 - k*32 + q*4]);
        }
        if (tid < 128)
            cpa16(&su[tid*40 + 32], &hin[(rowbase + tid)*256 + 256 - k*32]);
        CP_COMMIT();
    }
    #pragma unroll
    for (int t = 0; t < 8; ++t){
        int idx = tid + t*256;
        int x = idx & 127, e2 = (idx >> 7) & 1, g = idx >> 8;
        twc[g*260 + e2*128 + x] = g_ec[(g*2 + e2)*256 + x];
        tws[g*260 + e2*128 + x] = g_es[(g*2 + e2)*256 + x];
    }

    u64 ar[4][2], ai[4][2];
    #pragma unroll
    for (int j = 0; j < 4; ++j){ ar[j][0]=ar[j][1]=ai[j][0]=ai[j][1]=0ull; }
    const u64 NEG1 = fpack2(-1.f, -1.f);

    for (int k = 0; k < 4; ++k){
        cp_wait<0>();
        __syncthreads();
        #pragma unroll
        for (int t = 0; t < 8; ++t){
            int idx = tid + t*256;
            int row = idx >> 4, xl = (idx & 15)*2;
            u64 vv = *(const u64*)&sv[row*36 + xl];
            float p0 = (k == 0 && xl == 0) ? 0.f : su[row*40 + 32 - xl];
            float p1 = su[row*40 + 31 - xl];
            u64 pp = fpack2(p0, p1);
            *(u64*)&ss[row*36 + xl] = fadd2(vv, pp);
            *(u64*)&sd[row*36 + xl] = ffma2(pp, NEG1, vv);
        }
        __syncthreads();
        if (k < 3){
            int kn = k + 1;
            #pragma unroll
            for (int t = 0; t < 4; ++t){
                int idx = tid + t*256;
                int row = idx >> 3, q = idx & 7;
                cpa16(&sv[row*36 + q*4], &hin[(rowbase + row)*256 + kn*32 + q*4]);
            }
            #pragma unroll
            for (int t = 0; t < 4; ++t){
                int idx = tid + t*256;
                int row = idx >> 3, q = idx & 7;
                cpa16(&su[row*40 + q*4], &hin[(rowbase + row)*256 + 224 - kn*32 + q*4]);
            }
            if (tid < 128)
                cpa16(&su[tid*40 + 32], &hin[(rowbase + tid)*256 + 256 - kn*32]);
            CP_COMMIT();
        }
        #pragma unroll 4
        for (int j4 = 0; j4 < 32; j4 += 4){
            int xg = k*32 + j4;
            ulonglong2 c0 = *(const ulonglong2*)&twc[kg*260 + xg];
            ulonglong2 c1 = *(const ulonglong2*)&twc[kg*260 + 128 + xg];
            ulonglong2 s0 = *(const ulonglong2*)&tws[kg*260 + xg];
            ulonglong2 s1 = *(const ulonglong2*)&tws[kg*260 + 128 + xg];
            #pragma unroll
            for (int j = 0; j < 4; ++j){
                int r = rg + 32*j;
                ulonglong2 sp = *(const ulonglong2*)&ss[r*36 + j4];
                ulonglong2 dp = *(const ulonglong2*)&sd[r*36 + j4];
                ar[j][0] = ffma2(sp.x, c0.x, ar[j][0]);
                ar[j][0] = ffma2(sp.y, c0.y, ar[j][0]);
                ar[j][1] = ffma2(sp.x, c1.x, ar[j][1]);
                ar[j][1] = ffma2(sp.y, c1.y, ar[j][1]);
                ai[j][0] = ffma2(dp.x, s0.x, ai[j][0]);
                ai[j][0] = ffma2(dp.y, s0.y, ai[j][0]);
                ai[j][1] = ffma2(dp.x, s1.x, ai[j][1]);
                ai[j][1] = ffma2(dp.y, s1.y, ai[j][1]);
            }
        }
        __syncthreads();
    }
    #pragma unroll
    for (int j = 0; j < 4; ++j){
        int r = rg + 32*j;
        float u0 = su[r*40];
        float2 re0 = funpack2(ar[j][0]), im0 = funpack2(ai[j][0]);
        float2 re1 = funpack2(ar[j][1]), im1 = funpack2(ai[j][1]);
        float4 o = make_float4(re0.x + re0.y + u0, im0.x + im0.y,
                               re1.x + re1.y - u0, im1.x + im1.y);
        *(float4*)&f1[(rowbase + r)*16 + kg*2] = o;
    }
}

// ---------------- fwd DFT along H: f32x2 register-tiled (R15) ----------------
__global__ __launch_bounds__(256) void kfwd2(const float2* __restrict__ f1, float2* __restrict__ modes){
    extern __shared__ __align__(16) float dsmf[];
    float* sfx  = dsmf;                            // [16][266]
    float* sfy  = sfx + 16*266;                    // [16][266]
    u64*   tw2c = (u64*)(sfy + 16*266);            // [16][132]
    u64*   tw2s = tw2c + 16*132;
    int tid = threadIdx.x;                         // 256
    int bc = blockIdx.x;

    #pragma unroll
    for (int t = 0; t < 4; ++t){
        int idx = tid + t*256;
        int kx = idx >> 6, yq = (idx & 63)*2;
        cpa16(&tw2c[kx*132 + yq], &g_e2c[kx*128 + yq]);
        cpa16(&tw2s[kx*132 + yq], &g_e2s[kx*128 + yq]);
    }
    CP_COMMIT();
    {
        const float4* src = (const float4*)(f1 + (size_t)bc * 4096);
        #pragma unroll
        for (int t = 0; t < 8; ++t){
            int idx = tid + t*256;
            int y = idx >> 3, kyq = idx & 7;
            float4 v = src[idx];
            sfx[(2*kyq)*266 + y]     = v.x;
            sfy[(2*kyq)*266 + y]     = v.y;
            sfx[(2*kyq + 1)*266 + y] = v.z;
            sfy[(2*kyq + 1)*266 + y] = v.w;
        }
    }
    cp_wait<0>();
    __syncthreads();

    int kx = tid >> 4, ky = tid & 15;
    u64 A = 0ull, B = 0ull, C = 0ull, D = 0ull;
    const float* fx = &sfx[ky*266];
    const float* fy = &sfy[ky*266];
    const u64* tc = &tw2c[kx*132];
    const u64* ts = &tw2s[kx*132];
    #pragma unroll 8
    for (int i = 0; i < 64; ++i){
        u64 vx0 = *(const u64*)&fx[4*i];
        u64 vx1 = *(const u64*)&fx[4*i + 2];
        u64 vy0 = *(const u64*)&fy[4*i];
        u64 vy1 = *(const u64*)&fy[4*i + 2];
        ulonglong2 c2 = *(const ulonglong2*)&tc[2*i];
        ulonglong2 s2 = *(const ulonglong2*)&ts[2*i];
        A = ffma2(vx0, c2.x, A); A = ffma2(vx1, c2.y, A);
        B = ffma2(vy0, s2.x, B); B = ffma2(vy1, s2.y, B);
        C = ffma2(vy0, c2.x, C); C = ffma2(vy1, c2.y, C);
        D = ffma2(vx0, s2.x, D); D = ffma2(vx1, s2.y, D);
    }
    float2 a = funpack2(A), b2 = funpack2(B), c = funpack2(C), d = funpack2(D);
    modes[bc*256 + tid] = make_float2(a.x + a.y + b2.x + b2.y,
                                      c.x + c.y - d.x - d.y);
}

// ---------------- mode mixing -> mixedT [b][ky][kx][o] ----------------
__global__ void kmix(const float2* __restrict__ modes, const float2* __restrict__ wt,
                     float2* __restrict__ mixedT){
    __shared__ float2 swt[4096];
    __shared__ float2 sin_[512];
    int tid = threadIdx.x, m = blockIdx.x;
    int ky = m & 15, kx = m >> 4;
    const float2* wsrc = wt + (size_t)m * 4096;
    for (int idx = tid; idx < 4096; idx += 256) swt[idx] = wsrc[idx];
    for (int idx = tid; idx < 512; idx += 256){
        int b = idx >> 6, i = idx & 63;
        sin_[idx] = modes[(b*64 + i)*256 + m];
    }
    __syncthreads();
    int o = tid & 63;
    for (int half = 0; half < 2; ++half){
        int b = (tid >> 6) + half * 4;
        float re = 0.f, im = 0.f;
        #pragma unroll 8
        for (int i = 0; i < 64; ++i){
            float2 a = sin_[b*64 + i];
            float2 wv = swt[i*64 + o];
            re += a.x*wv.x - a.y*wv.y;
            im += a.x*wv.y + a.y*wv.x;
        }
        mixedT[((b*16 + ky)*16 + kx)*64 + o] = make_float2(re, im);
    }
}

// ---------------- inv DFT along H: f32x2, broadcast twiddles, reg-held modes ----------------
// block = (b, ky, yhalf); thread = (ygroup, c); 16 FFMA2 per kx-step, twiddles broadcast
__global__ __launch_bounds__(256) void kinv1(const float2* __restrict__ mixedT, float2* __restrict__ G){
    __shared__ __align__(16) u64 twc[16*68];       // [kx][64 ypairs + pad]
    __shared__ __align__(16) u64 tws[16*68];
    int tid = threadIdx.x;                         // 256
    int ky = blockIdx.x & 15, yh = (blockIdx.x >> 4) & 1, b = blockIdx.x >> 5;

    #pragma unroll
    for (int t = 0; t < 4; ++t){
        int idx = tid + t*256;                     // 1024 = 16 kx * 64 ypairs
        int kx = idx >> 6, p = idx & 63;
        twc[kx*68 + p] = g_e2c[kx*128 + yh*64 + p];
        tws[kx*68 + p] = g_e2s[kx*128 + yh*64 + p];
    }
    int yg = tid >> 6, c = tid & 63;
    // per-thread mode registers (loop-invariant over y)
    float mr[16], mi[16];
    {
        const float2* msrc = mixedT + (size_t)(b*16 + ky) * 1024 + c;
        #pragma unroll
        for (int kx = 0; kx < 16; ++kx){
            float2 v = msrc[kx*64];
            mr[kx] = v.x; mi[kx] = v.y;
        }
    }
    __syncthreads();

    int pbase = yg*16;                             // 16 ypairs per thread
    #pragma unroll
    for (int ch = 0; ch < 4; ++ch){
        int p0 = pbase + ch*4;
        u64 aR[4] = {0ull,0ull,0ull,0ull};
        u64 aI[4] = {0ull,0ull,0ull,0ull};
        #pragma unroll
        for (int kx = 0; kx < 16; ++kx){
            ulonglong2 cA = *(const ulonglong2*)&twc[kx*68 + p0];
            ulonglong2 cB = *(const ulonglong2*)&twc[kx*68 + p0 + 2];
            ulonglong2 sA = *(const ulonglong2*)&tws[kx*68 + p0];
            ulonglong2 sB = *(const ulonglong2*)&tws[kx*68 + p0 + 2];
            u64 mrd = fpack2(mr[kx], mr[kx]);
            u64 mid = fpack2(mi[kx], mi[kx]);
            u64 nid = fpack2(-mi[kx], -mi[kx]);
            aR[0] = ffma2(mrd, cA.x, aR[0]); aR[0] = ffma2(nid, sA.x, aR[0]);
            aR[1] = ffma2(mrd, cA.y, aR[1]); aR[1] = ffma2(nid, sA.y, aR[1]);
            aR[2] = ffma2(mrd, cB.x, aR[2]); aR[2] = ffma2(nid, sB.x, aR[2]);
            aR[3] = ffma2(mrd, cB.y, aR[3]); aR[3] = ffma2(nid, sB.y, aR[3]);
            aI[0] = ffma2(mrd, sA.x, aI[0]); aI[0] = ffma2(mid, cA.x, aI[0]);
            aI[1] = ffma2(mrd, sA.y, aI[1]); aI[1] = ffma2(mid, cA.y, aI[1]);
            aI[2] = ffma2(mrd, sB.x, aI[2]); aI[2] = ffma2(mid, cB.x, aI[2]);
            aI[3] = ffma2(mrd, sB.y, aI[3]); aI[3] = ffma2(mid, cB.y, aI[3]);
        }
        int y0 = yh*128 + p0*2;                    // first y of this chunk
        #pragma unroll
        for (int j = 0; j < 4; ++j){
            float2 r = funpack2(aR[j]);
            float2 im = funpack2(aI[j]);
            size_t base = ((size_t)(b*256 + y0 + 2*j) * 16 + ky) * 64 + c;
            G[base]            = make_float2(r.x, im.x);
            G[base + 16*64]    = make_float2(r.y, im.y);
        }
    }
}

// ---------------- fused: 1x1 conv + inv DFT along W + bias + relu (R15) ----------------
#define CMAD(oo, wd) \
    acc[oo][0]=ffma2(wd,h01.x,acc[oo][0]); acc[oo][1]=ffma2(wd,h01.y,acc[oo][1]); \
    acc[oo][2]=ffma2(wd,h23.x,acc[oo][2]); acc[oo][3]=ffma2(wd,h23.y,acc[oo][3]);
#define IMAD2(oo, gxd, gyd) \
    acc[oo][0]=ffma2(gxd,A01.x,acc[oo][0]); acc[oo][0]=ffma2(gyd,B01.x,acc[oo][0]); \
    acc[oo][1]=ffma2(gxd,A01.y,acc[oo][1]); acc[oo][1]=ffma2(gyd,B01.y,acc[oo][1]); \
    acc[oo][2]=ffma2(gxd,A23.x,acc[oo][2]); acc[oo][2]=ffma2(gyd,B23.x,acc[oo][2]); \
    acc[oo][3]=ffma2(gxd,A23.y,acc[oo][3]); acc[oo][3]=ffma2(gyd,B23.y,acc[oo][3]);

__global__ __launch_bounds__(256) void kfused(
        const float* __restrict__ hin, const float2* __restrict__ G,
        const float* __restrict__ ww, const float* __restrict__ wb,
        float* __restrict__ hout){
    extern __shared__ __align__(16) float dsm2[];
    float*  sh = dsm2;                             // [64 i][132]
    float*  sA = sh + 64*132;                      // [16 ky][132]
    float*  sB = sA + 16*132;                      // [16 ky][132]
    float*  sw = sB + 16*132;                      // [64 i][66]
    float2* sg = (float2*)(sw + 64*66);            // [16 ky][66]
    float*  sb = (float*)(sg + 16*66);             // [64]
    int tid = threadIdx.x;                         // 256
    int xh = blockIdx.x & 1;
    int y  = (blockIdx.x >> 1) & 255;
    int b  = blockIdx.x >> 9;
    int xg2 = xh * 128;

    {
        const float2* Gb = G + ((size_t)(b*256) + y) * 1024;
        #pragma unroll
        for (int k = 0; k < 4; ++k){
            int idx = tid + k*256;
            int ky = idx >> 6, o = idx & 63;
            cpa8(&sg[ky*66 + o], &Gb[idx]);
        }
        #pragma unroll
        for (int k = 0; k < 2; ++k){
            int idx = tid + k*256;
            int ky = idx >> 5, xq = (idx & 31)*4;
            if (ky < 16){
                cpa16(&sA[ky*132 + xq], &g_ic[ky*256 + xg2 + xq]);
                cpa16(&sB[ky*132 + xq], &g_is[ky*256 + xg2 + xq]);
            }
        }
        CP_COMMIT();
    }
    {
        const float* hb = hin + ((size_t)(b*64)*256 + y)*256 + xg2;
        #pragma unroll
        for (int k = 0; k < 8; ++k){
            int idx = tid + k*256;
            int i = idx >> 5, xq = (idx & 31)*4;
            cpa16(&sh[i*132 + xq], &hb[(size_t)i*65536 + xq]);
        }
        CP_COMMIT();
    }
    #pragma unroll
    for (int k = 0; k < 16; ++k){
        int idx = tid + k*256;
        int i = idx & 63, o = idx >> 6;
        sw[i*66 + o] = ww[idx];
    }
    if (tid < 64) sb[tid] = wb[tid];
    cp_wait<1>();
    __syncthreads();

    int w = tid >> 5, l = tid & 31;
    int o0 = ((w & 1)*8 + (l >> 2)) * 4;
    int x0 = ((w >> 1)*4 + (l & 3)) * 8;
    u64 acc[4][4];
    {
        float4 bv = *(const float4*)&sb[o0];
        u64 b0 = fpack2(bv.x, bv.x), b1 = fpack2(bv.y, bv.y);
        u64 b2 = fpack2(bv.z, bv.z), b3 = fpack2(bv.w, bv.w);
        #pragma unroll
        for (int p = 0; p < 4; ++p){ acc[0][p]=b0; acc[1][p]=b1; acc[2][p]=b2; acc[3][p]=b3; }
    }
    #pragma unroll 4
    for (int ky = 0; ky < 16; ++ky){
        ulonglong2 A01 = *(const ulonglong2*)&sA[ky*132 + x0];
        ulonglong2 A23 = *(const ulonglong2*)&sA[ky*132 + x0 + 4];
        ulonglong2 B01 = *(const ulonglong2*)&sB[ky*132 + x0];
        ulonglong2 B23 = *(const ulonglong2*)&sB[ky*132 + x0 + 4];
        float2 ga = sg[ky*66 + o0],     gb2 = sg[ky*66 + o0 + 1];
        float2 gc = sg[ky*66 + o0 + 2], gd  = sg[ky*66 + o0 + 3];
        u64 gx0 = fpack2(ga.x, ga.x),  gy0 = fpack2(ga.y, ga.y);
        u64 gx1 = fpack2(gb2.x, gb2.x), gy1 = fpack2(gb2.y, gb2.y);
        u64 gx2 = fpack2(gc.x, gc.x),  gy2 = fpack2(gc.y, gc.y);
        u64 gx3 = fpack2(gd.x, gd.x),  gy3 = fpack2(gd.y, gd.y);
        IMAD2(0, gx0, gy0) IMAD2(1, gx1, gy1) IMAD2(2, gx2, gy2) IMAD2(3, gx3, gy3)
    }
    cp_wait<0>();
    __syncthreads();
    #pragma unroll 4
    for (int i = 0; i < 64; ++i){
        ulonglong2 h01 = *(const ulonglong2*)&sh[i*132 + x0];
        ulonglong2 h23 = *(const ulonglong2*)&sh[i*132 + x0 + 4];
        float2 wab = *(const float2*)&sw[i*66 + o0];
        float2 wcd = *(const float2*)&sw[i*66 + o0 + 2];
        u64 w0 = fpack2(wab.x, wab.x), w1 = fpack2(wab.y, wab.y);
        u64 w2 = fpack2(wcd.x, wcd.x), w3 = fpack2(wcd.y, wcd.y);
        CMAD(0, w0) CMAD(1, w1) CMAD(2, w2) CMAD(3, w3)
    }
    float* ob = hout + ((size_t)(b*64 + o0)*256 + y)*256 + xg2 + x0;
    #pragma unroll
    for (int oo = 0; oo < 4; ++oo){
        float2 p0 = funpack2(acc[oo][0]), p1 = funpack2(acc[oo][1]);
        float2 p2 = funpack2(acc[oo][2]), p3 = funpack2(acc[oo][3]);
        float4 v0 = make_float4(fmaxf(p0.x,0.f), fmaxf(p0.y,0.f), fmaxf(p1.x,0.f), fmaxf(p1.y,0.f));
        float4 v1 = make_float4(fmaxf(p2.x,0.f), fmaxf(p2.y,0.f), fmaxf(p3.x,0.f), fmaxf(p3.y,0.f));
        *(float4*)&ob[(size_t)oo*65536]     = v0;
        *(float4*)&ob[(size_t)oo*65536 + 4] = v1;
    }
}

// ---------------- fused MLP head (R15) ----------------
#define HMAD(mm, wd) \
    acc[mm][0]=ffma2(wd,h01.x,acc[mm][0]); acc[mm][1]=ffma2(wd,h01.y,acc[mm][1]); \
    acc[mm][2]=ffma2(wd,h23.x,acc[mm][2]); acc[mm][3]=ffma2(wd,h23.y,acc[mm][3]);

__global__ __launch_bounds__(256) void khead(
        const float* __restrict__ hin,
        const float* __restrict__ w1, const float* __restrict__ b1,
        const float* __restrict__ w2, const float* __restrict__ b2,
        float* __restrict__ out){
    extern __shared__ __align__(16) float dsm3[];
    float* sh   = dsm3;                            // [64 c][68]
    float* sw1t = sh + 64*68;                      // [64 c][130]
    float* shid = sw1t + 64*130;                   // [128 m][68]
    float* sw2s = shid + 128*68;                   // [384]
    float* sb1s = sw2s + 384;                      // [128]
    int tid = threadIdx.x;                         // 256
    int xc = (blockIdx.x & 3) << 6;
    int y  = (blockIdx.x >> 2) & 255;
    int b  = blockIdx.x >> 10;

    {
        const float* hb = hin + ((size_t)(b*64)*256 + y)*256 + xc;
        #pragma unroll
        for (int k = 0; k < 4; ++k){
            int idx = tid + k*256;
            int c = idx >> 4, xq = (idx & 15)*4;
            cpa16(&sh[c*68 + xq], &hb[(size_t)c*65536 + xq]);
        }
        CP_COMMIT();
    }
    #pragma unroll
    for (int k = 0; k < 32; ++k){
        int idx = tid + k*256;
        int c = idx & 63, m = idx >> 6;
        sw1t[c*130 + m] = w1[idx];
    }
    for (int idx = tid; idx < 384; idx += 256) sw2s[idx] = w2[idx];
    if (tid < 128) sb1s[tid] = b1[tid];
    cp_wait<0>();
    __syncthreads();

    int w = tid >> 5, l = tid & 31;
    int m0 = ((w & 3)*8 + (l >> 2)) * 4;
    int x0 = ((w >> 2)*4 + (l & 3)) * 8;
    u64 acc[4][4];
    {
        float4 bv = *(const float4*)&sb1s[m0];
        u64 b0v = fpack2(bv.x,bv.x), b1v = fpack2(bv.y,bv.y);
        u64 b2v = fpack2(bv.z,bv.z), b3v = fpack2(bv.w,bv.w);
        #pragma unroll
        for (int p = 0; p < 4; ++p){ acc[0][p]=b0v; acc[1][p]=b1v; acc[2][p]=b2v; acc[3][p]=b3v; }
    }
    #pragma unroll 4
    for (int c = 0; c < 64; ++c){
        ulonglong2 h01 = *(const ulonglong2*)&sh[c*68 + x0];
        ulonglong2 h23 = *(const ulonglong2*)&sh[c*68 + x0 + 4];
        float2 wab = *(const float2*)&sw1t[c*130 + m0];
        float2 wcd = *(const float2*)&sw1t[c*130 + m0 + 2];
        u64 w0 = fpack2(wab.x,wab.x), w1d = fpack2(wab.y,wab.y);
        u64 w2d = fpack2(wcd.x,wcd.x), w3d = fpack2(wcd.y,wcd.y);
        HMAD(0, w0) HMAD(1, w1d) HMAD(2, w2d) HMAD(3, w3d)
    }
    #pragma unroll
    for (int mm = 0; mm < 4; ++mm){
        float2 p0 = funpack2(acc[mm][0]), p1 = funpack2(acc[mm][1]);
        float2 p2 = funpack2(acc[mm][2]), p3 = funpack2(acc[mm][3]);
        float4 v0 = make_float4(fmaxf(p0.x,0.f), fmaxf(p0.y,0.f), fmaxf(p1.x,0.f), fmaxf(p1.y,0.f));
        float4 v1 = make_float4(fmaxf(p2.x,0.f), fmaxf(p2.y,0.f), fmaxf(p3.x,0.f), fmaxf(p3.y,0.f));
        *(float4*)&shid[(m0+mm)*68 + x0]     = v0;
        *(float4*)&shid[(m0+mm)*68 + x0 + 4] = v1;
    }
    __syncthreads();
    if (tid < 192){
        int o = tid >> 6, xl = tid & 63;
        float a0 = b2[o], a1 = 0.f;
        #pragma unroll 8
        for (int m = 0; m < 64; ++m){
            a0 = fmaf(shid[m*68 + xl],        sw2s[o*128 + m],      a0);
            a1 = fmaf(shid[(m + 64)*68 + xl], sw2s[o*128 + m + 64], a1);
        }
        out[((size_t)(b*3 + o)*256 + y)*256 + xc + xl] = a0 + a1;
    }
}

// ---------------- host ----------------
extern "C" void kernel_launch(void* const* d_in, const int* in_sizes, int n_in,
                              void* d_out, int out_size) {
    const float* x       = (const float*)d_in[0];
    const float* fc0_w   = (const float*)d_in[1];
    const float* fc0_b   = (const float*)d_in[2];
    const float* spec_re = (const float*)d_in[3];
    const float* spec_im = (const float*)d_in[4];
    const float* w_w     = (const float*)d_in[5];
    const float* w_b     = (const float*)d_in[6];
    const float* fc1_w   = (const float*)d_in[7];
    const float* fc1_b   = (const float*)d_in[8];
    const float* fc2_w   = (const float*)d_in[9];
    const float* fc2_b   = (const float*)d_in[10];

    float  *h0, *h1;
    float2 *f1, *mo, *mx, *G, *wt;
    cudaGetSymbolAddress((void**)&h0, g_h0);
    cudaGetSymbolAddress((void**)&h1, g_h1);
    cudaGetSymbolAddress((void**)&f1, g_f1);
    cudaGetSymbolAddress((void**)&mo, g_modes);
    cudaGetSymbolAddress((void**)&mx, g_mixed);
    cudaGetSymbolAddress((void**)&G,  g_G);
    cudaGetSymbolAddress((void**)&wt, g_wt);

    const int SM1 = (128*36 + 128*40 + 128*36 + 128*36 + 2*8*260) * 4;          // 92416
    const int SMF = (2*16*266)*4 + (2*16*132)*8;                                // 67840
    const int SM2 = (64*132 + 32*132 + 64*66)*4 + 16*66*8 + 64*4;               // 76288
    const int SM3 = (64*68 + 64*130 + 128*68)*4 + 384*4 + 128*4;                // 87552
    cudaFuncSetAttribute(kfwd1,  cudaFuncAttributeMaxDynamicSharedMemorySize, SM1);
    cudaFuncSetAttribute(kfwd2,  cudaFuncAttributeMaxDynamicSharedMemorySize, SMF);
    cudaFuncSetAttribute(kfused, cudaFuncAttributeMaxDynamicSharedMemorySize, SM2);
    cudaFuncSetAttribute(khead,  cudaFuncAttributeMaxDynamicSharedMemorySize, SM3);

    kprep<<<16, 256>>>();
    ktw<<<16384, 256>>>(spec_re, spec_im);
    kfc0<<<32768, 256>>>(x, fc0_w, fc0_b, h0);

    float* hin = h0;
    float* hout = h1;
    for (int d = 0; d < NDEPTH; ++d) {
        kfwd1<<<1024, 256, SM1>>>(hin, f1);
        kfwd2<<<512, 256, SMF>>>(f1, mo);
        kmix<<<256, 256>>>(mo, wt + (size_t)d * 256 * 4096, mx);
        kinv1<<<256, 256>>>(mx, G);
        kfused<<<4096, 256, SM2>>>(hin, G, w_w + d * 4096, w_b + d * 64, hout);
        float* t = hin; hin = hout; hout = t;
    }
    khead<<<8192, 256, SM3>>>(hin, fc1_w, fc1_b, fc2_w, fc2_b, (float*)d_out);
}

// round 17
// speedup vs baseline: 1.4057x; 1.0423x over previous
#include <cuda_runtime.h>

#define NDEPTH 4
typedef unsigned long long u64;

__device__ __forceinline__ u64 ffma2(u64 a, u64 b, u64 c){
    u64 d; asm("fma.rn.f32x2 %0, %1, %2, %3;" : "=l"(d) : "l"(a), "l"(b), "l"(c)); return d;
}
__device__ __forceinline__ u64 fadd2(u64 a, u64 b){
    u64 d; asm("add.rn.f32x2 %0, %1, %2;" : "=l"(d) : "l"(a), "l"(b)); return d;
}
__device__ __forceinline__ u64 fpack2(float x, float y){
    u64 d; asm("mov.b64 %0, {%1, %2};" : "=l"(d) : "f"(x), "f"(y)); return d;
}
__device__ __forceinline__ float2 funpack2(u64 a){
    float x, y; asm("mov.b64 {%0, %1}, %2;" : "=f"(x), "=f"(y) : "l"(a)); return make_float2(x, y);
}
__device__ __forceinline__ void cpa16(void* dst_smem, const void* src){
    unsigned sa = (unsigned)__cvta_generic_to_shared(dst_smem);
    asm volatile("cp.async.cg.shared.global [%0], [%1], 16;" :: "r"(sa), "l"(src));
}
__device__ __forceinline__ void cpa8(void* dst_smem, const void* src){
    unsigned sa = (unsigned)__cvta_generic_to_shared(dst_smem);
    asm volatile("cp.async.ca.shared.global [%0], [%1], 8;" :: "r"(sa), "l"(src));
}
#define CP_COMMIT() asm volatile("cp.async.commit_group;")
template<int N> __device__ __forceinline__ void cp_wait(){
    asm volatile("cp.async.wait_group %0;" :: "n"(N));
}

// ---------------- scratch (device globals) ----------------
__device__ float  g_h0[8*64*65536 + 64];
__device__ float  g_h1[8*64*65536 + 64];
__device__ float2 g_f1[8*64*256*16];
__device__ float2 g_modes[8*64*256];
__device__ float2 g_mixed[8*64*256];               // mixedT [b][ky][kx][o]
__device__ float2 g_G[8*256*16*64];                // [b][y][ky][c]
__device__ float2 g_wt[NDEPTH*256*64*64];          // [d][m][i][o]
__device__ float  g_ec[16*256], g_es[16*256];      // fwd: cos, -sin
__device__ float  g_ic[16*256], g_is[16*256];      // inv-W scaled tables
__device__ u64    g_e2c[16*128], g_e2s[16*128];    // y-paired (cos,cos)/(sin,sin)
__device__ float  g_w1t[64*128];                   // fc1 w transposed [c][m]

// ---------------- prep: DFT tables + w1 transpose ----------------
__global__ void kprep(const float* __restrict__ w1){
    int idx = blockIdx.x * 256 + threadIdx.x;      // grid 32 -> 8192
    if (idx < 4096){
        int x = idx & 255, ky = idx >> 8;
        float ang = 6.283185307179586f * (float)((ky * x) & 255) / 256.f;
        float c = cosf(ang), s = sinf(ang);
        g_ec[idx] = c; g_es[idx] = -s;
        const float sc = 1.f / 65536.f;
        g_ic[idx] = (ky == 0) ? sc : 2.f * sc * c;
        g_is[idx] = (ky == 0) ? 0.f : -2.f * sc * s;
    }
    if (idx < 2048){                               // y-paired tables
        int kx = idx >> 7, yp = idx & 127;
        float a0 = 6.283185307179586f * (float)((kx * (2*yp))     & 255) / 256.f;
        float a1 = 6.283185307179586f * (float)((kx * (2*yp + 1)) & 255) / 256.f;
        g_e2c[idx] = fpack2(cosf(a0), cosf(a1));
        g_e2s[idx] = fpack2(sinf(a0), sinf(a1));
    }
    {                                              // w1t[c][m] = w1[m][c]
        int c = idx >> 7, m = idx & 127;
        g_w1t[idx] = w1[m*64 + c];
    }
}

// ---------------- spectral weight transpose ----------------
__global__ void ktw(const float* __restrict__ wre, const float* __restrict__ wim){
    int idx = blockIdx.x * 256 + threadIdx.x;
    int ky = idx & 15, kx = (idx >> 4) & 15, o = (idx >> 8) & 63, i = (idx >> 14) & 63, d = idx >> 20;
    int m = kx * 16 + ky;
    g_wt[((d * 256 + m) * 64 + i) * 64 + o] = make_float2(wre[idx], wim[idx]);
}

// ---------------- fc0 ----------------
__global__ void kfc0(const float* __restrict__ x, const float* __restrict__ w,
                     const float* __restrict__ bv, float* __restrict__ out){
    int idx = blockIdx.x * 256 + threadIdx.x;
    int p4 = idx & 16383;
    int c  = (idx >> 14) & 63;
    int b  = idx >> 20;
    const float* xb = x + (size_t)b * 3 * 65536 + p4 * 4;
    float4 a0 = *(const float4*)&xb[0];
    float4 a1 = *(const float4*)&xb[65536];
    float4 a2 = *(const float4*)&xb[131072];
    float w0 = w[c*3], w1 = w[c*3+1], w2 = w[c*3+2], bb = bv[c];
    float4 r;
    r.x = bb + a0.x*w0 + a1.x*w1 + a2.x*w2;
    r.y = bb + a0.y*w0 + a1.y*w1 + a2.y*w2;
    r.z = bb + a0.z*w0 + a1.z*w1 + a2.z*w2;
    r.w = bb + a0.w*w0 + a1.w*w1 + a2.w*w2;
    *(float4*)&out[(size_t)idx * 4] = r;
}

// ---------------- fwd DFT along W: real-input symmetry (R13/R15) ----------------
__global__ __launch_bounds__(256) void kfwd1(const float* __restrict__ hin, float2* __restrict__ f1){
    extern __shared__ __align__(16) float dsm1[];
    float* sv  = dsm1;                              // [128][36]
    float* su  = sv + 128*36;                       // [128][40]
    float* ss  = su + 128*40;                       // [128][36]
    float* sd  = ss + 128*36;                       // [128][36]
    float* twc = sd + 128*36;                       // [8][260]
    float* tws = twc + 8*260;
    int tid = threadIdx.x;
    size_t rowbase = (size_t)blockIdx.x * 128;
    int rg = tid >> 3, kg = tid & 7;

    {
        const int k = 0;
        #pragma unroll
        for (int t = 0; t < 4; ++t){
            int idx = tid + t*256;
            int row = idx >> 3, q = idx & 7;
            cpa16(&sv[row*36 + q*4], &hin[(rowbase + row)*256 + k*32 + q*4]);
        }
        #pragma unroll
        for (int t = 0; t < 4; ++t){
            int idx = tid + t*256;
            int row = idx >> 3, q = idx & 7;
            cpa16(&su[row*40 + q*4], &hin[(rowbase + row)*256 + 224 - k*32 + q*4]);
        }
        if (tid < 128)
            cpa16(&su[tid*40 + 32], &hin[(rowbase + tid)*256 + 256 - k*32]);
        CP_COMMIT();
    }
    #pragma unroll
    for (int t = 0; t < 8; ++t){
        int idx = tid + t*256;
        int x = idx & 127, e2 = (idx >> 7) & 1, g = idx >> 8;
        twc[g*260 + e2*128 + x] = g_ec[(g*2 + e2)*256 + x];
        tws[g*260 + e2*128 + x] = g_es[(g*2 + e2)*256 + x];
    }

    u64 ar[4][2], ai[4][2];
    #pragma unroll
    for (int j = 0; j < 4; ++j){ ar[j][0]=ar[j][1]=ai[j][0]=ai[j][1]=0ull; }
    const u64 NEG1 = fpack2(-1.f, -1.f);

    for (int k = 0; k < 4; ++k){
        cp_wait<0>();
        __syncthreads();
        #pragma unroll
        for (int t = 0; t < 8; ++t){
            int idx = tid + t*256;
            int row = idx >> 4, xl = (idx & 15)*2;
            u64 vv = *(const u64*)&sv[row*36 + xl];
            float p0 = (k == 0 && xl == 0) ? 0.f : su[row*40 + 32 - xl];
            float p1 = su[row*40 + 31 - xl];
            u64 pp = fpack2(p0, p1);
            *(u64*)&ss[row*36 + xl] = fadd2(vv, pp);
            *(u64*)&sd[row*36 + xl] = ffma2(pp, NEG1, vv);
        }
        __syncthreads();
        if (k < 3){
            int kn = k + 1;
            #pragma unroll
            for (int t = 0; t < 4; ++t){
                int idx = tid + t*256;
                int row = idx >> 3, q = idx & 7;
                cpa16(&sv[row*36 + q*4], &hin[(rowbase + row)*256 + kn*32 + q*4]);
            }
            #pragma unroll
            for (int t = 0; t < 4; ++t){
                int idx = tid + t*256;
                int row = idx >> 3, q = idx & 7;
                cpa16(&su[row*40 + q*4], &hin[(rowbase + row)*256 + 224 - kn*32 + q*4]);
            }
            if (tid < 128)
                cpa16(&su[tid*40 + 32], &hin[(rowbase + tid)*256 + 256 - kn*32]);
            CP_COMMIT();
        }
        #pragma unroll 4
        for (int j4 = 0; j4 < 32; j4 += 4){
            int xg = k*32 + j4;
            ulonglong2 c0 = *(const ulonglong2*)&twc[kg*260 + xg];
            ulonglong2 c1 = *(const ulonglong2*)&twc[kg*260 + 128 + xg];
            ulonglong2 s0 = *(const ulonglong2*)&tws[kg*260 + xg];
            ulonglong2 s1 = *(const ulonglong2*)&tws[kg*260 + 128 + xg];
            #pragma unroll
            for (int j = 0; j < 4; ++j){
                int r = rg + 32*j;
                ulonglong2 sp = *(const ulonglong2*)&ss[r*36 + j4];
                ulonglong2 dp = *(const ulonglong2*)&sd[r*36 + j4];
                ar[j][0] = ffma2(sp.x, c0.x, ar[j][0]);
                ar[j][0] = ffma2(sp.y, c0.y, ar[j][0]);
                ar[j][1] = ffma2(sp.x, c1.x, ar[j][1]);
                ar[j][1] = ffma2(sp.y, c1.y, ar[j][1]);
                ai[j][0] = ffma2(dp.x, s0.x, ai[j][0]);
                ai[j][0] = ffma2(dp.y, s0.y, ai[j][0]);
                ai[j][1] = ffma2(dp.x, s1.x, ai[j][1]);
                ai[j][1] = ffma2(dp.y, s1.y, ai[j][1]);
            }
        }
        __syncthreads();
    }
    #pragma unroll
    for (int j = 0; j < 4; ++j){
        int r = rg + 32*j;
        float u0 = su[r*40];
        float2 re0 = funpack2(ar[j][0]), im0 = funpack2(ai[j][0]);
        float2 re1 = funpack2(ar[j][1]), im1 = funpack2(ai[j][1]);
        float4 o = make_float4(re0.x + re0.y + u0, im0.x + im0.y,
                               re1.x + re1.y - u0, im1.x + im1.y);
        *(float4*)&f1[(rowbase + r)*16 + kg*2] = o;
    }
}

// ---------------- fwd DFT along H: f32x2 register-tiled (R15) ----------------
__global__ __launch_bounds__(256) void kfwd2(const float2* __restrict__ f1, float2* __restrict__ modes){
    extern __shared__ __align__(16) float dsmf[];
    float* sfx  = dsmf;                            // [16][266]
    float* sfy  = sfx + 16*266;                    // [16][266]
    u64*   tw2c = (u64*)(sfy + 16*266);            // [16][132]
    u64*   tw2s = tw2c + 16*132;
    int tid = threadIdx.x;                         // 256
    int bc = blockIdx.x;

    #pragma unroll
    for (int t = 0; t < 4; ++t){
        int idx = tid + t*256;
        int kx = idx >> 6, yq = (idx & 63)*2;
        cpa16(&tw2c[kx*132 + yq], &g_e2c[kx*128 + yq]);
        cpa16(&tw2s[kx*132 + yq], &g_e2s[kx*128 + yq]);
    }
    CP_COMMIT();
    {
        const float4* src = (const float4*)(f1 + (size_t)bc * 4096);
        #pragma unroll
        for (int t = 0; t < 8; ++t){
            int idx = tid + t*256;
            int y = idx >> 3, kyq = idx & 7;
            float4 v = src[idx];
            sfx[(2*kyq)*266 + y]     = v.x;
            sfy[(2*kyq)*266 + y]     = v.y;
            sfx[(2*kyq + 1)*266 + y] = v.z;
            sfy[(2*kyq + 1)*266 + y] = v.w;
        }
    }
    cp_wait<0>();
    __syncthreads();

    int kx = tid >> 4, ky = tid & 15;
    u64 A = 0ull, B = 0ull, C = 0ull, D = 0ull;
    const float* fx = &sfx[ky*266];
    const float* fy = &sfy[ky*266];
    const u64* tc = &tw2c[kx*132];
    const u64* ts = &tw2s[kx*132];
    #pragma unroll 8
    for (int i = 0; i < 64; ++i){
        u64 vx0 = *(const u64*)&fx[4*i];
        u64 vx1 = *(const u64*)&fx[4*i + 2];
        u64 vy0 = *(const u64*)&fy[4*i];
        u64 vy1 = *(const u64*)&fy[4*i + 2];
        ulonglong2 c2 = *(const ulonglong2*)&tc[2*i];
        ulonglong2 s2 = *(const ulonglong2*)&ts[2*i];
        A = ffma2(vx0, c2.x, A); A = ffma2(vx1, c2.y, A);
        B = ffma2(vy0, s2.x, B); B = ffma2(vy1, s2.y, B);
        C = ffma2(vy0, c2.x, C); C = ffma2(vy1, c2.y, C);
        D = ffma2(vx0, s2.x, D); D = ffma2(vx1, s2.y, D);
    }
    float2 a = funpack2(A), b2 = funpack2(B), c = funpack2(C), d = funpack2(D);
    modes[bc*256 + tid] = make_float2(a.x + a.y + b2.x + b2.y,
                                      c.x + c.y - d.x - d.y);
}

// ---------------- mode mixing -> mixedT [b][ky][kx][o] ----------------
__global__ void kmix(const float2* __restrict__ modes, const float2* __restrict__ wt,
                     float2* __restrict__ mixedT){
    __shared__ float2 swt[4096];
    __shared__ float2 sin_[512];
    int tid = threadIdx.x, m = blockIdx.x;
    int ky = m & 15, kx = m >> 4;
    const float2* wsrc = wt + (size_t)m * 4096;
    for (int idx = tid; idx < 4096; idx += 256) swt[idx] = wsrc[idx];
    for (int idx = tid; idx < 512; idx += 256){
        int b = idx >> 6, i = idx & 63;
        sin_[idx] = modes[(b*64 + i)*256 + m];
    }
    __syncthreads();
    int o = tid & 63;
    for (int half = 0; half < 2; ++half){
        int b = (tid >> 6) + half * 4;
        float re = 0.f, im = 0.f;
        #pragma unroll 8
        for (int i = 0; i < 64; ++i){
            float2 a = sin_[b*64 + i];
            float2 wv = swt[i*64 + o];
            re += a.x*wv.x - a.y*wv.y;
            im += a.x*wv.y + a.y*wv.x;
        }
        mixedT[((b*16 + ky)*16 + kx)*64 + o] = make_float2(re, im);
    }
}

// ---------------- inv DFT along H (R16) ----------------
__global__ __launch_bounds__(256) void kinv1(const float2* __restrict__ mixedT, float2* __restrict__ G){
    __shared__ __align__(16) u64 twc[16*68];
    __shared__ __align__(16) u64 tws[16*68];
    int tid = threadIdx.x;                         // 256
    int ky = blockIdx.x & 15, yh = (blockIdx.x >> 4) & 1, b = blockIdx.x >> 5;

    #pragma unroll
    for (int t = 0; t < 4; ++t){
        int idx = tid + t*256;
        int kx = idx >> 6, p = idx & 63;
        twc[kx*68 + p] = g_e2c[kx*128 + yh*64 + p];
        tws[kx*68 + p] = g_e2s[kx*128 + yh*64 + p];
    }
    int yg = tid >> 6, c = tid & 63;
    float mr[16], mi[16];
    {
        const float2* msrc = mixedT + (size_t)(b*16 + ky) * 1024 + c;
        #pragma unroll
        for (int kx = 0; kx < 16; ++kx){
            float2 v = msrc[kx*64];
            mr[kx] = v.x; mi[kx] = v.y;
        }
    }
    __syncthreads();

    int pbase = yg*16;
    #pragma unroll
    for (int ch = 0; ch < 4; ++ch){
        int p0 = pbase + ch*4;
        u64 aR[4] = {0ull,0ull,0ull,0ull};
        u64 aI[4] = {0ull,0ull,0ull,0ull};
        #pragma unroll
        for (int kx = 0; kx < 16; ++kx){
            ulonglong2 cA = *(const ulonglong2*)&twc[kx*68 + p0];
            ulonglong2 cB = *(const ulonglong2*)&twc[kx*68 + p0 + 2];
            ulonglong2 sA = *(const ulonglong2*)&tws[kx*68 + p0];
            ulonglong2 sB = *(const ulonglong2*)&tws[kx*68 + p0 + 2];
            u64 mrd = fpack2(mr[kx], mr[kx]);
            u64 mid = fpack2(mi[kx], mi[kx]);
            u64 nid = fpack2(-mi[kx], -mi[kx]);
            aR[0] = ffma2(mrd, cA.x, aR[0]); aR[0] = ffma2(nid, sA.x, aR[0]);
            aR[1] = ffma2(mrd, cA.y, aR[1]); aR[1] = ffma2(nid, sA.y, aR[1]);
            aR[2] = ffma2(mrd, cB.x, aR[2]); aR[2] = ffma2(nid, sB.x, aR[2]);
            aR[3] = ffma2(mrd, cB.y, aR[3]); aR[3] = ffma2(nid, sB.y, aR[3]);
            aI[0] = ffma2(mrd, sA.x, aI[0]); aI[0] = ffma2(mid, cA.x, aI[0]);
            aI[1] = ffma2(mrd, sA.y, aI[1]); aI[1] = ffma2(mid, cA.y, aI[1]);
            aI[2] = ffma2(mrd, sB.x, aI[2]); aI[2] = ffma2(mid, cB.x, aI[2]);
            aI[3] = ffma2(mrd, sB.y, aI[3]); aI[3] = ffma2(mid, cB.y, aI[3]);
        }
        int y0 = yh*128 + p0*2;
        #pragma unroll
        for (int j = 0; j < 4; ++j){
            float2 r = funpack2(aR[j]);
            float2 im = funpack2(aI[j]);
            size_t base = ((size_t)(b*256 + y0 + 2*j) * 16 + ky) * 64 + c;
            G[base]         = make_float2(r.x, im.x);
            G[base + 16*64] = make_float2(r.y, im.y);
        }
    }
}

// ---------------- fused: 1x1 conv + inv DFT along W + bias + relu ----------------
// strides 128 (conflict-free: warp reads are same-row), smem 74752 -> 3 blocks/SM
#define CMAD(oo, wd) \
    acc[oo][0]=ffma2(wd,h01.x,acc[oo][0]); acc[oo][1]=ffma2(wd,h01.y,acc[oo][1]); \
    acc[oo][2]=ffma2(wd,h23.x,acc[oo][2]); acc[oo][3]=ffma2(wd,h23.y,acc[oo][3]);
#define IMAD2(oo, gxd, gyd) \
    acc[oo][0]=ffma2(gxd,A01.x,acc[oo][0]); acc[oo][0]=ffma2(gyd,B01.x,acc[oo][0]); \
    acc[oo][1]=ffma2(gxd,A01.y,acc[oo][1]); acc[oo][1]=ffma2(gyd,B01.y,acc[oo][1]); \
    acc[oo][2]=ffma2(gxd,A23.x,acc[oo][2]); acc[oo][2]=ffma2(gyd,B23.x,acc[oo][2]); \
    acc[oo][3]=ffma2(gxd,A23.y,acc[oo][3]); acc[oo][3]=ffma2(gyd,B23.y,acc[oo][3]);
#define CONVI(i) { \
    ulonglong2 h01 = *(const ulonglong2*)&sh[(i)*128 + x0]; \
    ulonglong2 h23 = *(const ulonglong2*)&sh[(i)*128 + x0 + 4]; \
    float2 wab = *(const float2*)&sw[(i)*66 + o0]; \
    float2 wcd = *(const float2*)&sw[(i)*66 + o0 + 2]; \
    u64 w0 = fpack2(wab.x, wab.x), w1 = fpack2(wab.y, wab.y); \
    u64 w2 = fpack2(wcd.x, wcd.x), w3 = fpack2(wcd.y, wcd.y); \
    CMAD(0, w0) CMAD(1, w1) CMAD(2, w2) CMAD(3, w3) }

__global__ __launch_bounds__(256) void kfused(
        const float* __restrict__ hin, const float2* __restrict__ G,
        const float* __restrict__ ww, const float* __restrict__ wb,
        float* __restrict__ hout){
    extern __shared__ __align__(16) float dsm2[];
    float*  sh = dsm2;                             // [64 i][128]
    float*  sA = sh + 64*128;                      // [16 ky][128]
    float*  sB = sA + 16*128;                      // [16 ky][128]
    float*  sw = sB + 16*128;                      // [64 i][66]
    float2* sg = (float2*)(sw + 64*66);            // [16 ky][66]
    float*  sb = (float*)(sg + 16*66);             // [64]
    int tid = threadIdx.x;                         // 256
    int xh = blockIdx.x & 1;
    int y  = (blockIdx.x >> 1) & 255;
    int b  = blockIdx.x >> 9;
    int xg2 = xh * 128;

    // group 0: sg + sA + sB
    {
        const float2* Gb = G + ((size_t)(b*256) + y) * 1024;
        #pragma unroll
        for (int k = 0; k < 4; ++k){
            int idx = tid + k*256;
            int ky = idx >> 6, o = idx & 63;
            cpa8(&sg[ky*66 + o], &Gb[idx]);
        }
        #pragma unroll
        for (int k = 0; k < 2; ++k){
            int idx = tid + k*256;
            int ky = idx >> 5, xq = (idx & 31)*4;
            if (ky < 16){
                cpa16(&sA[ky*128 + xq], &g_ic[ky*256 + xg2 + xq]);
                cpa16(&sB[ky*128 + xq], &g_is[ky*256 + xg2 + xq]);
            }
        }
        CP_COMMIT();
    }
    // group 1: h channels 0-31; group 2: h channels 32-63
    {
        const float* hb = hin + ((size_t)(b*64)*256 + y)*256 + xg2;
        #pragma unroll
        for (int k = 0; k < 4; ++k){
            int idx = tid + k*256;
            int i = idx >> 5, xq = (idx & 31)*4;
            cpa16(&sh[i*128 + xq], &hb[(size_t)i*65536 + xq]);
        }
        CP_COMMIT();
        #pragma unroll
        for (int k = 4; k < 8; ++k){
            int idx = tid + k*256;
            int i = idx >> 5, xq = (idx & 31)*4;
            cpa16(&sh[i*128 + xq], &hb[(size_t)i*65536 + xq]);
        }
        CP_COMMIT();
    }
    #pragma unroll
    for (int k = 0; k < 16; ++k){
        int idx = tid + k*256;
        int i = idx & 63, o = idx >> 6;
        sw[i*66 + o] = ww[idx];
    }
    if (tid < 64) sb[tid] = wb[tid];
    cp_wait<2>();                                  // group0 done
    __syncthreads();

    int w = tid >> 5, l = tid & 31;
    int o0 = ((w & 1)*8 + (l >> 2)) * 4;
    int x0 = ((w >> 1)*4 + (l & 3)) * 8;
    u64 acc[4][4];
    {
        float4 bv = *(const float4*)&sb[o0];
        u64 b0 = fpack2(bv.x, bv.x), b1 = fpack2(bv.y, bv.y);
        u64 b2 = fpack2(bv.z, bv.z), b3 = fpack2(bv.w, bv.w);
        #pragma unroll
        for (int p = 0; p < 4; ++p){ acc[0][p]=b0; acc[1][p]=b1; acc[2][p]=b2; acc[3][p]=b3; }
    }
    // inv-DFT (overlaps in-flight h groups)
    #pragma unroll 4
    for (int ky = 0; ky < 16; ++ky){
        ulonglong2 A01 = *(const ulonglong2*)&sA[ky*128 + x0];
        ulonglong2 A23 = *(const ulonglong2*)&sA[ky*128 + x0 + 4];
        ulonglong2 B01 = *(const ulonglong2*)&sB[ky*128 + x0];
        ulonglong2 B23 = *(const ulonglong2*)&sB[ky*128 + x0 + 4];
        float2 ga = sg[ky*66 + o0],     gb2 = sg[ky*66 + o0 + 1];
        float2 gc = sg[ky*66 + o0 + 2], gd  = sg[ky*66 + o0 + 3];
        u64 gx0 = fpack2(ga.x, ga.x),  gy0 = fpack2(ga.y, ga.y);
        u64 gx1 = fpack2(gb2.x, gb2.x), gy1 = fpack2(gb2.y, gb2.y);
        u64 gx2 = fpack2(gc.x, gc.x),  gy2 = fpack2(gc.y, gc.y);
        u64 gx3 = fpack2(gd.x, gd.x),  gy3 = fpack2(gd.y, gd.y);
        IMAD2(0, gx0, gy0) IMAD2(1, gx1, gy1) IMAD2(2, gx2, gy2) IMAD2(3, gx3, gy3)
    }
    cp_wait<1>();                                  // h 0-31 done
    __syncthreads();
    #pragma unroll 4
    for (int i = 0; i < 32; ++i) CONVI(i)
    cp_wait<0>();                                  // h 32-63 done
    __syncthreads();
    #pragma unroll 4
    for (int i = 32; i < 64; ++i) CONVI(i)

    float* ob = hout + ((size_t)(b*64 + o0)*256 + y)*256 + xg2 + x0;
    #pragma unroll
    for (int oo = 0; oo < 4; ++oo){
        float2 p0 = funpack2(acc[oo][0]), p1 = funpack2(acc[oo][1]);
        float2 p2 = funpack2(acc[oo][2]), p3 = funpack2(acc[oo][3]);
        float4 v0 = make_float4(fmaxf(p0.x,0.f), fmaxf(p0.y,0.f), fmaxf(p1.x,0.f), fmaxf(p1.y,0.f));
        float4 v1 = make_float4(fmaxf(p2.x,0.f), fmaxf(p2.y,0.f), fmaxf(p3.x,0.f), fmaxf(p3.y,0.f));
        *(float4*)&ob[(size_t)oo*65536]     = v0;
        *(float4*)&ob[(size_t)oo*65536 + 4] = v1;
    }
}

// ---------------- fused MLP head (w1^T via cp.async from g_w1t) ----------------
#define HMAD(mm, wd) \
    acc[mm][0]=ffma2(wd,h01.x,acc[mm][0]); acc[mm][1]=ffma2(wd,h01.y,acc[mm][1]); \
    acc[mm][2]=ffma2(wd,h23.x,acc[mm][2]); acc[mm][3]=ffma2(wd,h23.y,acc[mm][3]);

__global__ __launch_bounds__(256) void khead(
        const float* __restrict__ hin,
        const float* __restrict__ b1,
        const float* __restrict__ w2, const float* __restrict__ b2,
        float* __restrict__ out){
    extern __shared__ __align__(16) float dsm3[];
    float* sh   = dsm3;                            // [64 c][68]
    float* sw1t = sh + 64*68;                      // [64 c][132]
    float* shid = sw1t + 64*132;                   // [128 m][68]
    float* sw2s = shid + 128*68;                   // [384]
    float* sb1s = sw2s + 384;                      // [128]
    int tid = threadIdx.x;                         // 256
    int xc = (blockIdx.x & 3) << 6;
    int y  = (blockIdx.x >> 2) & 255;
    int b  = blockIdx.x >> 10;

    {
        const float* hb = hin + ((size_t)(b*64)*256 + y)*256 + xc;
        #pragma unroll
        for (int k = 0; k < 4; ++k){
            int idx = tid + k*256;
            int c = idx >> 4, xq = (idx & 15)*4;
            cpa16(&sh[c*68 + xq], &hb[(size_t)c*65536 + xq]);
        }
        #pragma unroll
        for (int k = 0; k < 8; ++k){
            int idx = tid + k*256;                 // 2048 float4
            int c = idx >> 5, mq = (idx & 31)*4;
            cpa16(&sw1t[c*132 + mq], &g_w1t[c*128 + mq]);
        }
        CP_COMMIT();
    }
    for (int idx = tid; idx < 384; idx += 256) sw2s[idx] = w2[idx];
    if (tid < 128) sb1s[tid] = b1[tid];
    cp_wait<0>();
    __syncthreads();

    int w = tid >> 5, l = tid & 31;
    int m0 = ((w & 3)*8 + (l >> 2)) * 4;
    int x0 = ((w >> 2)*4 + (l & 3)) * 8;
    u64 acc[4][4];
    {
        float4 bv = *(const float4*)&sb1s[m0];
        u64 b0v = fpack2(bv.x,bv.x), b1v = fpack2(bv.y,bv.y);
        u64 b2v = fpack2(bv.z,bv.z), b3v = fpack2(bv.w,bv.w);
        #pragma unroll
        for (int p = 0; p < 4; ++p){ acc[0][p]=b0v; acc[1][p]=b1v; acc[2][p]=b2v; acc[3][p]=b3v; }
    }
    #pragma unroll 4
    for (int c = 0; c < 64; ++c){
        ulonglong2 h01 = *(const ulonglong2*)&sh[c*68 + x0];
        ulonglong2 h23 = *(const ulonglong2*)&sh[c*68 + x0 + 4];
        float2 wab = *(const float2*)&sw1t[c*132 + m0];
        float2 wcd = *(const float2*)&sw1t[c*132 + m0 + 2];
        u64 w0 = fpack2(wab.x,wab.x), w1d = fpack2(wab.y,wab.y);
        u64 w2d = fpack2(wcd.x,wcd.x), w3d = fpack2(wcd.y,wcd.y);
        HMAD(0, w0) HMAD(1, w1d) HMAD(2, w2d) HMAD(3, w3d)
    }
    #pragma unroll
    for (int mm = 0; mm < 4; ++mm){
        float2 p0 = funpack2(acc[mm][0]), p1 = funpack2(acc[mm][1]);
        float2 p2 = funpack2(acc[mm][2]), p3 = funpack2(acc[mm][3]);
        float4 v0 = make_float4(fmaxf(p0.x,0.f), fmaxf(p0.y,0.f), fmaxf(p1.x,0.f), fmaxf(p1.y,0.f));
        float4 v1 = make_float4(fmaxf(p2.x,0.f), fmaxf(p2.y,0.f), fmaxf(p3.x,0.f), fmaxf(p3.y,0.f));
        *(float4*)&shid[(m0+mm)*68 + x0]     = v0;
        *(float4*)&shid[(m0+mm)*68 + x0 + 4] = v1;
    }
    __syncthreads();
    if (tid < 192){
        int o = tid >> 6, xl = tid & 63;
        float a0 = b2[o], a1 = 0.f;
        #pragma unroll 8
        for (int m = 0; m < 64; ++m){
            a0 = fmaf(shid[m*68 + xl],        sw2s[o*128 + m],      a0);
            a1 = fmaf(shid[(m + 64)*68 + xl], sw2s[o*128 + m + 64], a1);
        }
        out[((size_t)(b*3 + o)*256 + y)*256 + xc + xl] = a0 + a1;
    }
}

// ---------------- host ----------------
extern "C" void kernel_launch(void* const* d_in, const int* in_sizes, int n_in,
                              void* d_out, int out_size) {
    const float* x       = (const float*)d_in[0];
    const float* fc0_w   = (const float*)d_in[1];
    const float* fc0_b   = (const float*)d_in[2];
    const float* spec_re = (const float*)d_in[3];
    const float* spec_im = (const float*)d_in[4];
    const float* w_w     = (const float*)d_in[5];
    const float* w_b     = (const float*)d_in[6];
    const float* fc1_w   = (const float*)d_in[7];
    const float* fc1_b   = (const float*)d_in[8];
    const float* fc2_w   = (const float*)d_in[9];
    const float* fc2_b   = (const float*)d_in[10];

    float  *h0, *h1;
    float2 *f1, *mo, *mx, *G, *wt;
    cudaGetSymbolAddress((void**)&h0, g_h0);
    cudaGetSymbolAddress((void**)&h1, g_h1);
    cudaGetSymbolAddress((void**)&f1, g_f1);
    cudaGetSymbolAddress((void**)&mo, g_modes);
    cudaGetSymbolAddress((void**)&mx, g_mixed);
    cudaGetSymbolAddress((void**)&G,  g_G);
    cudaGetSymbolAddress((void**)&wt, g_wt);

    const int SM1 = (128*36 + 128*40 + 128*36 + 128*36 + 2*8*260) * 4;          // 92416
    const int SMF = (2*16*266)*4 + (2*16*132)*8;                                // 67840
    const int SM2 = (64*128 + 32*128 + 64*66)*4 + 16*66*8 + 64*4;               // 74752
    const int SM3 = (64*68 + 64*132 + 128*68)*4 + 384*4 + 128*4;                // 88064
    cudaFuncSetAttribute(kfwd1,  cudaFuncAttributeMaxDynamicSharedMemorySize, SM1);
    cudaFuncSetAttribute(kfwd2,  cudaFuncAttributeMaxDynamicSharedMemorySize, SMF);
    cudaFuncSetAttribute(kfused, cudaFuncAttributeMaxDynamicSharedMemorySize, SM2);
    cudaFuncSetAttribute(khead,  cudaFuncAttributeMaxDynamicSharedMemorySize, SM3);

    kprep<<<32, 256>>>(fc1_w);
    ktw<<<16384, 256>>>(spec_re, spec_im);
    kfc0<<<32768, 256>>>(x, fc0_w, fc0_b, h0);

    float* hin = h0;
    float* hout = h1;
    for (int d = 0; d < NDEPTH; ++d) {
        kfwd1<<<1024, 256, SM1>>>(hin, f1);
        kfwd2<<<512, 256, SMF>>>(f1, mo);
        kmix<<<256, 256>>>(mo, wt + (size_t)d * 256 * 4096, mx);
        kinv1<<<256, 256>>>(mx, G);
        kfused<<<4096, 256, SM2>>>(hin, G, w_w + d * 4096, w_b + d * 64, hout);
        float* t = hin; hin = hout; hout = t;
    }
    khead<<<8192, 256, SM3>>>(hin, fc1_b, fc2_w, fc2_b, (float*)d_out);
}